// round 1
// baseline (speedup 1.0000x reference)
#include <cuda_runtime.h>
#include <math.h>

#define SS 2048
#define DM 1024
#define HH 16
#define DHD 64
#define BB 2
#define MROWS (BB*SS)   // 4096
#define LN_EPS 1e-3f

// ---------------- scratch buffers (no allocation allowed) ----------------
__device__ float g_buf0[MROWS*DM];
__device__ float g_buf1[MROWS*DM];
__device__ float g_buf2[MROWS*DM];
__device__ float g_buf3[MROWS*DM];

// ======================= SGEMM 128x128x16, fp32 ==========================
// C[M,N] = A[M,K] @ B[K,N], optional relu epilogue.
__global__ __launch_bounds__(256) void sgemm_kernel(
    const float* __restrict__ A, const float* __restrict__ B,
    float* __restrict__ C, int M, int N, int K, int do_relu)
{
    __shared__ float As[16][128];   // transposed A tile: As[k][m]
    __shared__ float Bs[16][128];   // natural B tile:  Bs[k][n]

    const int tid = threadIdx.x;
    const int tx = tid & 15;        // column group
    const int ty = tid >> 4;        // row group
    const int m0 = blockIdx.y * 128;
    const int n0 = blockIdx.x * 128;

    const int arow = tid >> 2;            // 0..63
    const int ac   = (tid & 3) << 2;      // 0..12
    const int brow = tid >> 5;            // 0..7
    const int bc   = (tid & 31) << 2;     // 0..124

    const float* Ap = A + (m0 + arow) * K + ac;
    const float* Bp = B + brow * N + n0 + bc;

    float acc[8][8];
#pragma unroll
    for (int i = 0; i < 8; i++)
#pragma unroll
        for (int j = 0; j < 8; j++) acc[i][j] = 0.f;

    for (int k0 = 0; k0 < K; k0 += 16) {
        float4 a0 = *(const float4*)(Ap);
        float4 a1 = *(const float4*)(Ap + 64 * K);
        float4 b0 = *(const float4*)(Bp);
        float4 b1 = *(const float4*)(Bp + 8 * N);
        Ap += 16; Bp += 16 * N;

        __syncthreads();   // previous-iteration compute reads are done
        As[ac+0][arow]    = a0.x; As[ac+1][arow]    = a0.y;
        As[ac+2][arow]    = a0.z; As[ac+3][arow]    = a0.w;
        As[ac+0][arow+64] = a1.x; As[ac+1][arow+64] = a1.y;
        As[ac+2][arow+64] = a1.z; As[ac+3][arow+64] = a1.w;
        *(float4*)&Bs[brow  ][bc] = b0;
        *(float4*)&Bs[brow+8][bc] = b1;
        __syncthreads();

#pragma unroll
        for (int kk = 0; kk < 16; kk++) {
            float a[8], b[8];
            *(float4*)&a[0] = *(const float4*)&As[kk][ty*8];
            *(float4*)&a[4] = *(const float4*)&As[kk][ty*8+4];
            *(float4*)&b[0] = *(const float4*)&Bs[kk][tx*8];
            *(float4*)&b[4] = *(const float4*)&Bs[kk][tx*8+4];
#pragma unroll
            for (int i = 0; i < 8; i++)
#pragma unroll
                for (int j = 0; j < 8; j++)
                    acc[i][j] = fmaf(a[i], b[j], acc[i][j]);
        }
    }

#pragma unroll
    for (int i = 0; i < 8; i++) {
        float* Cp = C + (m0 + ty*8 + i) * N + n0 + tx*8;
        float4 o0 = make_float4(acc[i][0], acc[i][1], acc[i][2], acc[i][3]);
        float4 o1 = make_float4(acc[i][4], acc[i][5], acc[i][6], acc[i][7]);
        if (do_relu) {
            o0.x = fmaxf(o0.x, 0.f); o0.y = fmaxf(o0.y, 0.f);
            o0.z = fmaxf(o0.z, 0.f); o0.w = fmaxf(o0.w, 0.f);
            o1.x = fmaxf(o1.x, 0.f); o1.y = fmaxf(o1.y, 0.f);
            o1.z = fmaxf(o1.z, 0.f); o1.w = fmaxf(o1.w, 0.f);
        }
        *(float4*)(Cp)     = o0;
        *(float4*)(Cp + 4) = o1;
    }
}

// ===================== flash attention, fp32, Br=Bc=64 ====================
// Q,K,V in [B,S,D] layout (head h at columns h*64..h*64+63). O same layout.
// Swizzled transposed smem layout for Q/K (d-major) for conflict-free MAC.
__device__ __forceinline__ int qk_off(int d, int r) {
    return (d << 6) + ((((r >> 2) ^ (d >> 2)) << 2) | (r & 3));
}

__global__ __launch_bounds__(256) void attn_kernel(
    const float* __restrict__ Q, const float* __restrict__ K,
    const float* __restrict__ V, float* __restrict__ O)
{
    __shared__ float Qs[64*64];
    __shared__ float Ks[64*64];
    __shared__ float Vs[64*64];
    float* Ps = Ks;   // alias: P tile reuses K tile storage

    const int tid = threadIdx.x;
    const int tx = tid & 15;   // 4 columns each (keys for S, dh for O)
    const int ty = tid >> 4;   // 4 rows each
    const int q0 = blockIdx.x * 64;
    const int h  = blockIdx.y;
    const int b  = blockIdx.z;

    const float* Qb = Q + (b * SS) * DM + h * DHD;
    const float* Kb = K + (b * SS) * DM + h * DHD;
    const float* Vb = V + (b * SS) * DM + h * DHD;
    const float scale = 0.125f;   // 1/sqrt(64)

    // load Q tile, pre-scaled, transposed+swizzled
#pragma unroll
    for (int i = 0; i < 4; i++) {
        int idx = tid + i * 256;
        int row = idx >> 4;
        int d4  = (idx & 15) << 2;
        float4 v = *(const float4*)(Qb + (q0 + row) * DM + d4);
        Qs[qk_off(d4+0, row)] = v.x * scale;
        Qs[qk_off(d4+1, row)] = v.y * scale;
        Qs[qk_off(d4+2, row)] = v.z * scale;
        Qs[qk_off(d4+3, row)] = v.w * scale;
    }

    float runm[4], runs[4], acc[4][4];
#pragma unroll
    for (int i = 0; i < 4; i++) {
        runm[i] = -1e30f; runs[i] = 0.f;
#pragma unroll
        for (int j = 0; j < 4; j++) acc[i][j] = 0.f;
    }

    for (int kt = 0; kt < SS / 64; kt++) {
        __syncthreads();   // previous PV reads of Ps(/Ks) and Vs done
#pragma unroll
        for (int i = 0; i < 4; i++) {
            int idx = tid + i * 256;
            int row = idx >> 4;
            int d4  = (idx & 15) << 2;
            const float* kp = Kb + (kt*64 + row) * DM + d4;
            float4 kv = *(const float4*)kp;
            Ks[qk_off(d4+0, row)] = kv.x;
            Ks[qk_off(d4+1, row)] = kv.y;
            Ks[qk_off(d4+2, row)] = kv.z;
            Ks[qk_off(d4+3, row)] = kv.w;
            const float* vp = Vb + (kt*64 + row) * DM + d4;
            *(float4*)&Vs[row*64 + d4] = *(const float4*)vp;
        }
        __syncthreads();

        // scores s[i][j]: rows ty*4+i, keys tx*4+j
        float s[4][4];
#pragma unroll
        for (int i = 0; i < 4; i++)
#pragma unroll
            for (int j = 0; j < 4; j++) s[i][j] = 0.f;

#pragma unroll 8
        for (int d = 0; d < 64; d++) {
            float4 q4 = *(const float4*)&Qs[(d << 6) + ((ty ^ (d >> 2)) << 2)];
            float4 k4 = *(const float4*)&Ks[(d << 6) + ((tx ^ (d >> 2)) << 2)];
            float qa[4] = {q4.x, q4.y, q4.z, q4.w};
            float ka[4] = {k4.x, k4.y, k4.z, k4.w};
#pragma unroll
            for (int i = 0; i < 4; i++)
#pragma unroll
                for (int j = 0; j < 4; j++)
                    s[i][j] = fmaf(qa[i], ka[j], s[i][j]);
        }

        // online softmax
        float p[4][4];
#pragma unroll
        for (int i = 0; i < 4; i++) {
            float m = fmaxf(fmaxf(s[i][0], s[i][1]), fmaxf(s[i][2], s[i][3]));
#pragma unroll
            for (int o = 1; o < 16; o <<= 1)
                m = fmaxf(m, __shfl_xor_sync(0xffffffffu, m, o));
            float newm = fmaxf(runm[i], m);
            float corr = __expf(runm[i] - newm);
            runm[i] = newm;
            float ps = 0.f;
#pragma unroll
            for (int j = 0; j < 4; j++) {
                p[i][j] = __expf(s[i][j] - newm);
                ps += p[i][j];
            }
#pragma unroll
            for (int o = 1; o < 16; o <<= 1)
                ps += __shfl_xor_sync(0xffffffffu, ps, o);
            runs[i] = runs[i] * corr + ps;
#pragma unroll
            for (int j = 0; j < 4; j++) acc[i][j] *= corr;
        }

        __syncthreads();   // all score reads of Ks done before P overwrite
#pragma unroll
        for (int i = 0; i < 4; i++)
            *(float4*)&Ps[(ty*4+i)*64 + tx*4] =
                make_float4(p[i][0], p[i][1], p[i][2], p[i][3]);
        __syncthreads();

        // O += P @ V  (thread owns rows ty*4+i, dh cols tx*4+j)
#pragma unroll 8
        for (int k2 = 0; k2 < 64; k2++) {
            float4 v4 = *(const float4*)&Vs[k2*64 + tx*4];
#pragma unroll
            for (int i = 0; i < 4; i++) {
                float pv = Ps[(ty*4+i)*64 + k2];
                acc[i][0] = fmaf(pv, v4.x, acc[i][0]);
                acc[i][1] = fmaf(pv, v4.y, acc[i][1]);
                acc[i][2] = fmaf(pv, v4.z, acc[i][2]);
                acc[i][3] = fmaf(pv, v4.w, acc[i][3]);
            }
        }
    }

#pragma unroll
    for (int i = 0; i < 4; i++) {
        float inv = 1.f / runs[i];
        int row = q0 + ty*4 + i;
        float* op = O + (b * SS + row) * DM + h * DHD + tx*4;
        *(float4*)op = make_float4(acc[i][0]*inv, acc[i][1]*inv,
                                   acc[i][2]*inv, acc[i][3]*inv);
    }
}

// ======================= residual-add + LayerNorm =========================
__device__ __forceinline__ float block_sum256(float v, float* red) {
#pragma unroll
    for (int o = 16; o; o >>= 1) v += __shfl_xor_sync(0xffffffffu, v, o);
    int lane = threadIdx.x & 31, wid = threadIdx.x >> 5;
    if (lane == 0) red[wid] = v;
    __syncthreads();
    if (threadIdx.x < 32) {
        float t = (threadIdx.x < 8) ? red[threadIdx.x] : 0.f;
#pragma unroll
        for (int o = 4; o; o >>= 1) t += __shfl_xor_sync(0xffffffffu, t, o);
        if (threadIdx.x == 0) red[0] = t;
    }
    __syncthreads();
    float r = red[0];
    __syncthreads();   // red reusable after this
    return r;
}

__global__ __launch_bounds__(256) void ln_kernel(
    const float* __restrict__ x, const float* __restrict__ res,
    const float* __restrict__ gamma, const float* __restrict__ beta,
    float* __restrict__ out)
{
    __shared__ float red[8];
    const int row = blockIdx.x;
    const int tid = threadIdx.x;

    float4 v = ((const float4*)(x + row * DM))[tid];
    float4 r = ((const float4*)(res + row * DM))[tid];
    v.x += r.x; v.y += r.y; v.z += r.z; v.w += r.w;

    float s = v.x + v.y + v.z + v.w;
    float tot = block_sum256(s, red);
    float mean = tot * (1.f / DM);

    float dx = v.x - mean, dy = v.y - mean, dz = v.z - mean, dw = v.w - mean;
    float sq = dx*dx + dy*dy + dz*dz + dw*dw;
    float totsq = block_sum256(sq, red);
    float rstd = rsqrtf(totsq * (1.f / DM) + LN_EPS);

    float4 g = ((const float4*)gamma)[tid];
    float4 b = ((const float4*)beta)[tid];
    float4 o;
    o.x = dx * rstd * g.x + b.x;
    o.y = dy * rstd * g.y + b.y;
    o.z = dz * rstd * g.z + b.z;
    o.w = dw * rstd * g.w + b.w;
    ((float4*)(out + row * DM))[tid] = o;
}

// ================================ driver ==================================
extern "C" void kernel_launch(void* const* d_in, const int* in_sizes, int n_in,
                              void* d_out, int out_size)
{
    const float* query = (const float*)d_in[0];
    const float* Wq    = (const float*)d_in[1];
    const float* Wk    = (const float*)d_in[2];
    const float* Wv    = (const float*)d_in[3];
    const float* W1    = (const float*)d_in[4];
    const float* W2    = (const float*)d_in[5];
    const float* W3    = (const float*)d_in[6];
    const float* gamma = (const float*)d_in[7];
    const float* beta  = (const float*)d_in[8];

    float *b0, *b1, *b2, *b3;
    cudaGetSymbolAddress((void**)&b0, g_buf0);
    cudaGetSymbolAddress((void**)&b1, g_buf1);
    cudaGetSymbolAddress((void**)&b2, g_buf2);
    cudaGetSymbolAddress((void**)&b3, g_buf3);

    dim3 gg(DM / 128, MROWS / 128);   // (8, 32)

    // QKV projections
    sgemm_kernel<<<gg, 256>>>(query, Wq, b0, MROWS, DM, DM, 0);
    sgemm_kernel<<<gg, 256>>>(query, Wk, b1, MROWS, DM, DM, 0);
    sgemm_kernel<<<gg, 256>>>(query, Wv, b2, MROWS, DM, DM, 0);

    // attention -> b3 (ctx in [B,S,D])
    attn_kernel<<<dim3(SS / 64, HH, BB), 256>>>(b0, b1, b2, b3);

    // ctx @ W1 -> b0 ; LN(b0 + query) -> b1 (residual)
    sgemm_kernel<<<gg, 256>>>(b3, W1, b0, MROWS, DM, DM, 0);
    ln_kernel<<<MROWS, 256>>>(b0, query, gamma, beta, b1);

    // relu(b1 @ W2) -> b2 ; b2 @ W3 -> b0 ; LN(b0 + b1) -> out
    sgemm_kernel<<<gg, 256>>>(b1, W2, b2, MROWS, DM, DM, 1);
    sgemm_kernel<<<gg, 256>>>(b2, W3, b0, MROWS, DM, DM, 0);
    ln_kernel<<<MROWS, 256>>>(b0, b1, gamma, beta, (float*)d_out);
}

// round 3
// speedup vs baseline: 1.4676x; 1.4676x over previous
#include <cuda_runtime.h>
#include <cuda_bf16.h>
#include <cstdint>
#include <math.h>

#define SS 2048
#define DM 1024
#define HH 16
#define DHD 64
#define BB 2
#define MROWS (BB*SS)   // 4096
#define LN_EPS 1e-3f

// ---------------- scratch buffers (no allocation allowed) ----------------
__device__ float g_buf0[MROWS*DM];
__device__ float g_buf1[MROWS*DM];
__device__ float g_buf2[MROWS*DM];
__device__ float g_buf3[MROWS*DM];
__device__ __nv_bfloat16 g_ahi[MROWS*DM];
__device__ __nv_bfloat16 g_alo[MROWS*DM];
__device__ __nv_bfloat16 g_wthi[6*DM*DM];
__device__ __nv_bfloat16 g_wtlo[6*DM*DM];

// ========================= PTX helpers (portable) =========================
__device__ __forceinline__ uint32_t smem_u32(const void* p) {
    uint32_t a;
    asm("{ .reg .u64 t; cvta.to.shared.u64 t, %1; cvt.u32.u64 %0, t; }"
        : "=r"(a) : "l"(p));
    return a;
}
#define CP16(dst, src) \
    asm volatile("cp.async.cg.shared.global [%0], [%1], 16;" \
                 :: "r"(dst), "l"(src) : "memory")
#define CP_COMMIT()  asm volatile("cp.async.commit_group;" ::: "memory")
#define CP_WAIT1()   asm volatile("cp.async.wait_group 1;" ::: "memory")
#define CP_WAIT0()   asm volatile("cp.async.wait_group 0;" ::: "memory")

#define LDSM4(r, addr) \
    asm volatile("ldmatrix.sync.aligned.m8n8.x4.shared.b16 {%0,%1,%2,%3}, [%4];" \
        : "=r"((r)[0]), "=r"((r)[1]), "=r"((r)[2]), "=r"((r)[3]) : "r"(addr))
#define LDSM2(r, addr) \
    asm volatile("ldmatrix.sync.aligned.m8n8.x2.shared.b16 {%0,%1}, [%2];" \
        : "=r"((r)[0]), "=r"((r)[1]) : "r"(addr))
#define MMA16816(d, a, b) \
    asm volatile("mma.sync.aligned.m16n8k16.row.col.f32.bf16.bf16.f32 " \
        "{%0,%1,%2,%3}, {%4,%5,%6,%7}, {%8,%9}, {%0,%1,%2,%3};" \
        : "+f"((d)[0]), "+f"((d)[1]), "+f"((d)[2]), "+f"((d)[3]) \
        : "r"((a)[0]), "r"((a)[1]), "r"((a)[2]), "r"((a)[3]), \
          "r"((b)[0]), "r"((b)[1]))

// ================= split-bf16 GEMM via mma.sync (HMMA) ====================
// C[4096,1024] = A @ W. A as bf16 hi/lo [M,K] row-major; W pre-transposed
// and split: B[n,k] = W[k,n], bf16 hi/lo [N,K] row-major (TN gemm).
// CTA 128x128, 8 warps (2x4), warp tile 64x32, K-chunk 32, 2-stage cp.async.
// Smem stage: A block 128 rows x 128B  (row = [hi k0..31 | lo k0..31]),
//             B block 128 rows x 128B, both SW128-swizzled.
#define NCH 32             // 1024 / 32
#define STG 32768          // bytes per stage (A 16K + B 16K)
#define SMEM_GEMM (2*STG)  // 64 KB

__device__ __forceinline__ void gemm_issue_stage(
    uint32_t s, int tid, int m0, int n0, int kc,
    const __nv_bfloat16* __restrict__ Ahi, const __nv_bfloat16* __restrict__ Alo,
    const __nv_bfloat16* __restrict__ Bhi, const __nv_bfloat16* __restrict__ Blo)
{
#pragma unroll
    for (int i = 0; i < 2; i++) {
        int idx = tid + i * 256;
        int row = idx >> 2, g = idx & 3;
        uint32_t oh = row * 128 + g * 16;      oh ^= (oh >> 3) & 0x70;
        uint32_t ol = row * 128 + 64 + g * 16; ol ^= (ol >> 3) & 0x70;
        size_t ga = (size_t)(m0 + row) * DM + kc + g * 8;
        size_t gb = (size_t)(n0 + row) * DM + kc + g * 8;
        CP16(s + oh, Ahi + ga);
        CP16(s + ol, Alo + ga);
        CP16(s + 16384 + oh, Bhi + gb);
        CP16(s + 16384 + ol, Blo + gb);
    }
}

__global__ __launch_bounds__(256, 2) void gemm_mma_kernel(
    const __nv_bfloat16* __restrict__ Ahi, const __nv_bfloat16* __restrict__ Alo,
    const __nv_bfloat16* __restrict__ Bhi, const __nv_bfloat16* __restrict__ Blo,
    float* __restrict__ C, int do_relu)
{
    extern __shared__ char smem[];
    const uint32_t sb = smem_u32(smem);
    const int tid = threadIdx.x;
    const int lane = tid & 31;
    const int wid = tid >> 5;
    const int wm = wid & 1;       // 0..1  (M dir, 64 rows each)
    const int wn = wid >> 1;      // 0..3  (N dir, 32 cols each)
    const int m0 = blockIdx.y * 128;
    const int n0 = blockIdx.x * 128;

    float acc[4][4][4];
#pragma unroll
    for (int mt = 0; mt < 4; mt++)
#pragma unroll
        for (int nt = 0; nt < 4; nt++)
#pragma unroll
            for (int r = 0; r < 4; r++) acc[mt][nt][r] = 0.f;

    // precomputed ldmatrix lane offsets (within 128B row layout)
    const int a_row = (lane & 15);               // + wm*64 + mt*16
    const int a_kb  = ((lane >> 4) << 3) * 2;    // + kk*32 bytes
    const int b_row = (lane & 7);                // + wn*32 + nt*8
    const int b_kb  = (((lane >> 3) & 1) << 3) * 2;

    gemm_issue_stage(sb, tid, m0, n0, 0, Ahi, Alo, Bhi, Blo);
    CP_COMMIT();

    for (int c = 0; c < NCH; c++) {
        if (c + 1 < NCH) {
            gemm_issue_stage(sb + ((c + 1) & 1) * STG, tid, m0, n0, (c + 1) * 32,
                             Ahi, Alo, Bhi, Blo);
            CP_COMMIT();
            CP_WAIT1();
        } else {
            CP_WAIT0();
        }
        __syncthreads();

        const uint32_t sA = sb + (c & 1) * STG;
        const uint32_t sB = sA + 16384;

#pragma unroll
        for (int kk = 0; kk < 2; kk++) {
            uint32_t a[4][4], bh[4][2], bl[4][2];
            const int kbyte = kk * 32;   // 16 bf16 per kk step

            // A hi fragments (4 m-tiles)
#pragma unroll
            for (int mt = 0; mt < 4; mt++) {
                uint32_t off = (uint32_t)(wm*64 + mt*16 + a_row) * 128 + kbyte + a_kb;
                off ^= (off >> 3) & 0x70;
                LDSM4(a[mt], sA + off);
            }
            // B hi + lo fragments (4 n-tiles)
#pragma unroll
            for (int nt = 0; nt < 4; nt++) {
                uint32_t offh = (uint32_t)(wn*32 + nt*8 + b_row) * 128 + kbyte + b_kb;
                offh ^= (offh >> 3) & 0x70;
                LDSM2(bh[nt], sB + offh);
                uint32_t offl = (uint32_t)(wn*32 + nt*8 + b_row) * 128 + 64 + kbyte + b_kb;
                offl ^= (offl >> 3) & 0x70;
                LDSM2(bl[nt], sB + offl);
            }
            // hi*hi and hi*lo
#pragma unroll
            for (int mt = 0; mt < 4; mt++)
#pragma unroll
                for (int nt = 0; nt < 4; nt++) {
                    MMA16816(acc[mt][nt], a[mt], bh[nt]);
                    MMA16816(acc[mt][nt], a[mt], bl[nt]);
                }
            // A lo fragments (reuse a[])
#pragma unroll
            for (int mt = 0; mt < 4; mt++) {
                uint32_t off = (uint32_t)(wm*64 + mt*16 + a_row) * 128 + 64 + kbyte + a_kb;
                off ^= (off >> 3) & 0x70;
                LDSM4(a[mt], sA + off);
            }
            // lo*hi
#pragma unroll
            for (int mt = 0; mt < 4; mt++)
#pragma unroll
                for (int nt = 0; nt < 4; nt++)
                    MMA16816(acc[mt][nt], a[mt], bh[nt]);
        }
        __syncthreads();
    }

    // epilogue: d-frag mapping row = lane/4 (+8), col = (lane%4)*2
#pragma unroll
    for (int mt = 0; mt < 4; mt++) {
        int r0 = m0 + wm*64 + mt*16 + (lane >> 2);
#pragma unroll
        for (int nt = 0; nt < 4; nt++) {
            int cc = n0 + wn*32 + nt*8 + (lane & 3)*2;
            float2 v0 = make_float2(acc[mt][nt][0], acc[mt][nt][1]);
            float2 v1 = make_float2(acc[mt][nt][2], acc[mt][nt][3]);
            if (do_relu) {
                v0.x = fmaxf(v0.x, 0.f); v0.y = fmaxf(v0.y, 0.f);
                v1.x = fmaxf(v1.x, 0.f); v1.y = fmaxf(v1.y, 0.f);
            }
            *(float2*)(C + (size_t)r0 * DM + cc)       = v0;
            *(float2*)(C + (size_t)(r0 + 8) * DM + cc) = v1;
        }
    }
}

// =================== split fp32 -> bf16 hi/lo (elementwise) ===============
__global__ __launch_bounds__(256) void split_kernel(
    const float4* __restrict__ X, __nv_bfloat162* __restrict__ hi,
    __nv_bfloat162* __restrict__ lo)
{
    int i = blockIdx.x * 256 + threadIdx.x;
    float4 v = X[i];
    __nv_bfloat16 h0 = __float2bfloat16_rn(v.x);
    __nv_bfloat16 h1 = __float2bfloat16_rn(v.y);
    __nv_bfloat16 h2 = __float2bfloat16_rn(v.z);
    __nv_bfloat16 h3 = __float2bfloat16_rn(v.w);
    __nv_bfloat16 l0 = __float2bfloat16_rn(v.x - __bfloat162float(h0));
    __nv_bfloat16 l1 = __float2bfloat16_rn(v.y - __bfloat162float(h1));
    __nv_bfloat16 l2 = __float2bfloat16_rn(v.z - __bfloat162float(h2));
    __nv_bfloat16 l3 = __float2bfloat16_rn(v.w - __bfloat162float(h3));
    hi[i*2+0] = __halves2bfloat162(h0, h1);
    hi[i*2+1] = __halves2bfloat162(h2, h3);
    lo[i*2+0] = __halves2bfloat162(l0, l1);
    lo[i*2+1] = __halves2bfloat162(l2, l3);
}

// ============ transpose + split: T[n,k] = split(W[k,n]) ===================
__global__ __launch_bounds__(256) void transpose_split_kernel(
    const float* __restrict__ W, __nv_bfloat16* __restrict__ Thi,
    __nv_bfloat16* __restrict__ Tlo)
{
    __shared__ float t[32][33];
    const int n0 = blockIdx.x * 32, k0 = blockIdx.y * 32;
    const int tx = threadIdx.x, ty = threadIdx.y;   // 32 x 8
#pragma unroll
    for (int r = 0; r < 32; r += 8)
        t[ty + r][tx] = W[(size_t)(k0 + ty + r) * DM + n0 + tx];
    __syncthreads();
#pragma unroll
    for (int r = 0; r < 32; r += 8) {
        float v = t[tx][ty + r];
        __nv_bfloat16 h = __float2bfloat16_rn(v);
        __nv_bfloat16 l = __float2bfloat16_rn(v - __bfloat162float(h));
        size_t o = (size_t)(n0 + ty + r) * DM + k0 + tx;
        Thi[o] = h;
        Tlo[o] = l;
    }
}

// ===================== flash attention, fp32, Br=Bc=64 ====================
__device__ __forceinline__ int qk_off(int d, int r) {
    return (d << 6) + ((((r >> 2) ^ (d >> 2)) << 2) | (r & 3));
}

__global__ __launch_bounds__(256) void attn_kernel(
    const float* __restrict__ Q, const float* __restrict__ K,
    const float* __restrict__ V, float* __restrict__ O)
{
    __shared__ float Qs[64*64];
    __shared__ float Ks[64*64];
    __shared__ float Vs[64*64];
    float* Ps = Ks;

    const int tid = threadIdx.x;
    const int tx = tid & 15;
    const int ty = tid >> 4;
    const int q0 = blockIdx.x * 64;
    const int h  = blockIdx.y;
    const int b  = blockIdx.z;

    const float* Qb = Q + (b * SS) * DM + h * DHD;
    const float* Kb = K + (b * SS) * DM + h * DHD;
    const float* Vb = V + (b * SS) * DM + h * DHD;
    const float scale = 0.125f;

#pragma unroll
    for (int i = 0; i < 4; i++) {
        int idx = tid + i * 256;
        int row = idx >> 4;
        int d4  = (idx & 15) << 2;
        float4 v = *(const float4*)(Qb + (q0 + row) * DM + d4);
        Qs[qk_off(d4+0, row)] = v.x * scale;
        Qs[qk_off(d4+1, row)] = v.y * scale;
        Qs[qk_off(d4+2, row)] = v.z * scale;
        Qs[qk_off(d4+3, row)] = v.w * scale;
    }

    float runm[4], runs[4], acc[4][4];
#pragma unroll
    for (int i = 0; i < 4; i++) {
        runm[i] = -1e30f; runs[i] = 0.f;
#pragma unroll
        for (int j = 0; j < 4; j++) acc[i][j] = 0.f;
    }

    for (int kt = 0; kt < SS / 64; kt++) {
        __syncthreads();
#pragma unroll
        for (int i = 0; i < 4; i++) {
            int idx = tid + i * 256;
            int row = idx >> 4;
            int d4  = (idx & 15) << 2;
            const float* kp = Kb + (kt*64 + row) * DM + d4;
            float4 kv = *(const float4*)kp;
            Ks[qk_off(d4+0, row)] = kv.x;
            Ks[qk_off(d4+1, row)] = kv.y;
            Ks[qk_off(d4+2, row)] = kv.z;
            Ks[qk_off(d4+3, row)] = kv.w;
            const float* vp = Vb + (kt*64 + row) * DM + d4;
            *(float4*)&Vs[row*64 + d4] = *(const float4*)vp;
        }
        __syncthreads();

        float s[4][4];
#pragma unroll
        for (int i = 0; i < 4; i++)
#pragma unroll
            for (int j = 0; j < 4; j++) s[i][j] = 0.f;

#pragma unroll 8
        for (int d = 0; d < 64; d++) {
            float4 q4 = *(const float4*)&Qs[(d << 6) + ((ty ^ (d >> 2)) << 2)];
            float4 k4 = *(const float4*)&Ks[(d << 6) + ((tx ^ (d >> 2)) << 2)];
            float qa[4] = {q4.x, q4.y, q4.z, q4.w};
            float ka[4] = {k4.x, k4.y, k4.z, k4.w};
#pragma unroll
            for (int i = 0; i < 4; i++)
#pragma unroll
                for (int j = 0; j < 4; j++)
                    s[i][j] = fmaf(qa[i], ka[j], s[i][j]);
        }

        float p[4][4];
#pragma unroll
        for (int i = 0; i < 4; i++) {
            float m = fmaxf(fmaxf(s[i][0], s[i][1]), fmaxf(s[i][2], s[i][3]));
#pragma unroll
            for (int o = 1; o < 16; o <<= 1)
                m = fmaxf(m, __shfl_xor_sync(0xffffffffu, m, o));
            float newm = fmaxf(runm[i], m);
            float corr = __expf(runm[i] - newm);
            runm[i] = newm;
            float ps = 0.f;
#pragma unroll
            for (int j = 0; j < 4; j++) {
                p[i][j] = __expf(s[i][j] - newm);
                ps += p[i][j];
            }
#pragma unroll
            for (int o = 1; o < 16; o <<= 1)
                ps += __shfl_xor_sync(0xffffffffu, ps, o);
            runs[i] = runs[i] * corr + ps;
#pragma unroll
            for (int j = 0; j < 4; j++) acc[i][j] *= corr;
        }

        __syncthreads();
#pragma unroll
        for (int i = 0; i < 4; i++)
            *(float4*)&Ps[(ty*4+i)*64 + tx*4] =
                make_float4(p[i][0], p[i][1], p[i][2], p[i][3]);
        __syncthreads();

#pragma unroll 8
        for (int k2 = 0; k2 < 64; k2++) {
            float4 v4 = *(const float4*)&Vs[k2*64 + tx*4];
#pragma unroll
            for (int i = 0; i < 4; i++) {
                float pv = Ps[(ty*4+i)*64 + k2];
                acc[i][0] = fmaf(pv, v4.x, acc[i][0]);
                acc[i][1] = fmaf(pv, v4.y, acc[i][1]);
                acc[i][2] = fmaf(pv, v4.z, acc[i][2]);
                acc[i][3] = fmaf(pv, v4.w, acc[i][3]);
            }
        }
    }

#pragma unroll
    for (int i = 0; i < 4; i++) {
        float inv = 1.f / runs[i];
        int row = q0 + ty*4 + i;
        float* op = O + (b * SS + row) * DM + h * DHD + tx*4;
        *(float4*)op = make_float4(acc[i][0]*inv, acc[i][1]*inv,
                                   acc[i][2]*inv, acc[i][3]*inv);
    }
}

// ======================= residual-add + LayerNorm =========================
__device__ __forceinline__ float block_sum256(float v, float* red) {
#pragma unroll
    for (int o = 16; o; o >>= 1) v += __shfl_xor_sync(0xffffffffu, v, o);
    int lane = threadIdx.x & 31, wid = threadIdx.x >> 5;
    if (lane == 0) red[wid] = v;
    __syncthreads();
    if (threadIdx.x < 32) {
        float t = (threadIdx.x < 8) ? red[threadIdx.x] : 0.f;
#pragma unroll
        for (int o = 4; o; o >>= 1) t += __shfl_xor_sync(0xffffffffu, t, o);
        if (threadIdx.x == 0) red[0] = t;
    }
    __syncthreads();
    float r = red[0];
    __syncthreads();
    return r;
}

__global__ __launch_bounds__(256) void ln_kernel(
    const float* __restrict__ x, const float* __restrict__ res,
    const float* __restrict__ gamma, const float* __restrict__ beta,
    float* __restrict__ out)
{
    __shared__ float red[8];
    const int row = blockIdx.x;
    const int tid = threadIdx.x;

    float4 v = ((const float4*)(x + row * DM))[tid];
    float4 r = ((const float4*)(res + row * DM))[tid];
    v.x += r.x; v.y += r.y; v.z += r.z; v.w += r.w;

    float s = v.x + v.y + v.z + v.w;
    float tot = block_sum256(s, red);
    float mean = tot * (1.f / DM);

    float dx = v.x - mean, dy = v.y - mean, dz = v.z - mean, dw = v.w - mean;
    float sq = dx*dx + dy*dy + dz*dz + dw*dw;
    float totsq = block_sum256(sq, red);
    float rstd = rsqrtf(totsq * (1.f / DM) + LN_EPS);

    float4 g = ((const float4*)gamma)[tid];
    float4 b = ((const float4*)beta)[tid];
    float4 o;
    o.x = dx * rstd * g.x + b.x;
    o.y = dy * rstd * g.y + b.y;
    o.z = dz * rstd * g.z + b.z;
    o.w = dw * rstd * g.w + b.w;
    ((float4*)(out + row * DM))[tid] = o;
}

// ================================ driver ==================================
extern "C" void kernel_launch(void* const* d_in, const int* in_sizes, int n_in,
                              void* d_out, int out_size)
{
    const float* query = (const float*)d_in[0];
    const float* Ws[6] = { (const float*)d_in[1], (const float*)d_in[2],
                           (const float*)d_in[3], (const float*)d_in[4],
                           (const float*)d_in[5], (const float*)d_in[6] };
    const float* gamma = (const float*)d_in[7];
    const float* beta  = (const float*)d_in[8];

    float *b0, *b1, *b2, *b3;
    __nv_bfloat16 *ahi, *alo, *wthi, *wtlo;
    cudaGetSymbolAddress((void**)&b0, g_buf0);
    cudaGetSymbolAddress((void**)&b1, g_buf1);
    cudaGetSymbolAddress((void**)&b2, g_buf2);
    cudaGetSymbolAddress((void**)&b3, g_buf3);
    cudaGetSymbolAddress((void**)&ahi, g_ahi);
    cudaGetSymbolAddress((void**)&alo, g_alo);
    cudaGetSymbolAddress((void**)&wthi, g_wthi);
    cudaGetSymbolAddress((void**)&wtlo, g_wtlo);

    cudaFuncSetAttribute(gemm_mma_kernel,
                         cudaFuncAttributeMaxDynamicSharedMemorySize, SMEM_GEMM);

    const dim3 ggrid(DM / 128, MROWS / 128);          // (8, 32)
    const int split_blocks = (MROWS * DM / 4) / 256;  // 4096
    const dim3 tgrid(DM / 32, DM / 32);
    const dim3 tblock(32, 8);

    // prep: transpose+split all 6 weights
    for (int i = 0; i < 6; i++)
        transpose_split_kernel<<<tgrid, tblock>>>(Ws[i], wthi + (size_t)i*DM*DM,
                                                  wtlo + (size_t)i*DM*DM);

    // QKV projections
    split_kernel<<<split_blocks, 256>>>((const float4*)query,
                                        (__nv_bfloat162*)ahi, (__nv_bfloat162*)alo);
    gemm_mma_kernel<<<ggrid, 256, SMEM_GEMM>>>(ahi, alo, wthi + 0*DM*DM, wtlo + 0*DM*DM, b0, 0);
    gemm_mma_kernel<<<ggrid, 256, SMEM_GEMM>>>(ahi, alo, wthi + 1*DM*DM, wtlo + 1*DM*DM, b1, 0);
    gemm_mma_kernel<<<ggrid, 256, SMEM_GEMM>>>(ahi, alo, wthi + 2*DM*DM, wtlo + 2*DM*DM, b2, 0);

    // attention -> b3
    attn_kernel<<<dim3(SS / 64, HH, BB), 256>>>(b0, b1, b2, b3);

    // ctx @ W1 -> b0 ; LN(b0 + query) -> b1
    split_kernel<<<split_blocks, 256>>>((const float4*)b3,
                                        (__nv_bfloat162*)ahi, (__nv_bfloat162*)alo);
    gemm_mma_kernel<<<ggrid, 256, SMEM_GEMM>>>(ahi, alo, wthi + 3*DM*DM, wtlo + 3*DM*DM, b0, 0);
    ln_kernel<<<MROWS, 256>>>(b0, query, gamma, beta, b1);

    // relu(b1 @ W2) -> b2 ; b2 @ W3 -> b0 ; LN(b0 + b1) -> out
    split_kernel<<<split_blocks, 256>>>((const float4*)b1,
                                        (__nv_bfloat162*)ahi, (__nv_bfloat162*)alo);
    gemm_mma_kernel<<<ggrid, 256, SMEM_GEMM>>>(ahi, alo, wthi + 4*DM*DM, wtlo + 4*DM*DM, b2, 1);
    split_kernel<<<split_blocks, 256>>>((const float4*)b2,
                                        (__nv_bfloat162*)ahi, (__nv_bfloat162*)alo);
    gemm_mma_kernel<<<ggrid, 256, SMEM_GEMM>>>(ahi, alo, wthi + 5*DM*DM, wtlo + 5*DM*DM, b0, 0);
    ln_kernel<<<MROWS, 256>>>(b0, b1, gamma, beta, (float*)d_out);
}

// round 4
// speedup vs baseline: 2.8140x; 1.9174x over previous
#include <cuda_runtime.h>
#include <cuda_bf16.h>
#include <cstdint>
#include <math.h>

#define SS 2048
#define DM 1024
#define HH 16
#define DHD 64
#define BB 2
#define MROWS (BB*SS)   // 4096
#define LN_EPS 1e-3f

// ---------------- scratch buffers (no allocation allowed) ----------------
__device__ float g_buf0[MROWS*DM];
__device__ float g_buf1[MROWS*DM];
__device__ __nv_bfloat16 g_ahi[MROWS*DM];
__device__ __nv_bfloat16 g_alo[MROWS*DM];
__device__ __nv_bfloat16 g_bhi[MROWS*DM];
__device__ __nv_bfloat16 g_blo[MROWS*DM];
__device__ __nv_bfloat16 g_qhi[MROWS*DM];
__device__ __nv_bfloat16 g_qlo[MROWS*DM];
__device__ __nv_bfloat16 g_khi[MROWS*DM];
__device__ __nv_bfloat16 g_klo[MROWS*DM];
__device__ __nv_bfloat16 g_vhi[MROWS*DM];
__device__ __nv_bfloat16 g_vlo[MROWS*DM];
__device__ __nv_bfloat16 g_wthi[6*DM*DM];
__device__ __nv_bfloat16 g_wtlo[6*DM*DM];

// ========================= PTX helpers (portable) =========================
__device__ __forceinline__ uint32_t smem_u32(const void* p) {
    uint32_t a;
    asm("{ .reg .u64 t; cvta.to.shared.u64 t, %1; cvt.u32.u64 %0, t; }"
        : "=r"(a) : "l"(p));
    return a;
}
#define CP16(dst, src) \
    asm volatile("cp.async.cg.shared.global [%0], [%1], 16;" \
                 :: "r"(dst), "l"(src) : "memory")
#define CP_COMMIT()  asm volatile("cp.async.commit_group;" ::: "memory")
#define CP_WAIT1()   asm volatile("cp.async.wait_group 1;" ::: "memory")
#define CP_WAIT0()   asm volatile("cp.async.wait_group 0;" ::: "memory")

#define LDSM4(r, addr) \
    asm volatile("ldmatrix.sync.aligned.m8n8.x4.shared.b16 {%0,%1,%2,%3}, [%4];" \
        : "=r"((r)[0]), "=r"((r)[1]), "=r"((r)[2]), "=r"((r)[3]) : "r"(addr))
#define LDSM2(r, addr) \
    asm volatile("ldmatrix.sync.aligned.m8n8.x2.shared.b16 {%0,%1}, [%2];" \
        : "=r"((r)[0]), "=r"((r)[1]) : "r"(addr))
#define LDSM2T(r, addr) \
    asm volatile("ldmatrix.sync.aligned.m8n8.x2.trans.shared.b16 {%0,%1}, [%2];" \
        : "=r"((r)[0]), "=r"((r)[1]) : "r"(addr))
#define MMA16816(d, a, b) \
    asm volatile("mma.sync.aligned.m16n8k16.row.col.f32.bf16.bf16.f32 " \
        "{%0,%1,%2,%3}, {%4,%5,%6,%7}, {%8,%9}, {%0,%1,%2,%3};" \
        : "+f"((d)[0]), "+f"((d)[1]), "+f"((d)[2]), "+f"((d)[3]) \
        : "r"((a)[0]), "r"((a)[1]), "r"((a)[2]), "r"((a)[3]), \
          "r"((b)[0]), "r"((b)[1]))

// pack two fp32 -> bf16x2 (lo in low half)
__device__ __forceinline__ uint32_t packbf(float lo, float hi) {
    uint32_t r;
    asm("cvt.rn.bf16x2.f32 %0, %1, %2;" : "=r"(r) : "f"(hi), "f"(lo));
    return r;
}
__device__ __forceinline__ float bfhi_f(float x) {
    return __bfloat162float(__float2bfloat16_rn(x));
}

// ================= split-bf16 GEMM via mma.sync (HMMA) ====================
// C = A @ W. A bf16 hi/lo [M,K] rm; B[n,k]=W[k,n] bf16 hi/lo [N,K] rm.
// CTA 128x128, 8 warps (2x4), warp tile 64x32, K-chunk 32, 2-stage cp.async.
#define NCH 32
#define STG 32768
#define SMEM_GEMM (2*STG)

__device__ __forceinline__ void gemm_issue_stage(
    uint32_t s, int tid, int m0, int n0, int kc,
    const __nv_bfloat16* __restrict__ Ahi, const __nv_bfloat16* __restrict__ Alo,
    const __nv_bfloat16* __restrict__ Bhi, const __nv_bfloat16* __restrict__ Blo)
{
#pragma unroll
    for (int i = 0; i < 2; i++) {
        int idx = tid + i * 256;
        int row = idx >> 2, g = idx & 3;
        uint32_t oh = row * 128 + g * 16;      oh ^= (oh >> 3) & 0x70;
        uint32_t ol = row * 128 + 64 + g * 16; ol ^= (ol >> 3) & 0x70;
        size_t ga = (size_t)(m0 + row) * DM + kc + g * 8;
        size_t gb = (size_t)(n0 + row) * DM + kc + g * 8;
        CP16(s + oh, Ahi + ga);
        CP16(s + ol, Alo + ga);
        CP16(s + 16384 + oh, Bhi + gb);
        CP16(s + 16384 + ol, Blo + gb);
    }
}

__global__ __launch_bounds__(256, 2) void gemm_mma_kernel(
    const __nv_bfloat16* __restrict__ Ahi, const __nv_bfloat16* __restrict__ Alo,
    const __nv_bfloat16* __restrict__ Bhi, const __nv_bfloat16* __restrict__ Blo,
    float* __restrict__ Cf, __nv_bfloat16* __restrict__ Chi,
    __nv_bfloat16* __restrict__ Clo, int do_relu, float scale)
{
    extern __shared__ char smem[];
    const uint32_t sb = smem_u32(smem);
    const int tid = threadIdx.x;
    const int lane = tid & 31;
    const int wid = tid >> 5;
    const int wm = wid & 1;
    const int wn = wid >> 1;
    const int m0 = blockIdx.y * 128;
    const int n0 = blockIdx.x * 128;

    float acc[4][4][4];
#pragma unroll
    for (int mt = 0; mt < 4; mt++)
#pragma unroll
        for (int nt = 0; nt < 4; nt++)
#pragma unroll
            for (int r = 0; r < 4; r++) acc[mt][nt][r] = 0.f;

    const int a_row = (lane & 15);
    const int a_kb  = ((lane >> 4) << 3) * 2;
    const int b_row = (lane & 7);
    const int b_kb  = (((lane >> 3) & 1) << 3) * 2;

    gemm_issue_stage(sb, tid, m0, n0, 0, Ahi, Alo, Bhi, Blo);
    CP_COMMIT();

    for (int c = 0; c < NCH; c++) {
        if (c + 1 < NCH) {
            gemm_issue_stage(sb + ((c + 1) & 1) * STG, tid, m0, n0, (c + 1) * 32,
                             Ahi, Alo, Bhi, Blo);
            CP_COMMIT();
            CP_WAIT1();
        } else {
            CP_WAIT0();
        }
        __syncthreads();

        const uint32_t sA = sb + (c & 1) * STG;
        const uint32_t sB = sA + 16384;

#pragma unroll
        for (int kk = 0; kk < 2; kk++) {
            uint32_t a[4][4], bh[4][2], bl[4][2];
            const int kbyte = kk * 32;

#pragma unroll
            for (int mt = 0; mt < 4; mt++) {
                uint32_t off = (uint32_t)(wm*64 + mt*16 + a_row) * 128 + kbyte + a_kb;
                off ^= (off >> 3) & 0x70;
                LDSM4(a[mt], sA + off);
            }
#pragma unroll
            for (int nt = 0; nt < 4; nt++) {
                uint32_t offh = (uint32_t)(wn*32 + nt*8 + b_row) * 128 + kbyte + b_kb;
                offh ^= (offh >> 3) & 0x70;
                LDSM2(bh[nt], sB + offh);
                uint32_t offl = (uint32_t)(wn*32 + nt*8 + b_row) * 128 + 64 + kbyte + b_kb;
                offl ^= (offl >> 3) & 0x70;
                LDSM2(bl[nt], sB + offl);
            }
#pragma unroll
            for (int mt = 0; mt < 4; mt++)
#pragma unroll
                for (int nt = 0; nt < 4; nt++) {
                    MMA16816(acc[mt][nt], a[mt], bh[nt]);
                    MMA16816(acc[mt][nt], a[mt], bl[nt]);
                }
#pragma unroll
            for (int mt = 0; mt < 4; mt++) {
                uint32_t off = (uint32_t)(wm*64 + mt*16 + a_row) * 128 + 64 + kbyte + a_kb;
                off ^= (off >> 3) & 0x70;
                LDSM4(a[mt], sA + off);
            }
#pragma unroll
            for (int mt = 0; mt < 4; mt++)
#pragma unroll
                for (int nt = 0; nt < 4; nt++)
                    MMA16816(acc[mt][nt], a[mt], bh[nt]);
        }
        __syncthreads();
    }

    // epilogue
#pragma unroll
    for (int mt = 0; mt < 4; mt++) {
        int r0 = m0 + wm*64 + mt*16 + (lane >> 2);
#pragma unroll
        for (int nt = 0; nt < 4; nt++) {
            int cc = n0 + wn*32 + nt*8 + (lane & 3)*2;
            float v[4];
#pragma unroll
            for (int r = 0; r < 4; r++) {
                v[r] = acc[mt][nt][r] * scale;
                if (do_relu) v[r] = fmaxf(v[r], 0.f);
            }
            if (Cf) {
                *(float2*)(Cf + (size_t)r0 * DM + cc)       = make_float2(v[0], v[1]);
                *(float2*)(Cf + (size_t)(r0 + 8) * DM + cc) = make_float2(v[2], v[3]);
            }
            if (Chi) {
                *(uint32_t*)(Chi + (size_t)r0 * DM + cc)       = packbf(v[0], v[1]);
                *(uint32_t*)(Chi + (size_t)(r0+8) * DM + cc)   = packbf(v[2], v[3]);
                *(uint32_t*)(Clo + (size_t)r0 * DM + cc)       =
                    packbf(v[0]-bfhi_f(v[0]), v[1]-bfhi_f(v[1]));
                *(uint32_t*)(Clo + (size_t)(r0+8) * DM + cc)   =
                    packbf(v[2]-bfhi_f(v[2]), v[3]-bfhi_f(v[3]));
            }
        }
    }
}

// =================== split fp32 -> bf16 hi/lo (elementwise) ===============
__global__ __launch_bounds__(256) void split_kernel(
    const float4* __restrict__ X, __nv_bfloat162* __restrict__ hi,
    __nv_bfloat162* __restrict__ lo)
{
    int i = blockIdx.x * 256 + threadIdx.x;
    float4 v = X[i];
    ((uint32_t*)hi)[i*2+0] = packbf(v.x, v.y);
    ((uint32_t*)hi)[i*2+1] = packbf(v.z, v.w);
    ((uint32_t*)lo)[i*2+0] = packbf(v.x-bfhi_f(v.x), v.y-bfhi_f(v.y));
    ((uint32_t*)lo)[i*2+1] = packbf(v.z-bfhi_f(v.z), v.w-bfhi_f(v.w));
}

// ============ transpose + split: T[n,k] = split(W[k,n]) ===================
__global__ __launch_bounds__(256) void transpose_split_kernel(
    const float* __restrict__ W, __nv_bfloat16* __restrict__ Thi,
    __nv_bfloat16* __restrict__ Tlo)
{
    __shared__ float t[32][33];
    const int n0 = blockIdx.x * 32, k0 = blockIdx.y * 32;
    const int tx = threadIdx.x, ty = threadIdx.y;
#pragma unroll
    for (int r = 0; r < 32; r += 8)
        t[ty + r][tx] = W[(size_t)(k0 + ty + r) * DM + n0 + tx];
    __syncthreads();
#pragma unroll
    for (int r = 0; r < 32; r += 8) {
        float v = t[tx][ty + r];
        __nv_bfloat16 h = __float2bfloat16_rn(v);
        __nv_bfloat16 l = __float2bfloat16_rn(v - __bfloat162float(h));
        size_t o = (size_t)(n0 + ty + r) * DM + k0 + tx;
        Thi[o] = h;
        Tlo[o] = l;
    }
}

// ============== tensor-core flash attention, split bf16 ===================
// Q pre-scaled by 1/8 in its GEMM epilogue. Br=128 (8 warps x 16 rows),
// Bc=64, K/V double-buffered. Output ctx written as bf16 hi/lo.
#define AT_QH 0
#define AT_QL 16384
#define AT_STG 32768
#define AT_STGSZ 32768
#define SMEM_ATTN (32768 + 2*32768)   // 96 KB

__device__ __forceinline__ void attn_issue_kv(
    uint32_t s, int tid, size_t base, int kt,
    const __nv_bfloat16* __restrict__ Kh, const __nv_bfloat16* __restrict__ Kl,
    const __nv_bfloat16* __restrict__ Vh, const __nv_bfloat16* __restrict__ Vl)
{
#pragma unroll
    for (int i = 0; i < 2; i++) {
        int idx = tid + i * 256;
        int row = idx >> 3, c16 = idx & 7;
        uint32_t off = row * 128 + c16 * 16;
        off ^= (off >> 3) & 0x70;
        size_t g = base + (size_t)(kt * 64 + row) * DM + c16 * 8;
        CP16(s + off,          Kh + g);
        CP16(s + 8192  + off,  Kl + g);
        CP16(s + 16384 + off,  Vh + g);
        CP16(s + 24576 + off,  Vl + g);
    }
}

__global__ __launch_bounds__(256) void attn_mma_kernel(
    const __nv_bfloat16* __restrict__ Qh, const __nv_bfloat16* __restrict__ Ql,
    const __nv_bfloat16* __restrict__ Kh, const __nv_bfloat16* __restrict__ Kl,
    const __nv_bfloat16* __restrict__ Vh, const __nv_bfloat16* __restrict__ Vl,
    __nv_bfloat16* __restrict__ Ohi, __nv_bfloat16* __restrict__ Olo)
{
    extern __shared__ char smem[];
    const uint32_t sb = smem_u32(smem);
    const int tid = threadIdx.x, lane = tid & 31, w = tid >> 5;
    const int q0 = blockIdx.x * 128;
    const int h = blockIdx.y, b = blockIdx.z;
    const size_t base = (size_t)b * SS * DM + h * DHD;

    // load Q tile (128 rows x 128B, hi + lo)
#pragma unroll
    for (int i = 0; i < 4; i++) {
        int idx = tid + i * 256;
        int row = idx >> 3, c16 = idx & 7;
        uint32_t off = row * 128 + c16 * 16;
        off ^= (off >> 3) & 0x70;
        size_t g = base + (size_t)(q0 + row) * DM + c16 * 8;
        CP16(sb + AT_QH + off, Qh + g);
        CP16(sb + AT_QL + off, Ql + g);
    }
    attn_issue_kv(sb + AT_STG, tid, base, 0, Kh, Kl, Vh, Vl);
    CP_COMMIT();

    float acco[8][4];
#pragma unroll
    for (int nt = 0; nt < 8; nt++)
#pragma unroll
        for (int r = 0; r < 4; r++) acco[nt][r] = 0.f;
    float runm0 = -1e30f, runm1 = -1e30f, runs0 = 0.f, runs1 = 0.f;

    const int arow = w * 16 + (lane & 15);
    const int akb  = (lane >> 4) << 4;
    const int brow = lane & 7;
    const int bkb  = ((lane >> 3) & 1) << 4;
    const int vrow = lane & 15;

    for (int kt = 0; kt < SS / 64; kt++) {
        if (kt + 1 < SS / 64) {
            attn_issue_kv(sb + AT_STG + ((kt + 1) & 1) * AT_STGSZ, tid, base,
                          kt + 1, Kh, Kl, Vh, Vl);
            CP_COMMIT();
            CP_WAIT1();
        } else {
            CP_WAIT0();
        }
        __syncthreads();

        const uint32_t sK  = sb + AT_STG + (kt & 1) * AT_STGSZ;
        const uint32_t sKl = sK + 8192;
        const uint32_t sV  = sK + 16384;
        const uint32_t sVl = sK + 24576;

        // ---- QK^T: scores 16x64 per warp ----
        float accs[8][4];
#pragma unroll
        for (int nt = 0; nt < 8; nt++)
#pragma unroll
            for (int r = 0; r < 4; r++) accs[nt][r] = 0.f;

#pragma unroll
        for (int ks = 0; ks < 4; ks++) {
            uint32_t aqh[4], aql[4];
            uint32_t o = (uint32_t)arow * 128 + ks * 32 + akb;
            o ^= (o >> 3) & 0x70;
            LDSM4(aqh, sb + AT_QH + o);
            LDSM4(aql, sb + AT_QL + o);
#pragma unroll
            for (int nt = 0; nt < 8; nt++) {
                uint32_t bo = (uint32_t)(nt * 8 + brow) * 128 + ks * 32 + bkb;
                bo ^= (bo >> 3) & 0x70;
                uint32_t bkh[2], bkl[2];
                LDSM2(bkh, sK + bo);
                LDSM2(bkl, sKl + bo);
                MMA16816(accs[nt], aqh, bkh);
                MMA16816(accs[nt], aqh, bkl);
                MMA16816(accs[nt], aql, bkh);
            }
        }

        // ---- online softmax (rows r0=lane>>2 and r0+8) ----
        float mx0 = -1e30f, mx1 = -1e30f;
#pragma unroll
        for (int nt = 0; nt < 8; nt++) {
            mx0 = fmaxf(mx0, fmaxf(accs[nt][0], accs[nt][1]));
            mx1 = fmaxf(mx1, fmaxf(accs[nt][2], accs[nt][3]));
        }
        mx0 = fmaxf(mx0, __shfl_xor_sync(0xffffffffu, mx0, 1));
        mx0 = fmaxf(mx0, __shfl_xor_sync(0xffffffffu, mx0, 2));
        mx1 = fmaxf(mx1, __shfl_xor_sync(0xffffffffu, mx1, 1));
        mx1 = fmaxf(mx1, __shfl_xor_sync(0xffffffffu, mx1, 2));
        float nm0 = fmaxf(runm0, mx0), nm1 = fmaxf(runm1, mx1);
        float c0 = __expf(runm0 - nm0), c1 = __expf(runm1 - nm1);
        runm0 = nm0; runm1 = nm1;
        float s0 = 0.f, s1 = 0.f;
#pragma unroll
        for (int nt = 0; nt < 8; nt++) {
            accs[nt][0] = __expf(accs[nt][0] - nm0); s0 += accs[nt][0];
            accs[nt][1] = __expf(accs[nt][1] - nm0); s0 += accs[nt][1];
            accs[nt][2] = __expf(accs[nt][2] - nm1); s1 += accs[nt][2];
            accs[nt][3] = __expf(accs[nt][3] - nm1); s1 += accs[nt][3];
        }
        s0 += __shfl_xor_sync(0xffffffffu, s0, 1);
        s0 += __shfl_xor_sync(0xffffffffu, s0, 2);
        s1 += __shfl_xor_sync(0xffffffffu, s1, 1);
        s1 += __shfl_xor_sync(0xffffffffu, s1, 2);
        runs0 = runs0 * c0 + s0;
        runs1 = runs1 * c1 + s1;
#pragma unroll
        for (int nt = 0; nt < 8; nt++) {
            acco[nt][0] *= c0; acco[nt][1] *= c0;
            acco[nt][2] *= c1; acco[nt][3] *= c1;
        }

        // ---- P @ V ----
#pragma unroll
        for (int j = 0; j < 4; j++) {
            uint32_t aph[4], apl[4];
            float* pa = accs[2*j];
            float* pb = accs[2*j + 1];
            aph[0] = packbf(pa[0], pa[1]);
            aph[1] = packbf(pa[2], pa[3]);
            aph[2] = packbf(pb[0], pb[1]);
            aph[3] = packbf(pb[2], pb[3]);
            apl[0] = packbf(pa[0]-bfhi_f(pa[0]), pa[1]-bfhi_f(pa[1]));
            apl[1] = packbf(pa[2]-bfhi_f(pa[2]), pa[3]-bfhi_f(pa[3]));
            apl[2] = packbf(pb[0]-bfhi_f(pb[0]), pb[1]-bfhi_f(pb[1]));
            apl[3] = packbf(pb[2]-bfhi_f(pb[2]), pb[3]-bfhi_f(pb[3]));
            uint32_t vr = (uint32_t)(j * 16 + vrow) * 128;
#pragma unroll
            for (int nt = 0; nt < 8; nt++) {
                uint32_t vo = vr + nt * 16;
                vo ^= (vo >> 3) & 0x70;
                uint32_t bvh[2], bvl[2];
                LDSM2T(bvh, sV + vo);
                LDSM2T(bvl, sVl + vo);
                MMA16816(acco[nt], aph, bvh);
                MMA16816(acco[nt], aph, bvl);
                MMA16816(acco[nt], apl, bvh);
            }
        }
        __syncthreads();
    }

    // ---- epilogue: normalize + split-write ctx ----
    const float i0 = 1.f / runs0, i1 = 1.f / runs1;
    const size_t r0 = (size_t)(b * SS + q0 + w * 16 + (lane >> 2));
#pragma unroll
    for (int nt = 0; nt < 8; nt++) {
        int cc = h * DHD + nt * 8 + (lane & 3) * 2;
        float x0 = acco[nt][0] * i0, x1 = acco[nt][1] * i0;
        float x2 = acco[nt][2] * i1, x3 = acco[nt][3] * i1;
        *(uint32_t*)(Ohi + r0 * DM + cc)     = packbf(x0, x1);
        *(uint32_t*)(Ohi + (r0+8) * DM + cc) = packbf(x2, x3);
        *(uint32_t*)(Olo + r0 * DM + cc)     = packbf(x0-bfhi_f(x0), x1-bfhi_f(x1));
        *(uint32_t*)(Olo + (r0+8) * DM + cc) = packbf(x2-bfhi_f(x2), x3-bfhi_f(x3));
    }
}

// ======================= residual-add + LayerNorm =========================
__device__ __forceinline__ float block_sum256(float v, float* red) {
#pragma unroll
    for (int o = 16; o; o >>= 1) v += __shfl_xor_sync(0xffffffffu, v, o);
    int lane = threadIdx.x & 31, wid = threadIdx.x >> 5;
    if (lane == 0) red[wid] = v;
    __syncthreads();
    if (threadIdx.x < 32) {
        float t = (threadIdx.x < 8) ? red[threadIdx.x] : 0.f;
#pragma unroll
        for (int o = 4; o; o >>= 1) t += __shfl_xor_sync(0xffffffffu, t, o);
        if (threadIdx.x == 0) red[0] = t;
    }
    __syncthreads();
    float r = red[0];
    __syncthreads();
    return r;
}

__global__ __launch_bounds__(256) void ln_kernel(
    const float* __restrict__ x, const float* __restrict__ res,
    const float* __restrict__ gamma, const float* __restrict__ beta,
    float* __restrict__ out, __nv_bfloat16* __restrict__ ohi,
    __nv_bfloat16* __restrict__ olo)
{
    __shared__ float red[8];
    const int row = blockIdx.x;
    const int tid = threadIdx.x;

    float4 v = ((const float4*)(x + (size_t)row * DM))[tid];
    float4 r = ((const float4*)(res + (size_t)row * DM))[tid];
    v.x += r.x; v.y += r.y; v.z += r.z; v.w += r.w;

    float s = v.x + v.y + v.z + v.w;
    float tot = block_sum256(s, red);
    float mean = tot * (1.f / DM);

    float dx = v.x - mean, dy = v.y - mean, dz = v.z - mean, dw = v.w - mean;
    float sq = dx*dx + dy*dy + dz*dz + dw*dw;
    float totsq = block_sum256(sq, red);
    float rstd = rsqrtf(totsq * (1.f / DM) + LN_EPS);

    float4 g = ((const float4*)gamma)[tid];
    float4 bb = ((const float4*)beta)[tid];
    float4 o;
    o.x = dx * rstd * g.x + bb.x;
    o.y = dy * rstd * g.y + bb.y;
    o.z = dz * rstd * g.z + bb.z;
    o.w = dw * rstd * g.w + bb.w;
    if (out) ((float4*)(out + (size_t)row * DM))[tid] = o;
    if (ohi) {
        uint32_t* hp = (uint32_t*)(ohi + (size_t)row * DM) + tid*2;
        uint32_t* lp = (uint32_t*)(olo + (size_t)row * DM) + tid*2;
        hp[0] = packbf(o.x, o.y);
        hp[1] = packbf(o.z, o.w);
        lp[0] = packbf(o.x-bfhi_f(o.x), o.y-bfhi_f(o.y));
        lp[1] = packbf(o.z-bfhi_f(o.z), o.w-bfhi_f(o.w));
    }
}

// ================================ driver ==================================
extern "C" void kernel_launch(void* const* d_in, const int* in_sizes, int n_in,
                              void* d_out, int out_size)
{
    const float* query = (const float*)d_in[0];
    const float* Ws[6] = { (const float*)d_in[1], (const float*)d_in[2],
                           (const float*)d_in[3], (const float*)d_in[4],
                           (const float*)d_in[5], (const float*)d_in[6] };
    const float* gamma = (const float*)d_in[7];
    const float* beta  = (const float*)d_in[8];

    float *b0, *b1;
    __nv_bfloat16 *ah, *al, *bh, *bl, *qh, *ql, *kh, *kl, *vh, *vl, *wh, *wl;
    cudaGetSymbolAddress((void**)&b0, g_buf0);
    cudaGetSymbolAddress((void**)&b1, g_buf1);
    cudaGetSymbolAddress((void**)&ah, g_ahi);
    cudaGetSymbolAddress((void**)&al, g_alo);
    cudaGetSymbolAddress((void**)&bh, g_bhi);
    cudaGetSymbolAddress((void**)&bl, g_blo);
    cudaGetSymbolAddress((void**)&qh, g_qhi);
    cudaGetSymbolAddress((void**)&ql, g_qlo);
    cudaGetSymbolAddress((void**)&kh, g_khi);
    cudaGetSymbolAddress((void**)&kl, g_klo);
    cudaGetSymbolAddress((void**)&vh, g_vhi);
    cudaGetSymbolAddress((void**)&vl, g_vlo);
    cudaGetSymbolAddress((void**)&wh, g_wthi);
    cudaGetSymbolAddress((void**)&wl, g_wtlo);

    cudaFuncSetAttribute(gemm_mma_kernel,
                         cudaFuncAttributeMaxDynamicSharedMemorySize, SMEM_GEMM);
    cudaFuncSetAttribute(attn_mma_kernel,
                         cudaFuncAttributeMaxDynamicSharedMemorySize, SMEM_ATTN);

    const dim3 ggrid(DM / 128, MROWS / 128);
    const int split_blocks = (MROWS * DM / 4) / 256;
    const dim3 tgrid(DM / 32, DM / 32);
    const dim3 tblock(32, 8);

    for (int i = 0; i < 6; i++)
        transpose_split_kernel<<<tgrid, tblock>>>(Ws[i], wh + (size_t)i*DM*DM,
                                                  wl + (size_t)i*DM*DM);

    // split query once
    split_kernel<<<split_blocks, 256>>>((const float4*)query,
                                        (__nv_bfloat162*)ah, (__nv_bfloat162*)al);

    // QKV projections -> bf16 hi/lo directly (Q pre-scaled by 1/8)
    gemm_mma_kernel<<<ggrid, 256, SMEM_GEMM>>>(ah, al, wh + 0*DM*DM, wl + 0*DM*DM,
                                               nullptr, qh, ql, 0, 0.125f);
    gemm_mma_kernel<<<ggrid, 256, SMEM_GEMM>>>(ah, al, wh + 1*DM*DM, wl + 1*DM*DM,
                                               nullptr, kh, kl, 0, 1.f);
    gemm_mma_kernel<<<ggrid, 256, SMEM_GEMM>>>(ah, al, wh + 2*DM*DM, wl + 2*DM*DM,
                                               nullptr, vh, vl, 0, 1.f);

    // attention -> ctx bf16 hi/lo in ah/al
    attn_mma_kernel<<<dim3(SS/128, HH, BB), 256, SMEM_ATTN>>>(
        qh, ql, kh, kl, vh, vl, ah, al);

    // ctx @ W1 -> fp32 b0 ; LN(b0 + query) -> fp32 b1 + split ah/al
    gemm_mma_kernel<<<ggrid, 256, SMEM_GEMM>>>(ah, al, wh + 3*DM*DM, wl + 3*DM*DM,
                                               b0, nullptr, nullptr, 0, 1.f);
    ln_kernel<<<MROWS, 256>>>(b0, query, gamma, beta, b1, ah, al);

    // relu(residual @ W2) -> split bh/bl ; @ W3 -> fp32 b0 ; LN -> out
    gemm_mma_kernel<<<ggrid, 256, SMEM_GEMM>>>(ah, al, wh + 4*DM*DM, wl + 4*DM*DM,
                                               nullptr, bh, bl, 1, 1.f);
    gemm_mma_kernel<<<ggrid, 256, SMEM_GEMM>>>(bh, bl, wh + 5*DM*DM, wl + 5*DM*DM,
                                               b0, nullptr, nullptr, 0, 1.f);
    ln_kernel<<<MROWS, 256>>>(b0, b1, gamma, beta, (float*)d_out, nullptr, nullptr);
}

// round 5
// speedup vs baseline: 2.8203x; 1.0022x over previous
#include <cuda_runtime.h>
#include <cuda_bf16.h>
#include <cstdint>
#include <math.h>

#define SS 2048
#define DM 1024
#define HH 16
#define DHD 64
#define BB 2
#define MROWS (BB*SS)   // 4096
#define LN_EPS 1e-3f

// ---------------- scratch buffers (no allocation allowed) ----------------
__device__ float g_buf0[MROWS*DM];
__device__ float g_buf1[MROWS*DM];
__device__ __nv_bfloat16 g_ahi[MROWS*DM];
__device__ __nv_bfloat16 g_alo[MROWS*DM];
__device__ __nv_bfloat16 g_bhi[MROWS*DM];
__device__ __nv_bfloat16 g_blo[MROWS*DM];
__device__ __nv_bfloat16 g_qhi[MROWS*DM];
__device__ __nv_bfloat16 g_qlo[MROWS*DM];
__device__ __nv_bfloat16 g_khi[MROWS*DM];
__device__ __nv_bfloat16 g_klo[MROWS*DM];
__device__ __nv_bfloat16 g_vhi[MROWS*DM];
__device__ __nv_bfloat16 g_vlo[MROWS*DM];
__device__ __nv_bfloat16 g_wthi[6*DM*DM];
__device__ __nv_bfloat16 g_wtlo[6*DM*DM];

// ========================= PTX helpers (portable) =========================
__device__ __forceinline__ uint32_t smem_u32(const void* p) {
    uint32_t a;
    asm("{ .reg .u64 t; cvta.to.shared.u64 t, %1; cvt.u32.u64 %0, t; }"
        : "=r"(a) : "l"(p));
    return a;
}
#define CP16(dst, src) \
    asm volatile("cp.async.cg.shared.global [%0], [%1], 16;" \
                 :: "r"(dst), "l"(src) : "memory")
#define CP_COMMIT()  asm volatile("cp.async.commit_group;" ::: "memory")
#define CP_WAIT1()   asm volatile("cp.async.wait_group 1;" ::: "memory")
#define CP_WAIT0()   asm volatile("cp.async.wait_group 0;" ::: "memory")

#define LDSM4(r, addr) \
    asm volatile("ldmatrix.sync.aligned.m8n8.x4.shared.b16 {%0,%1,%2,%3}, [%4];" \
        : "=r"((r)[0]), "=r"((r)[1]), "=r"((r)[2]), "=r"((r)[3]) : "r"(addr))
#define LDSM2(r, addr) \
    asm volatile("ldmatrix.sync.aligned.m8n8.x2.shared.b16 {%0,%1}, [%2];" \
        : "=r"((r)[0]), "=r"((r)[1]) : "r"(addr))
#define LDSM2T(r, addr) \
    asm volatile("ldmatrix.sync.aligned.m8n8.x2.trans.shared.b16 {%0,%1}, [%2];" \
        : "=r"((r)[0]), "=r"((r)[1]) : "r"(addr))
#define MMA16816(d, a, b) \
    asm volatile("mma.sync.aligned.m16n8k16.row.col.f32.bf16.bf16.f32 " \
        "{%0,%1,%2,%3}, {%4,%5,%6,%7}, {%8,%9}, {%0,%1,%2,%3};" \
        : "+f"((d)[0]), "+f"((d)[1]), "+f"((d)[2]), "+f"((d)[3]) \
        : "r"((a)[0]), "r"((a)[1]), "r"((a)[2]), "r"((a)[3]), \
          "r"((b)[0]), "r"((b)[1]))

__device__ __forceinline__ uint32_t packbf(float lo, float hi) {
    uint32_t r;
    asm("cvt.rn.bf16x2.f32 %0, %1, %2;" : "=r"(r) : "f"(hi), "f"(lo));
    return r;
}
__device__ __forceinline__ float bfhi_f(float x) {
    return __bfloat162float(__float2bfloat16_rn(x));
}

// ================= split-bf16 GEMM via mma.sync (HMMA) ====================
// C = A @ W. A bf16 hi/lo [M,K] rm; B[n,k]=W[k,n] bf16 hi/lo [N,K] rm.
// CTA 128x256, 512 threads (16 warps, 4x4), warp tile 32x64.
// K-chunk 32, 3-stage cp.async pipeline. Single-wave grid (4,32)=128 CTAs.
#define NCH 32
#define STG48 49152
#define SMEM_GEMM (3*STG48)

__device__ __forceinline__ void gemm_issue_stage(
    uint32_t s, int tid, int m0, int n0, int kc,
    const __nv_bfloat16* __restrict__ Ahi, const __nv_bfloat16* __restrict__ Alo,
    const __nv_bfloat16* __restrict__ Bhi, const __nv_bfloat16* __restrict__ Blo)
{
    // A: 128 rows x (64B hi | 64B lo) at +0 ; B: 256 rows at +16384
    {
        int row = tid >> 2, g = tid & 3;
        uint32_t oh = row * 128 + g * 16;      oh ^= (oh >> 3) & 0x70;
        uint32_t ol = row * 128 + 64 + g * 16; ol ^= (ol >> 3) & 0x70;
        size_t ga = (size_t)(m0 + row) * DM + kc + g * 8;
        CP16(s + oh, Ahi + ga);
        CP16(s + ol, Alo + ga);
    }
#pragma unroll
    for (int i = 0; i < 2; i++) {
        int idx = tid + i * 512;
        int row = idx >> 2, g = idx & 3;
        uint32_t oh = row * 128 + g * 16;      oh ^= (oh >> 3) & 0x70;
        uint32_t ol = row * 128 + 64 + g * 16; ol ^= (ol >> 3) & 0x70;
        size_t gb = (size_t)(n0 + row) * DM + kc + g * 8;
        CP16(s + 16384 + oh, Bhi + gb);
        CP16(s + 16384 + ol, Blo + gb);
    }
}

__global__ __launch_bounds__(512, 1) void gemm_mma_kernel(
    const __nv_bfloat16* __restrict__ Ahi, const __nv_bfloat16* __restrict__ Alo,
    const __nv_bfloat16* __restrict__ Bhi, const __nv_bfloat16* __restrict__ Blo,
    float* __restrict__ Cf, __nv_bfloat16* __restrict__ Chi,
    __nv_bfloat16* __restrict__ Clo, int do_relu, float scale)
{
    extern __shared__ char smem[];
    const uint32_t sb = smem_u32(smem);
    const int tid = threadIdx.x;
    const int lane = tid & 31;
    const int wid = tid >> 5;
    const int wm = wid & 3;       // 4 warps in M (32 rows each)
    const int wn = wid >> 2;      // 4 warps in N (64 cols each)
    const int m0 = blockIdx.y * 128;
    const int n0 = blockIdx.x * 256;

    float acc[2][8][4];
#pragma unroll
    for (int mt = 0; mt < 2; mt++)
#pragma unroll
        for (int nt = 0; nt < 8; nt++)
#pragma unroll
            for (int r = 0; r < 4; r++) acc[mt][nt][r] = 0.f;

    // A ldmatrix lane mapping (m16k16): rows lane&15, k-half lane>>4
    const int a_row = lane & 15;
    const int a_kb  = (lane >> 4) << 4;
    // B ldmatrix-x4 lane mapping (two n8 tiles per LDSM4):
    // m = lane>>3: rows +((m>>1)*8), k-half (m&1)
    const int b_row = ((lane >> 4) << 3) + (lane & 7);
    const int b_kb  = ((lane >> 3) & 1) << 4;

    gemm_issue_stage(sb, tid, m0, n0, 0, Ahi, Alo, Bhi, Blo);
    CP_COMMIT();
    gemm_issue_stage(sb + STG48, tid, m0, n0, 32, Ahi, Alo, Bhi, Blo);
    CP_COMMIT();

    for (int c = 0; c < NCH; c++) {
        if (c + 1 < NCH) CP_WAIT1(); else CP_WAIT0();
        __syncthreads();

        const uint32_t sA = sb + (c % 3) * STG48;
        const uint32_t sB = sA + 16384;

#pragma unroll
        for (int kk = 0; kk < 2; kk++) {
            const int kbyte = kk * 32;
            uint32_t af[2][4], af2[2][4], bf[8][2];

            // A hi
#pragma unroll
            for (int mt = 0; mt < 2; mt++) {
                uint32_t o = (uint32_t)(wm*32 + mt*16 + a_row) * 128 + kbyte + a_kb;
                o ^= (o >> 3) & 0x70;
                LDSM4(af[mt], sA + o);
            }
            // B hi (4 LDSM4 -> 8 n-tiles)
#pragma unroll
            for (int p = 0; p < 4; p++) {
                uint32_t rr[4];
                uint32_t o = (uint32_t)(wn*64 + p*16 + b_row) * 128 + kbyte + b_kb;
                o ^= (o >> 3) & 0x70;
                LDSM4(rr, sB + o);
                bf[p*2][0]   = rr[0]; bf[p*2][1]   = rr[1];
                bf[p*2+1][0] = rr[2]; bf[p*2+1][1] = rr[3];
            }
            // hi*hi
#pragma unroll
            for (int mt = 0; mt < 2; mt++)
#pragma unroll
                for (int nt = 0; nt < 8; nt++)
                    MMA16816(acc[mt][nt], af[mt], bf[nt]);
            // A lo
#pragma unroll
            for (int mt = 0; mt < 2; mt++) {
                uint32_t o = (uint32_t)(wm*32 + mt*16 + a_row) * 128 + 64 + kbyte + a_kb;
                o ^= (o >> 3) & 0x70;
                LDSM4(af2[mt], sA + o);
            }
            // lo*hi
#pragma unroll
            for (int mt = 0; mt < 2; mt++)
#pragma unroll
                for (int nt = 0; nt < 8; nt++)
                    MMA16816(acc[mt][nt], af2[mt], bf[nt]);
            // B lo (overwrite bf)
#pragma unroll
            for (int p = 0; p < 4; p++) {
                uint32_t rr[4];
                uint32_t o = (uint32_t)(wn*64 + p*16 + b_row) * 128 + 64 + kbyte + b_kb;
                o ^= (o >> 3) & 0x70;
                LDSM4(rr, sB + o);
                bf[p*2][0]   = rr[0]; bf[p*2][1]   = rr[1];
                bf[p*2+1][0] = rr[2]; bf[p*2+1][1] = rr[3];
            }
            // hi*lo
#pragma unroll
            for (int mt = 0; mt < 2; mt++)
#pragma unroll
                for (int nt = 0; nt < 8; nt++)
                    MMA16816(acc[mt][nt], af[mt], bf[nt]);
        }

        if (c + 2 < NCH) {
            gemm_issue_stage(sb + ((c + 2) % 3) * STG48, tid, m0, n0,
                             (c + 2) * 32, Ahi, Alo, Bhi, Blo);
            CP_COMMIT();
        }
    }

    // epilogue
#pragma unroll
    for (int mt = 0; mt < 2; mt++) {
        int r0 = m0 + wm*32 + mt*16 + (lane >> 2);
#pragma unroll
        for (int nt = 0; nt < 8; nt++) {
            int cc = n0 + wn*64 + nt*8 + (lane & 3)*2;
            float v[4];
#pragma unroll
            for (int r = 0; r < 4; r++) {
                v[r] = acc[mt][nt][r] * scale;
                if (do_relu) v[r] = fmaxf(v[r], 0.f);
            }
            if (Cf) {
                *(float2*)(Cf + (size_t)r0 * DM + cc)       = make_float2(v[0], v[1]);
                *(float2*)(Cf + (size_t)(r0 + 8) * DM + cc) = make_float2(v[2], v[3]);
            }
            if (Chi) {
                *(uint32_t*)(Chi + (size_t)r0 * DM + cc)     = packbf(v[0], v[1]);
                *(uint32_t*)(Chi + (size_t)(r0+8) * DM + cc) = packbf(v[2], v[3]);
                *(uint32_t*)(Clo + (size_t)r0 * DM + cc)     =
                    packbf(v[0]-bfhi_f(v[0]), v[1]-bfhi_f(v[1]));
                *(uint32_t*)(Clo + (size_t)(r0+8) * DM + cc) =
                    packbf(v[2]-bfhi_f(v[2]), v[3]-bfhi_f(v[3]));
            }
        }
    }
}

// =================== split fp32 -> bf16 hi/lo (elementwise) ===============
__global__ __launch_bounds__(256) void split_kernel(
    const float4* __restrict__ X, __nv_bfloat162* __restrict__ hi,
    __nv_bfloat162* __restrict__ lo)
{
    int i = blockIdx.x * 256 + threadIdx.x;
    float4 v = X[i];
    ((uint32_t*)hi)[i*2+0] = packbf(v.x, v.y);
    ((uint32_t*)hi)[i*2+1] = packbf(v.z, v.w);
    ((uint32_t*)lo)[i*2+0] = packbf(v.x-bfhi_f(v.x), v.y-bfhi_f(v.y));
    ((uint32_t*)lo)[i*2+1] = packbf(v.z-bfhi_f(v.z), v.w-bfhi_f(v.w));
}

// ===== transpose + split, all 6 weights in one launch (z = weight id) =====
struct W6 { const float* p[6]; };

__global__ __launch_bounds__(256) void transpose_split_all_kernel(
    W6 ws, __nv_bfloat16* __restrict__ Thi, __nv_bfloat16* __restrict__ Tlo)
{
    __shared__ float t[32][33];
    const int wz = blockIdx.z;
    const float* W = ws.p[wz];
    __nv_bfloat16* th = Thi + (size_t)wz * DM * DM;
    __nv_bfloat16* tl = Tlo + (size_t)wz * DM * DM;
    const int n0 = blockIdx.x * 32, k0 = blockIdx.y * 32;
    const int tx = threadIdx.x, ty = threadIdx.y;
#pragma unroll
    for (int r = 0; r < 32; r += 8)
        t[ty + r][tx] = W[(size_t)(k0 + ty + r) * DM + n0 + tx];
    __syncthreads();
#pragma unroll
    for (int r = 0; r < 32; r += 8) {
        float v = t[tx][ty + r];
        __nv_bfloat16 h = __float2bfloat16_rn(v);
        __nv_bfloat16 l = __float2bfloat16_rn(v - __bfloat162float(h));
        size_t o = (size_t)(n0 + ty + r) * DM + k0 + tx;
        th[o] = h;
        tl[o] = l;
    }
}

// ============== tensor-core flash attention, split bf16 ===================
#define AT_QH 0
#define AT_QL 16384
#define AT_STG 32768
#define AT_STGSZ 32768
#define SMEM_ATTN (32768 + 2*32768)   // 96 KB

__device__ __forceinline__ void attn_issue_kv(
    uint32_t s, int tid, size_t base, int kt,
    const __nv_bfloat16* __restrict__ Kh, const __nv_bfloat16* __restrict__ Kl,
    const __nv_bfloat16* __restrict__ Vh, const __nv_bfloat16* __restrict__ Vl)
{
#pragma unroll
    for (int i = 0; i < 2; i++) {
        int idx = tid + i * 256;
        int row = idx >> 3, c16 = idx & 7;
        uint32_t off = row * 128 + c16 * 16;
        off ^= (off >> 3) & 0x70;
        size_t g = base + (size_t)(kt * 64 + row) * DM + c16 * 8;
        CP16(s + off,          Kh + g);
        CP16(s + 8192  + off,  Kl + g);
        CP16(s + 16384 + off,  Vh + g);
        CP16(s + 24576 + off,  Vl + g);
    }
}

__global__ __launch_bounds__(256, 2) void attn_mma_kernel(
    const __nv_bfloat16* __restrict__ Qh, const __nv_bfloat16* __restrict__ Ql,
    const __nv_bfloat16* __restrict__ Kh, const __nv_bfloat16* __restrict__ Kl,
    const __nv_bfloat16* __restrict__ Vh, const __nv_bfloat16* __restrict__ Vl,
    __nv_bfloat16* __restrict__ Ohi, __nv_bfloat16* __restrict__ Olo)
{
    extern __shared__ char smem[];
    const uint32_t sb = smem_u32(smem);
    const int tid = threadIdx.x, lane = tid & 31, w = tid >> 5;
    const int q0 = blockIdx.x * 128;
    const int h = blockIdx.y, b = blockIdx.z;
    const size_t base = (size_t)b * SS * DM + h * DHD;

#pragma unroll
    for (int i = 0; i < 4; i++) {
        int idx = tid + i * 256;
        int row = idx >> 3, c16 = idx & 7;
        uint32_t off = row * 128 + c16 * 16;
        off ^= (off >> 3) & 0x70;
        size_t g = base + (size_t)(q0 + row) * DM + c16 * 8;
        CP16(sb + AT_QH + off, Qh + g);
        CP16(sb + AT_QL + off, Ql + g);
    }
    attn_issue_kv(sb + AT_STG, tid, base, 0, Kh, Kl, Vh, Vl);
    CP_COMMIT();

    float acco[8][4];
#pragma unroll
    for (int nt = 0; nt < 8; nt++)
#pragma unroll
        for (int r = 0; r < 4; r++) acco[nt][r] = 0.f;
    float runm0 = -1e30f, runm1 = -1e30f, runs0 = 0.f, runs1 = 0.f;

    const int arow = w * 16 + (lane & 15);
    const int akb  = (lane >> 4) << 4;
    const int brow = lane & 7;
    const int bkb  = ((lane >> 3) & 1) << 4;
    const int vrow = lane & 15;

    for (int kt = 0; kt < SS / 64; kt++) {
        if (kt + 1 < SS / 64) {
            attn_issue_kv(sb + AT_STG + ((kt + 1) & 1) * AT_STGSZ, tid, base,
                          kt + 1, Kh, Kl, Vh, Vl);
            CP_COMMIT();
            CP_WAIT1();
        } else {
            CP_WAIT0();
        }
        __syncthreads();

        const uint32_t sK  = sb + AT_STG + (kt & 1) * AT_STGSZ;
        const uint32_t sKl = sK + 8192;
        const uint32_t sV  = sK + 16384;
        const uint32_t sVl = sK + 24576;

        float accs[8][4];
#pragma unroll
        for (int nt = 0; nt < 8; nt++)
#pragma unroll
            for (int r = 0; r < 4; r++) accs[nt][r] = 0.f;

#pragma unroll
        for (int ks = 0; ks < 4; ks++) {
            uint32_t aqh[4], aql[4];
            uint32_t o = (uint32_t)arow * 128 + ks * 32 + akb;
            o ^= (o >> 3) & 0x70;
            LDSM4(aqh, sb + AT_QH + o);
            LDSM4(aql, sb + AT_QL + o);
#pragma unroll
            for (int nt = 0; nt < 8; nt++) {
                uint32_t bo = (uint32_t)(nt * 8 + brow) * 128 + ks * 32 + bkb;
                bo ^= (bo >> 3) & 0x70;
                uint32_t bkh[2], bkl[2];
                LDSM2(bkh, sK + bo);
                LDSM2(bkl, sKl + bo);
                MMA16816(accs[nt], aqh, bkh);
                MMA16816(accs[nt], aqh, bkl);
                MMA16816(accs[nt], aql, bkh);
            }
        }

        float mx0 = -1e30f, mx1 = -1e30f;
#pragma unroll
        for (int nt = 0; nt < 8; nt++) {
            mx0 = fmaxf(mx0, fmaxf(accs[nt][0], accs[nt][1]));
            mx1 = fmaxf(mx1, fmaxf(accs[nt][2], accs[nt][3]));
        }
        mx0 = fmaxf(mx0, __shfl_xor_sync(0xffffffffu, mx0, 1));
        mx0 = fmaxf(mx0, __shfl_xor_sync(0xffffffffu, mx0, 2));
        mx1 = fmaxf(mx1, __shfl_xor_sync(0xffffffffu, mx1, 1));
        mx1 = fmaxf(mx1, __shfl_xor_sync(0xffffffffu, mx1, 2));
        float nm0 = fmaxf(runm0, mx0), nm1 = fmaxf(runm1, mx1);
        float c0 = __expf(runm0 - nm0), c1 = __expf(runm1 - nm1);
        runm0 = nm0; runm1 = nm1;
        float s0 = 0.f, s1 = 0.f;
#pragma unroll
        for (int nt = 0; nt < 8; nt++) {
            accs[nt][0] = __expf(accs[nt][0] - nm0); s0 += accs[nt][0];
            accs[nt][1] = __expf(accs[nt][1] - nm0); s0 += accs[nt][1];
            accs[nt][2] = __expf(accs[nt][2] - nm1); s1 += accs[nt][2];
            accs[nt][3] = __expf(accs[nt][3] - nm1); s1 += accs[nt][3];
        }
        s0 += __shfl_xor_sync(0xffffffffu, s0, 1);
        s0 += __shfl_xor_sync(0xffffffffu, s0, 2);
        s1 += __shfl_xor_sync(0xffffffffu, s1, 1);
        s1 += __shfl_xor_sync(0xffffffffu, s1, 2);
        runs0 = runs0 * c0 + s0;
        runs1 = runs1 * c1 + s1;
#pragma unroll
        for (int nt = 0; nt < 8; nt++) {
            acco[nt][0] *= c0; acco[nt][1] *= c0;
            acco[nt][2] *= c1; acco[nt][3] *= c1;
        }

#pragma unroll
        for (int j = 0; j < 4; j++) {
            uint32_t aph[4], apl[4];
            float* pa = accs[2*j];
            float* pb = accs[2*j + 1];
            aph[0] = packbf(pa[0], pa[1]);
            aph[1] = packbf(pa[2], pa[3]);
            aph[2] = packbf(pb[0], pb[1]);
            aph[3] = packbf(pb[2], pb[3]);
            apl[0] = packbf(pa[0]-bfhi_f(pa[0]), pa[1]-bfhi_f(pa[1]));
            apl[1] = packbf(pa[2]-bfhi_f(pa[2]), pa[3]-bfhi_f(pa[3]));
            apl[2] = packbf(pb[0]-bfhi_f(pb[0]), pb[1]-bfhi_f(pb[1]));
            apl[3] = packbf(pb[2]-bfhi_f(pb[2]), pb[3]-bfhi_f(pb[3]));
            uint32_t vr = (uint32_t)(j * 16 + vrow) * 128;
#pragma unroll
            for (int nt = 0; nt < 8; nt++) {
                uint32_t vo = vr + nt * 16;
                vo ^= (vo >> 3) & 0x70;
                uint32_t bvh[2], bvl[2];
                LDSM2T(bvh, sV + vo);
                LDSM2T(bvl, sVl + vo);
                MMA16816(acco[nt], aph, bvh);
                MMA16816(acco[nt], aph, bvl);
                MMA16816(acco[nt], apl, bvh);
            }
        }
        __syncthreads();
    }

    const float i0 = 1.f / runs0, i1 = 1.f / runs1;
    const size_t r0 = (size_t)(b * SS + q0 + w * 16 + (lane >> 2));
#pragma unroll
    for (int nt = 0; nt < 8; nt++) {
        int cc = h * DHD + nt * 8 + (lane & 3) * 2;
        float x0 = acco[nt][0] * i0, x1 = acco[nt][1] * i0;
        float x2 = acco[nt][2] * i1, x3 = acco[nt][3] * i1;
        *(uint32_t*)(Ohi + r0 * DM + cc)     = packbf(x0, x1);
        *(uint32_t*)(Ohi + (r0+8) * DM + cc) = packbf(x2, x3);
        *(uint32_t*)(Olo + r0 * DM + cc)     = packbf(x0-bfhi_f(x0), x1-bfhi_f(x1));
        *(uint32_t*)(Olo + (r0+8) * DM + cc) = packbf(x2-bfhi_f(x2), x3-bfhi_f(x3));
    }
}

// ======================= residual-add + LayerNorm =========================
__device__ __forceinline__ float block_sum256(float v, float* red) {
#pragma unroll
    for (int o = 16; o; o >>= 1) v += __shfl_xor_sync(0xffffffffu, v, o);
    int lane = threadIdx.x & 31, wid = threadIdx.x >> 5;
    if (lane == 0) red[wid] = v;
    __syncthreads();
    if (threadIdx.x < 32) {
        float t = (threadIdx.x < 8) ? red[threadIdx.x] : 0.f;
#pragma unroll
        for (int o = 4; o; o >>= 1) t += __shfl_xor_sync(0xffffffffu, t, o);
        if (threadIdx.x == 0) red[0] = t;
    }
    __syncthreads();
    float r = red[0];
    __syncthreads();
    return r;
}

__global__ __launch_bounds__(256) void ln_kernel(
    const float* __restrict__ x, const float* __restrict__ res,
    const float* __restrict__ gamma, const float* __restrict__ beta,
    float* __restrict__ out, __nv_bfloat16* __restrict__ ohi,
    __nv_bfloat16* __restrict__ olo)
{
    __shared__ float red[8];
    const int row = blockIdx.x;
    const int tid = threadIdx.x;

    float4 v = ((const float4*)(x + (size_t)row * DM))[tid];
    float4 r = ((const float4*)(res + (size_t)row * DM))[tid];
    v.x += r.x; v.y += r.y; v.z += r.z; v.w += r.w;

    float s = v.x + v.y + v.z + v.w;
    float tot = block_sum256(s, red);
    float mean = tot * (1.f / DM);

    float dx = v.x - mean, dy = v.y - mean, dz = v.z - mean, dw = v.w - mean;
    float sq = dx*dx + dy*dy + dz*dz + dw*dw;
    float totsq = block_sum256(sq, red);
    float rstd = rsqrtf(totsq * (1.f / DM) + LN_EPS);

    float4 g = ((const float4*)gamma)[tid];
    float4 bb = ((const float4*)beta)[tid];
    float4 o;
    o.x = dx * rstd * g.x + bb.x;
    o.y = dy * rstd * g.y + bb.y;
    o.z = dz * rstd * g.z + bb.z;
    o.w = dw * rstd * g.w + bb.w;
    if (out) ((float4*)(out + (size_t)row * DM))[tid] = o;
    if (ohi) {
        uint32_t* hp = (uint32_t*)(ohi + (size_t)row * DM) + tid*2;
        uint32_t* lp = (uint32_t*)(olo + (size_t)row * DM) + tid*2;
        hp[0] = packbf(o.x, o.y);
        hp[1] = packbf(o.z, o.w);
        lp[0] = packbf(o.x-bfhi_f(o.x), o.y-bfhi_f(o.y));
        lp[1] = packbf(o.z-bfhi_f(o.z), o.w-bfhi_f(o.w));
    }
}

// ================================ driver ==================================
extern "C" void kernel_launch(void* const* d_in, const int* in_sizes, int n_in,
                              void* d_out, int out_size)
{
    const float* query = (const float*)d_in[0];
    const float* gamma = (const float*)d_in[7];
    const float* beta  = (const float*)d_in[8];

    float *b0, *b1;
    __nv_bfloat16 *ah, *al, *bh, *bl, *qh, *ql, *kh, *kl, *vh, *vl, *wh, *wl;
    cudaGetSymbolAddress((void**)&b0, g_buf0);
    cudaGetSymbolAddress((void**)&b1, g_buf1);
    cudaGetSymbolAddress((void**)&ah, g_ahi);
    cudaGetSymbolAddress((void**)&al, g_alo);
    cudaGetSymbolAddress((void**)&bh, g_bhi);
    cudaGetSymbolAddress((void**)&bl, g_blo);
    cudaGetSymbolAddress((void**)&qh, g_qhi);
    cudaGetSymbolAddress((void**)&ql, g_qlo);
    cudaGetSymbolAddress((void**)&kh, g_khi);
    cudaGetSymbolAddress((void**)&kl, g_klo);
    cudaGetSymbolAddress((void**)&vh, g_vhi);
    cudaGetSymbolAddress((void**)&vl, g_vlo);
    cudaGetSymbolAddress((void**)&wh, g_wthi);
    cudaGetSymbolAddress((void**)&wl, g_wtlo);

    cudaFuncSetAttribute(gemm_mma_kernel,
                         cudaFuncAttributeMaxDynamicSharedMemorySize, SMEM_GEMM);
    cudaFuncSetAttribute(attn_mma_kernel,
                         cudaFuncAttributeMaxDynamicSharedMemorySize, SMEM_ATTN);

    const dim3 ggrid(DM / 256, MROWS / 128);          // (4, 32) = 128 CTAs
    const int split_blocks = (MROWS * DM / 4) / 256;

    // weight transform: one launch for all 6
    W6 ws;
    for (int i = 0; i < 6; i++) ws.p[i] = (const float*)d_in[1 + i];
    transpose_split_all_kernel<<<dim3(DM/32, DM/32, 6), dim3(32, 8)>>>(ws, wh, wl);

    // split query once
    split_kernel<<<split_blocks, 256>>>((const float4*)query,
                                        (__nv_bfloat162*)ah, (__nv_bfloat162*)al);

    // QKV projections -> bf16 hi/lo (Q pre-scaled by 1/8)
    gemm_mma_kernel<<<ggrid, 512, SMEM_GEMM>>>(ah, al, wh + 0*DM*DM, wl + 0*DM*DM,
                                               nullptr, qh, ql, 0, 0.125f);
    gemm_mma_kernel<<<ggrid, 512, SMEM_GEMM>>>(ah, al, wh + 1*DM*DM, wl + 1*DM*DM,
                                               nullptr, kh, kl, 0, 1.f);
    gemm_mma_kernel<<<ggrid, 512, SMEM_GEMM>>>(ah, al, wh + 2*DM*DM, wl + 2*DM*DM,
                                               nullptr, vh, vl, 0, 1.f);

    // attention -> ctx bf16 hi/lo in ah/al
    attn_mma_kernel<<<dim3(SS/128, HH, BB), 256, SMEM_ATTN>>>(
        qh, ql, kh, kl, vh, vl, ah, al);

    // ctx @ W1 -> fp32 b0 ; LN(b0 + query) -> fp32 b1 + split ah/al
    gemm_mma_kernel<<<ggrid, 512, SMEM_GEMM>>>(ah, al, wh + 3*DM*DM, wl + 3*DM*DM,
                                               b0, nullptr, nullptr, 0, 1.f);
    ln_kernel<<<MROWS, 256>>>(b0, query, gamma, beta, b1, ah, al);

    // relu(residual @ W2) -> split bh/bl ; @ W3 -> fp32 b0 ; LN -> out
    gemm_mma_kernel<<<ggrid, 512, SMEM_GEMM>>>(ah, al, wh + 4*DM*DM, wl + 4*DM*DM,
                                               nullptr, bh, bl, 1, 1.f);
    gemm_mma_kernel<<<ggrid, 512, SMEM_GEMM>>>(bh, bl, wh + 5*DM*DM, wl + 5*DM*DM,
                                               b0, nullptr, nullptr, 0, 1.f);
    ln_kernel<<<MROWS, 256>>>(b0, b1, gamma, beta, (float*)d_out, nullptr, nullptr);
}

// round 7
// speedup vs baseline: 2.8736x; 1.0189x over previous
#include <cuda_runtime.h>
#include <cuda_bf16.h>
#include <cstdint>
#include <math.h>

#define SS 2048
#define DM 1024
#define HH 16
#define DHD 64
#define BB 2
#define MROWS (BB*SS)   // 4096
#define LN_EPS 1e-3f

// ---------------- scratch buffers (no allocation allowed) ----------------
__device__ float g_buf0[MROWS*DM];
__device__ float g_buf1[MROWS*DM];
__device__ __nv_bfloat16 g_ahi[MROWS*DM];
__device__ __nv_bfloat16 g_alo[MROWS*DM];
__device__ __nv_bfloat16 g_bhi[MROWS*DM];
__device__ __nv_bfloat16 g_blo[MROWS*DM];
__device__ __nv_bfloat16 g_qhi[MROWS*DM];
__device__ __nv_bfloat16 g_qlo[MROWS*DM];
__device__ __nv_bfloat16 g_khi[MROWS*DM];
__device__ __nv_bfloat16 g_klo[MROWS*DM];
__device__ __nv_bfloat16 g_vhi[MROWS*DM];
__device__ __nv_bfloat16 g_vlo[MROWS*DM];
__device__ __nv_bfloat16 g_wthi[6*DM*DM];
__device__ __nv_bfloat16 g_wtlo[6*DM*DM];

// ========================= PTX helpers (portable) =========================
__device__ __forceinline__ uint32_t smem_u32(const void* p) {
    uint32_t a;
    asm("{ .reg .u64 t; cvta.to.shared.u64 t, %1; cvt.u32.u64 %0, t; }"
        : "=r"(a) : "l"(p));
    return a;
}
#define CP16(dst, src) \
    asm volatile("cp.async.cg.shared.global [%0], [%1], 16;" \
                 :: "r"(dst), "l"(src) : "memory")
#define CP_COMMIT()  asm volatile("cp.async.commit_group;" ::: "memory")
#define CP_WAIT1()   asm volatile("cp.async.wait_group 1;" ::: "memory")
#define CP_WAIT0()   asm volatile("cp.async.wait_group 0;" ::: "memory")

#define LDSM4(r, addr) \
    asm volatile("ldmatrix.sync.aligned.m8n8.x4.shared.b16 {%0,%1,%2,%3}, [%4];" \
        : "=r"((r)[0]), "=r"((r)[1]), "=r"((r)[2]), "=r"((r)[3]) : "r"(addr))
#define LDSM2(r, addr) \
    asm volatile("ldmatrix.sync.aligned.m8n8.x2.shared.b16 {%0,%1}, [%2];" \
        : "=r"((r)[0]), "=r"((r)[1]) : "r"(addr))
#define LDSM2T(r, addr) \
    asm volatile("ldmatrix.sync.aligned.m8n8.x2.trans.shared.b16 {%0,%1}, [%2];" \
        : "=r"((r)[0]), "=r"((r)[1]) : "r"(addr))
#define MMA16816(d, a, b) \
    asm volatile("mma.sync.aligned.m16n8k16.row.col.f32.bf16.bf16.f32 " \
        "{%0,%1,%2,%3}, {%4,%5,%6,%7}, {%8,%9}, {%0,%1,%2,%3};" \
        : "+f"((d)[0]), "+f"((d)[1]), "+f"((d)[2]), "+f"((d)[3]) \
        : "r"((a)[0]), "r"((a)[1]), "r"((a)[2]), "r"((a)[3]), \
          "r"((b)[0]), "r"((b)[1]))

__device__ __forceinline__ uint32_t packbf(float lo, float hi) {
    uint32_t r;
    asm("cvt.rn.bf16x2.f32 %0, %1, %2;" : "=r"(r) : "f"(hi), "f"(lo));
    return r;
}
__device__ __forceinline__ float bfhi_f(float x) {
    return __bfloat162float(__float2bfloat16_rn(x));
}

// ================= split-bf16 GEMM via mma.sync (HMMA) ====================
// 3-product scheme: C = Ah*Bh + Ah*Bl + Al*Bh (fp32 accum), error ~2^-18.
// CTA tile 128x256, 256 threads (8 warps, 2 in M x 4 in N), warp tile 64x64.
// K-chunk 32 (smem row = [hi 64B | lo 64B]), 3-stage cp.async, 144 KB smem.
// Grid (4,32) = 128 CTAs = one wave.
#define NCH 32
#define STG48 49152         // A 16 KB + B 32 KB
#define SMEM_GEMM (3*STG48)

__device__ __forceinline__ void gemm_issue_stage(
    uint32_t s, int tid, int m0, int n0, int kc,
    const __nv_bfloat16* __restrict__ Ahi, const __nv_bfloat16* __restrict__ Alo,
    const __nv_bfloat16* __restrict__ Bhi, const __nv_bfloat16* __restrict__ Blo)
{
    const int g = tid & 7;                 // constant per thread
    const int koff = (g & 3) * 8;
    // A: 128 rows x 128B ([hi 64B | lo 64B]); 1024 chunks -> 4/thread
#pragma unroll
    for (int i = 0; i < 4; i++) {
        int row = (tid + i * 256) >> 3;
        uint32_t o = row * 128 + g * 16; o ^= (o >> 3) & 0x70;
        const __nv_bfloat16* src = (g < 4)
            ? Ahi + (size_t)(m0 + row) * DM + kc + koff
            : Alo + (size_t)(m0 + row) * DM + kc + koff;
        CP16(s + o, src);
    }
    // B: 256 rows x 128B; 2048 chunks -> 8/thread
#pragma unroll
    for (int i = 0; i < 8; i++) {
        int row = (tid + i * 256) >> 3;
        uint32_t o = row * 128 + g * 16; o ^= (o >> 3) & 0x70;
        const __nv_bfloat16* src = (g < 4)
            ? Bhi + (size_t)(n0 + row) * DM + kc + koff
            : Blo + (size_t)(n0 + row) * DM + kc + koff;
        CP16(s + 16384 + o, src);
    }
}

__global__ __launch_bounds__(256, 1) void gemm_mma_kernel(
    const __nv_bfloat16* __restrict__ Ahi, const __nv_bfloat16* __restrict__ Alo,
    const __nv_bfloat16* __restrict__ Bhi, const __nv_bfloat16* __restrict__ Blo,
    float* __restrict__ Cf, __nv_bfloat16* __restrict__ Chi,
    __nv_bfloat16* __restrict__ Clo, int do_relu, float scale)
{
    extern __shared__ char smem[];
    const uint32_t sb = smem_u32(smem);
    const int tid = threadIdx.x;
    const int lane = tid & 31;
    const int wid = tid >> 5;
    const int wm = wid & 1;       // 2 warps in M (64 rows each)
    const int wn = wid >> 1;      // 4 warps in N (64 cols each)
    const int m0 = blockIdx.y * 128;
    const int n0 = blockIdx.x * 256;

    float acc[4][8][4];
#pragma unroll
    for (int mt = 0; mt < 4; mt++)
#pragma unroll
        for (int nt = 0; nt < 8; nt++)
#pragma unroll
            for (int r = 0; r < 4; r++) acc[mt][nt][r] = 0.f;

    const int a_row = lane & 15;
    const int a_kb  = (lane >> 4) << 4;
    const int b_row = ((lane >> 4) << 3) + (lane & 7);
    const int b_kb  = ((lane >> 3) & 1) << 4;

    gemm_issue_stage(sb, tid, m0, n0, 0, Ahi, Alo, Bhi, Blo);
    CP_COMMIT();
    gemm_issue_stage(sb + STG48, tid, m0, n0, 32, Ahi, Alo, Bhi, Blo);
    CP_COMMIT();

    for (int c = 0; c < NCH; c++) {
        if (c + 1 < NCH) CP_WAIT1(); else CP_WAIT0();
        __syncthreads();

        const uint32_t sA = sb + (c % 3) * STG48;
        const uint32_t sB = sA + 16384;

#pragma unroll
        for (int kk = 0; kk < 2; kk++) {
            const int kbyte = kk * 32;
            uint32_t ah[4][4], al[4][4], bfr[8][2];

            // A hi (4 m-tiles of 16 rows)
#pragma unroll
            for (int mt = 0; mt < 4; mt++) {
                uint32_t o = (uint32_t)(wm*64 + mt*16 + a_row) * 128 + kbyte + a_kb;
                o ^= (o >> 3) & 0x70;
                LDSM4(ah[mt], sA + o);
            }
            // B hi (4 LDSM4 -> 8 n-tiles)
#pragma unroll
            for (int p = 0; p < 4; p++) {
                uint32_t rr[4];
                uint32_t o = (uint32_t)(wn*64 + p*16 + b_row) * 128 + kbyte + b_kb;
                o ^= (o >> 3) & 0x70;
                LDSM4(rr, sB + o);
                bfr[p*2][0]   = rr[0]; bfr[p*2][1]   = rr[1];
                bfr[p*2+1][0] = rr[2]; bfr[p*2+1][1] = rr[3];
            }
            // hi*hi
#pragma unroll
            for (int mt = 0; mt < 4; mt++)
#pragma unroll
                for (int nt = 0; nt < 8; nt++)
                    MMA16816(acc[mt][nt], ah[mt], bfr[nt]);
            // A lo
#pragma unroll
            for (int mt = 0; mt < 4; mt++) {
                uint32_t o = (uint32_t)(wm*64 + mt*16 + a_row) * 128 + 64 + kbyte + a_kb;
                o ^= (o >> 3) & 0x70;
                LDSM4(al[mt], sA + o);
            }
            // lo*hi
#pragma unroll
            for (int mt = 0; mt < 4; mt++)
#pragma unroll
                for (int nt = 0; nt < 8; nt++)
                    MMA16816(acc[mt][nt], al[mt], bfr[nt]);
            // B lo (overwrite bfr)
#pragma unroll
            for (int p = 0; p < 4; p++) {
                uint32_t rr[4];
                uint32_t o = (uint32_t)(wn*64 + p*16 + b_row) * 128 + 64 + kbyte + b_kb;
                o ^= (o >> 3) & 0x70;
                LDSM4(rr, sB + o);
                bfr[p*2][0]   = rr[0]; bfr[p*2][1]   = rr[1];
                bfr[p*2+1][0] = rr[2]; bfr[p*2+1][1] = rr[3];
            }
            // hi*lo
#pragma unroll
            for (int mt = 0; mt < 4; mt++)
#pragma unroll
                for (int nt = 0; nt < 8; nt++)
                    MMA16816(acc[mt][nt], ah[mt], bfr[nt]);
        }

        if (c + 2 < NCH) {
            gemm_issue_stage(sb + ((c + 2) % 3) * STG48, tid, m0, n0,
                             (c + 2) * 32, Ahi, Alo, Bhi, Blo);
            CP_COMMIT();
        }
    }

    // epilogue
#pragma unroll
    for (int mt = 0; mt < 4; mt++) {
        int r0 = m0 + wm*64 + mt*16 + (lane >> 2);
#pragma unroll
        for (int nt = 0; nt < 8; nt++) {
            int cc = n0 + wn*64 + nt*8 + (lane & 3)*2;
            float v[4];
#pragma unroll
            for (int r = 0; r < 4; r++) {
                v[r] = acc[mt][nt][r] * scale;
                if (do_relu) v[r] = fmaxf(v[r], 0.f);
            }
            if (Cf) {
                *(float2*)(Cf + (size_t)r0 * DM + cc)       = make_float2(v[0], v[1]);
                *(float2*)(Cf + (size_t)(r0 + 8) * DM + cc) = make_float2(v[2], v[3]);
            }
            if (Chi) {
                *(uint32_t*)(Chi + (size_t)r0 * DM + cc)     = packbf(v[0], v[1]);
                *(uint32_t*)(Chi + (size_t)(r0+8) * DM + cc) = packbf(v[2], v[3]);
                *(uint32_t*)(Clo + (size_t)r0 * DM + cc)     =
                    packbf(v[0]-bfhi_f(v[0]), v[1]-bfhi_f(v[1]));
                *(uint32_t*)(Clo + (size_t)(r0+8) * DM + cc) =
                    packbf(v[2]-bfhi_f(v[2]), v[3]-bfhi_f(v[3]));
            }
        }
    }
}

// =================== split fp32 -> bf16 hi/lo (elementwise) ===============
__global__ __launch_bounds__(256) void split_kernel(
    const float4* __restrict__ X, __nv_bfloat162* __restrict__ hi,
    __nv_bfloat162* __restrict__ lo)
{
    int i = blockIdx.x * 256 + threadIdx.x;
    float4 v = X[i];
    ((uint32_t*)hi)[i*2+0] = packbf(v.x, v.y);
    ((uint32_t*)hi)[i*2+1] = packbf(v.z, v.w);
    ((uint32_t*)lo)[i*2+0] = packbf(v.x-bfhi_f(v.x), v.y-bfhi_f(v.y));
    ((uint32_t*)lo)[i*2+1] = packbf(v.z-bfhi_f(v.z), v.w-bfhi_f(v.w));
}

// ===== transpose + split, all 6 weights in one launch (z = weight id) =====
struct W6 { const float* p[6]; };

__global__ __launch_bounds__(256) void transpose_split_all_kernel(
    W6 ws, __nv_bfloat16* __restrict__ Thi, __nv_bfloat16* __restrict__ Tlo)
{
    __shared__ float t[32][33];
    const int wz = blockIdx.z;
    const float* W = ws.p[wz];
    __nv_bfloat16* th = Thi + (size_t)wz * DM * DM;
    __nv_bfloat16* tl = Tlo + (size_t)wz * DM * DM;
    const int n0 = blockIdx.x * 32, k0 = blockIdx.y * 32;
    const int tx = threadIdx.x, ty = threadIdx.y;
#pragma unroll
    for (int r = 0; r < 32; r += 8)
        t[ty + r][tx] = W[(size_t)(k0 + ty + r) * DM + n0 + tx];
    __syncthreads();
#pragma unroll
    for (int r = 0; r < 32; r += 8) {
        float v = t[tx][ty + r];
        __nv_bfloat16 h = __float2bfloat16_rn(v);
        __nv_bfloat16 l = __float2bfloat16_rn(v - __bfloat162float(h));
        size_t o = (size_t)(n0 + ty + r) * DM + k0 + tx;
        th[o] = h;
        tl[o] = l;
    }
}

// ============== tensor-core flash attention, split bf16 ===================
// 3-product QK and PV (round-5 proven numerics).
#define AT_QH 0
#define AT_QL 16384
#define AT_STG 32768
#define AT_STGSZ 32768
#define SMEM_ATTN (32768 + 2*32768)   // 96 KB

__device__ __forceinline__ void attn_issue_kv(
    uint32_t s, int tid, size_t base, int kt,
    const __nv_bfloat16* __restrict__ Kh, const __nv_bfloat16* __restrict__ Kl,
    const __nv_bfloat16* __restrict__ Vh, const __nv_bfloat16* __restrict__ Vl)
{
#pragma unroll
    for (int i = 0; i < 2; i++) {
        int idx = tid + i * 256;
        int row = idx >> 3, c16 = idx & 7;
        uint32_t off = row * 128 + c16 * 16;
        off ^= (off >> 3) & 0x70;
        size_t g = base + (size_t)(kt * 64 + row) * DM + c16 * 8;
        CP16(s + off,          Kh + g);
        CP16(s + 8192  + off,  Kl + g);
        CP16(s + 16384 + off,  Vh + g);
        CP16(s + 24576 + off,  Vl + g);
    }
}

__global__ __launch_bounds__(256, 2) void attn_mma_kernel(
    const __nv_bfloat16* __restrict__ Qh, const __nv_bfloat16* __restrict__ Ql,
    const __nv_bfloat16* __restrict__ Kh, const __nv_bfloat16* __restrict__ Kl,
    const __nv_bfloat16* __restrict__ Vh, const __nv_bfloat16* __restrict__ Vl,
    __nv_bfloat16* __restrict__ Ohi, __nv_bfloat16* __restrict__ Olo)
{
    extern __shared__ char smem[];
    const uint32_t sb = smem_u32(smem);
    const int tid = threadIdx.x, lane = tid & 31, w = tid >> 5;
    const int q0 = blockIdx.x * 128;
    const int h = blockIdx.y, b = blockIdx.z;
    const size_t base = (size_t)b * SS * DM + h * DHD;

#pragma unroll
    for (int i = 0; i < 4; i++) {
        int idx = tid + i * 256;
        int row = idx >> 3, c16 = idx & 7;
        uint32_t off = row * 128 + c16 * 16;
        off ^= (off >> 3) & 0x70;
        size_t g = base + (size_t)(q0 + row) * DM + c16 * 8;
        CP16(sb + AT_QH + off, Qh + g);
        CP16(sb + AT_QL + off, Ql + g);
    }
    attn_issue_kv(sb + AT_STG, tid, base, 0, Kh, Kl, Vh, Vl);
    CP_COMMIT();

    float acco[8][4];
#pragma unroll
    for (int nt = 0; nt < 8; nt++)
#pragma unroll
        for (int r = 0; r < 4; r++) acco[nt][r] = 0.f;
    float runm0 = -1e30f, runm1 = -1e30f, runs0 = 0.f, runs1 = 0.f;

    const int arow = w * 16 + (lane & 15);
    const int akb  = (lane >> 4) << 4;
    const int brow = lane & 7;
    const int bkb  = ((lane >> 3) & 1) << 4;
    const int vrow = lane & 15;

    for (int kt = 0; kt < SS / 64; kt++) {
        if (kt + 1 < SS / 64) {
            attn_issue_kv(sb + AT_STG + ((kt + 1) & 1) * AT_STGSZ, tid, base,
                          kt + 1, Kh, Kl, Vh, Vl);
            CP_COMMIT();
            CP_WAIT1();
        } else {
            CP_WAIT0();
        }
        __syncthreads();

        const uint32_t sK  = sb + AT_STG + (kt & 1) * AT_STGSZ;
        const uint32_t sKl = sK + 8192;
        const uint32_t sV  = sK + 16384;
        const uint32_t sVl = sK + 24576;

        float accs[8][4];
#pragma unroll
        for (int nt = 0; nt < 8; nt++)
#pragma unroll
            for (int r = 0; r < 4; r++) accs[nt][r] = 0.f;

#pragma unroll
        for (int ks = 0; ks < 4; ks++) {
            uint32_t aqh[4], aql[4];
            uint32_t o = (uint32_t)arow * 128 + ks * 32 + akb;
            o ^= (o >> 3) & 0x70;
            LDSM4(aqh, sb + AT_QH + o);
            LDSM4(aql, sb + AT_QL + o);
#pragma unroll
            for (int nt = 0; nt < 8; nt++) {
                uint32_t bo = (uint32_t)(nt * 8 + brow) * 128 + ks * 32 + bkb;
                bo ^= (bo >> 3) & 0x70;
                uint32_t bkh[2], bkl[2];
                LDSM2(bkh, sK + bo);
                LDSM2(bkl, sKl + bo);
                MMA16816(accs[nt], aqh, bkh);
                MMA16816(accs[nt], aqh, bkl);
                MMA16816(accs[nt], aql, bkh);
            }
        }

        float mx0 = -1e30f, mx1 = -1e30f;
#pragma unroll
        for (int nt = 0; nt < 8; nt++) {
            mx0 = fmaxf(mx0, fmaxf(accs[nt][0], accs[nt][1]));
            mx1 = fmaxf(mx1, fmaxf(accs[nt][2], accs[nt][3]));
        }
        mx0 = fmaxf(mx0, __shfl_xor_sync(0xffffffffu, mx0, 1));
        mx0 = fmaxf(mx0, __shfl_xor_sync(0xffffffffu, mx0, 2));
        mx1 = fmaxf(mx1, __shfl_xor_sync(0xffffffffu, mx1, 1));
        mx1 = fmaxf(mx1, __shfl_xor_sync(0xffffffffu, mx1, 2));
        float nm0 = fmaxf(runm0, mx0), nm1 = fmaxf(runm1, mx1);
        float c0 = __expf(runm0 - nm0), c1 = __expf(runm1 - nm1);
        runm0 = nm0; runm1 = nm1;
        float s0 = 0.f, s1 = 0.f;
#pragma unroll
        for (int nt = 0; nt < 8; nt++) {
            accs[nt][0] = __expf(accs[nt][0] - nm0); s0 += accs[nt][0];
            accs[nt][1] = __expf(accs[nt][1] - nm0); s0 += accs[nt][1];
            accs[nt][2] = __expf(accs[nt][2] - nm1); s1 += accs[nt][2];
            accs[nt][3] = __expf(accs[nt][3] - nm1); s1 += accs[nt][3];
        }
        s0 += __shfl_xor_sync(0xffffffffu, s0, 1);
        s0 += __shfl_xor_sync(0xffffffffu, s0, 2);
        s1 += __shfl_xor_sync(0xffffffffu, s1, 1);
        s1 += __shfl_xor_sync(0xffffffffu, s1, 2);
        runs0 = runs0 * c0 + s0;
        runs1 = runs1 * c1 + s1;
#pragma unroll
        for (int nt = 0; nt < 8; nt++) {
            acco[nt][0] *= c0; acco[nt][1] *= c0;
            acco[nt][2] *= c1; acco[nt][3] *= c1;
        }

#pragma unroll
        for (int j = 0; j < 4; j++) {
            uint32_t aph[4], apl[4];
            float* pa = accs[2*j];
            float* pb = accs[2*j + 1];
            aph[0] = packbf(pa[0], pa[1]);
            aph[1] = packbf(pa[2], pa[3]);
            aph[2] = packbf(pb[0], pb[1]);
            aph[3] = packbf(pb[2], pb[3]);
            apl[0] = packbf(pa[0]-bfhi_f(pa[0]), pa[1]-bfhi_f(pa[1]));
            apl[1] = packbf(pa[2]-bfhi_f(pa[2]), pa[3]-bfhi_f(pa[3]));
            apl[2] = packbf(pb[0]-bfhi_f(pb[0]), pb[1]-bfhi_f(pb[1]));
            apl[3] = packbf(pb[2]-bfhi_f(pb[2]), pb[3]-bfhi_f(pb[3]));
            uint32_t vr = (uint32_t)(j * 16 + vrow) * 128;
#pragma unroll
            for (int nt = 0; nt < 8; nt++) {
                uint32_t vo = vr + nt * 16;
                vo ^= (vo >> 3) & 0x70;
                uint32_t bvh[2], bvl[2];
                LDSM2T(bvh, sV + vo);
                LDSM2T(bvl, sVl + vo);
                MMA16816(acco[nt], aph, bvh);
                MMA16816(acco[nt], aph, bvl);
                MMA16816(acco[nt], apl, bvh);
            }
        }
        __syncthreads();
    }

    const float i0 = 1.f / runs0, i1 = 1.f / runs1;
    const size_t r0 = (size_t)(b * SS + q0 + w * 16 + (lane >> 2));
#pragma unroll
    for (int nt = 0; nt < 8; nt++) {
        int cc = h * DHD + nt * 8 + (lane & 3) * 2;
        float x0 = acco[nt][0] * i0, x1 = acco[nt][1] * i0;
        float x2 = acco[nt][2] * i1, x3 = acco[nt][3] * i1;
        *(uint32_t*)(Ohi + r0 * DM + cc)     = packbf(x0, x1);
        *(uint32_t*)(Ohi + (r0+8) * DM + cc) = packbf(x2, x3);
        *(uint32_t*)(Olo + r0 * DM + cc)     = packbf(x0-bfhi_f(x0), x1-bfhi_f(x1));
        *(uint32_t*)(Olo + (r0+8) * DM + cc) = packbf(x2-bfhi_f(x2), x3-bfhi_f(x3));
    }
}

// ======================= residual-add + LayerNorm =========================
__device__ __forceinline__ float block_sum256(float v, float* red) {
#pragma unroll
    for (int o = 16; o; o >>= 1) v += __shfl_xor_sync(0xffffffffu, v, o);
    int lane = threadIdx.x & 31, wid = threadIdx.x >> 5;
    if (lane == 0) red[wid] = v;
    __syncthreads();
    if (threadIdx.x < 32) {
        float t = (threadIdx.x < 8) ? red[threadIdx.x] : 0.f;
#pragma unroll
        for (int o = 4; o; o >>= 1) t += __shfl_xor_sync(0xffffffffu, t, o);
        if (threadIdx.x == 0) red[0] = t;
    }
    __syncthreads();
    float r = red[0];
    __syncthreads();
    return r;
}

__global__ __launch_bounds__(256) void ln_kernel(
    const float* __restrict__ x, const float* __restrict__ res,
    const float* __restrict__ gamma, const float* __restrict__ beta,
    float* __restrict__ out, __nv_bfloat16* __restrict__ ohi,
    __nv_bfloat16* __restrict__ olo)
{
    __shared__ float red[8];
    const int row = blockIdx.x;
    const int tid = threadIdx.x;

    float4 v = ((const float4*)(x + (size_t)row * DM))[tid];
    float4 r = ((const float4*)(res + (size_t)row * DM))[tid];
    v.x += r.x; v.y += r.y; v.z += r.z; v.w += r.w;

    float s = v.x + v.y + v.z + v.w;
    float tot = block_sum256(s, red);
    float mean = tot * (1.f / DM);

    float dx = v.x - mean, dy = v.y - mean, dz = v.z - mean, dw = v.w - mean;
    float sq = dx*dx + dy*dy + dz*dz + dw*dw;
    float totsq = block_sum256(sq, red);
    float rstd = rsqrtf(totsq * (1.f / DM) + LN_EPS);

    float4 g = ((const float4*)gamma)[tid];
    float4 bb = ((const float4*)beta)[tid];
    float4 o;
    o.x = dx * rstd * g.x + bb.x;
    o.y = dy * rstd * g.y + bb.y;
    o.z = dz * rstd * g.z + bb.z;
    o.w = dw * rstd * g.w + bb.w;
    if (out) ((float4*)(out + (size_t)row * DM))[tid] = o;
    if (ohi) {
        uint32_t* hp = (uint32_t*)(ohi + (size_t)row * DM) + tid*2;
        uint32_t* lp = (uint32_t*)(olo + (size_t)row * DM) + tid*2;
        hp[0] = packbf(o.x, o.y);
        hp[1] = packbf(o.z, o.w);
        lp[0] = packbf(o.x-bfhi_f(o.x), o.y-bfhi_f(o.y));
        lp[1] = packbf(o.z-bfhi_f(o.z), o.w-bfhi_f(o.w));
    }
}

// ================================ driver ==================================
extern "C" void kernel_launch(void* const* d_in, const int* in_sizes, int n_in,
                              void* d_out, int out_size)
{
    const float* query = (const float*)d_in[0];
    const float* gamma = (const float*)d_in[7];
    const float* beta  = (const float*)d_in[8];

    float *b0, *b1;
    __nv_bfloat16 *ah, *al, *bh, *bl, *qh, *ql, *kh, *kl, *vh, *vl, *wh, *wl;
    cudaGetSymbolAddress((void**)&b0, g_buf0);
    cudaGetSymbolAddress((void**)&b1, g_buf1);
    cudaGetSymbolAddress((void**)&ah, g_ahi);
    cudaGetSymbolAddress((void**)&al, g_alo);
    cudaGetSymbolAddress((void**)&bh, g_bhi);
    cudaGetSymbolAddress((void**)&bl, g_blo);
    cudaGetSymbolAddress((void**)&qh, g_qhi);
    cudaGetSymbolAddress((void**)&ql, g_qlo);
    cudaGetSymbolAddress((void**)&kh, g_khi);
    cudaGetSymbolAddress((void**)&kl, g_klo);
    cudaGetSymbolAddress((void**)&vh, g_vhi);
    cudaGetSymbolAddress((void**)&vl, g_vlo);
    cudaGetSymbolAddress((void**)&wh, g_wthi);
    cudaGetSymbolAddress((void**)&wl, g_wtlo);

    cudaFuncSetAttribute(gemm_mma_kernel,
                         cudaFuncAttributeMaxDynamicSharedMemorySize, SMEM_GEMM);
    cudaFuncSetAttribute(attn_mma_kernel,
                         cudaFuncAttributeMaxDynamicSharedMemorySize, SMEM_ATTN);

    const dim3 ggrid(DM / 256, MROWS / 128);          // (4, 32) = 128 CTAs
    const int split_blocks = (MROWS * DM / 4) / 256;

    // weight transform: one launch for all 6
    W6 ws;
    for (int i = 0; i < 6; i++) ws.p[i] = (const float*)d_in[1 + i];
    transpose_split_all_kernel<<<dim3(DM/32, DM/32, 6), dim3(32, 8)>>>(ws, wh, wl);

    // split query once
    split_kernel<<<split_blocks, 256>>>((const float4*)query,
                                        (__nv_bfloat162*)ah, (__nv_bfloat162*)al);

    // QKV projections -> bf16 hi/lo (Q pre-scaled by 1/8)
    gemm_mma_kernel<<<ggrid, 256, SMEM_GEMM>>>(ah, al, wh + 0*DM*DM, wl + 0*DM*DM,
                                               nullptr, qh, ql, 0, 0.125f);
    gemm_mma_kernel<<<ggrid, 256, SMEM_GEMM>>>(ah, al, wh + 1*DM*DM, wl + 1*DM*DM,
                                               nullptr, kh, kl, 0, 1.f);
    gemm_mma_kernel<<<ggrid, 256, SMEM_GEMM>>>(ah, al, wh + 2*DM*DM, wl + 2*DM*DM,
                                               nullptr, vh, vl, 0, 1.f);

    // attention -> ctx bf16 hi/lo in ah/al
    attn_mma_kernel<<<dim3(SS/128, HH, BB), 256, SMEM_ATTN>>>(
        qh, ql, kh, kl, vh, vl, ah, al);

    // ctx @ W1 -> fp32 b0 ; LN(b0 + query) -> fp32 b1 + split ah/al
    gemm_mma_kernel<<<ggrid, 256, SMEM_GEMM>>>(ah, al, wh + 3*DM*DM, wl + 3*DM*DM,
                                               b0, nullptr, nullptr, 0, 1.f);
    ln_kernel<<<MROWS, 256>>>(b0, query, gamma, beta, b1, ah, al);

    // relu(residual @ W2) -> split bh/bl ; @ W3 -> fp32 b0 ; LN -> out
    gemm_mma_kernel<<<ggrid, 256, SMEM_GEMM>>>(ah, al, wh + 4*DM*DM, wl + 4*DM*DM,
                                               nullptr, bh, bl, 1, 1.f);
    gemm_mma_kernel<<<ggrid, 256, SMEM_GEMM>>>(bh, bl, wh + 5*DM*DM, wl + 5*DM*DM,
                                               b0, nullptr, nullptr, 0, 1.f);
    ln_kernel<<<MROWS, 256>>>(b0, b1, gamma, beta, (float*)d_out, nullptr, nullptr);
}

// round 8
// speedup vs baseline: 6.5671x; 2.2854x over previous
#include <cuda_runtime.h>
#include <cuda_fp16.h>
#include <cstdint>
#include <math.h>

#define SS 2048
#define DM 1024
#define HH 16
#define DHD 64
#define BB 2
#define MROWS (BB*SS)   // 4096
#define LN_EPS 1e-3f

// ---------------- scratch buffers (no allocation allowed) ----------------
__device__ float g_buf0[MROWS*DM];
__device__ float g_buf1[MROWS*DM];
__device__ __half g_a[MROWS*DM];
__device__ __half g_b[MROWS*DM];
__device__ __half g_q[MROWS*DM];
__device__ __half g_k[MROWS*DM];
__device__ __half g_v[MROWS*DM];
__device__ __half g_wt[6*DM*DM];

// ========================= PTX helpers (portable) =========================
__device__ __forceinline__ uint32_t smem_u32(const void* p) {
    uint32_t a;
    asm("{ .reg .u64 t; cvta.to.shared.u64 t, %1; cvt.u32.u64 %0, t; }"
        : "=r"(a) : "l"(p));
    return a;
}
#define CP16(dst, src) \
    asm volatile("cp.async.cg.shared.global [%0], [%1], 16;" \
                 :: "r"(dst), "l"(src) : "memory")
#define CP_COMMIT()  asm volatile("cp.async.commit_group;" ::: "memory")
#define CP_WAIT1()   asm volatile("cp.async.wait_group 1;" ::: "memory")
#define CP_WAIT0()   asm volatile("cp.async.wait_group 0;" ::: "memory")

#define LDSM4(r, addr) \
    asm volatile("ldmatrix.sync.aligned.m8n8.x4.shared.b16 {%0,%1,%2,%3}, [%4];" \
        : "=r"((r)[0]), "=r"((r)[1]), "=r"((r)[2]), "=r"((r)[3]) : "r"(addr))
#define LDSM2(r, addr) \
    asm volatile("ldmatrix.sync.aligned.m8n8.x2.shared.b16 {%0,%1}, [%2];" \
        : "=r"((r)[0]), "=r"((r)[1]) : "r"(addr))
#define LDSM2T(r, addr) \
    asm volatile("ldmatrix.sync.aligned.m8n8.x2.trans.shared.b16 {%0,%1}, [%2];" \
        : "=r"((r)[0]), "=r"((r)[1]) : "r"(addr))
#define MMA16816(d, a, b) \
    asm volatile("mma.sync.aligned.m16n8k16.row.col.f32.f16.f16.f32 " \
        "{%0,%1,%2,%3}, {%4,%5,%6,%7}, {%8,%9}, {%0,%1,%2,%3};" \
        : "+f"((d)[0]), "+f"((d)[1]), "+f"((d)[2]), "+f"((d)[3]) \
        : "r"((a)[0]), "r"((a)[1]), "r"((a)[2]), "r"((a)[3]), \
          "r"((b)[0]), "r"((b)[1]))

// pack two fp32 -> f16x2 (first arg in low half)
__device__ __forceinline__ uint32_t packh(float lo, float hi) {
    uint32_t r;
    asm("cvt.rn.f16x2.f32 %0, %1, %2;" : "=r"(r) : "f"(hi), "f"(lo));
    return r;
}

// ==================== fp16 GEMM via mma.sync (HMMA) =======================
// C = A @ W. A fp16 [M,K] rm; B[n,k]=W[k,n] fp16 [N,K] rm (TN).
// CTA 128x256, 256 threads (8 warps, 2Mx4N), warp tile 64x64, K-chunk 64,
// 3-stage cp.async (144 KB smem). Grid (4,32) = 128 CTAs = one wave.
#define NCH 16              // 1024 / 64
#define STG48 49152         // A 16 KB + B 32 KB
#define SMEM_GEMM (3*STG48)

__device__ __forceinline__ void gemm_issue_stage(
    uint32_t s, int tid, int m0, int n0, int kc,
    const __half* __restrict__ A, const __half* __restrict__ B)
{
    const int g = tid & 7;
    // A: 128 rows x 128B (64 fp16); 1024 16B-chunks -> 4/thread
#pragma unroll
    for (int i = 0; i < 4; i++) {
        int row = (tid + i * 256) >> 3;
        uint32_t o = row * 128 + g * 16; o ^= (o >> 3) & 0x70;
        CP16(s + o, A + (size_t)(m0 + row) * DM + kc + g * 8);
    }
    // B: 256 rows x 128B; 2048 chunks -> 8/thread
#pragma unroll
    for (int i = 0; i < 8; i++) {
        int row = (tid + i * 256) >> 3;
        uint32_t o = row * 128 + g * 16; o ^= (o >> 3) & 0x70;
        CP16(s + 16384 + o, B + (size_t)(n0 + row) * DM + kc + g * 8);
    }
}

__global__ __launch_bounds__(256, 1) void gemm_mma_kernel(
    const __half* __restrict__ A, const __half* __restrict__ B,
    float* __restrict__ Cf, __half* __restrict__ Ch,
    int do_relu, float scale)
{
    extern __shared__ char smem[];
    const uint32_t sb = smem_u32(smem);
    const int tid = threadIdx.x;
    const int lane = tid & 31;
    const int wid = tid >> 5;
    const int wm = wid & 1;       // 2 warps in M (64 rows each)
    const int wn = wid >> 1;      // 4 warps in N (64 cols each)
    const int m0 = blockIdx.y * 128;
    const int n0 = blockIdx.x * 256;

    float acc[4][8][4];
#pragma unroll
    for (int mt = 0; mt < 4; mt++)
#pragma unroll
        for (int nt = 0; nt < 8; nt++)
#pragma unroll
            for (int r = 0; r < 4; r++) acc[mt][nt][r] = 0.f;

    const int a_row = lane & 15;
    const int a_kb  = (lane >> 4) << 4;
    const int b_row = ((lane >> 4) << 3) + (lane & 7);
    const int b_kb  = ((lane >> 3) & 1) << 4;

    gemm_issue_stage(sb, tid, m0, n0, 0, A, B);
    CP_COMMIT();
    gemm_issue_stage(sb + STG48, tid, m0, n0, 64, A, B);
    CP_COMMIT();

    for (int c = 0; c < NCH; c++) {
        if (c + 1 < NCH) CP_WAIT1(); else CP_WAIT0();
        __syncthreads();

        const uint32_t sA = sb + (c % 3) * STG48;
        const uint32_t sB = sA + 16384;

#pragma unroll
        for (int kk = 0; kk < 4; kk++) {
            const int kbyte = kk * 32;   // 16 fp16
            uint32_t af[4][4], bfr[8][2];

#pragma unroll
            for (int mt = 0; mt < 4; mt++) {
                uint32_t o = (uint32_t)(wm*64 + mt*16 + a_row) * 128 + kbyte + a_kb;
                o ^= (o >> 3) & 0x70;
                LDSM4(af[mt], sA + o);
            }
#pragma unroll
            for (int p = 0; p < 4; p++) {
                uint32_t rr[4];
                uint32_t o = (uint32_t)(wn*64 + p*16 + b_row) * 128 + kbyte + b_kb;
                o ^= (o >> 3) & 0x70;
                LDSM4(rr, sB + o);
                bfr[p*2][0]   = rr[0]; bfr[p*2][1]   = rr[1];
                bfr[p*2+1][0] = rr[2]; bfr[p*2+1][1] = rr[3];
            }
#pragma unroll
            for (int mt = 0; mt < 4; mt++)
#pragma unroll
                for (int nt = 0; nt < 8; nt++)
                    MMA16816(acc[mt][nt], af[mt], bfr[nt]);
        }

        if (c + 2 < NCH) {
            gemm_issue_stage(sb + ((c + 2) % 3) * STG48, tid, m0, n0,
                             (c + 2) * 64, A, B);
            CP_COMMIT();
        }
    }

    // epilogue
#pragma unroll
    for (int mt = 0; mt < 4; mt++) {
        int r0 = m0 + wm*64 + mt*16 + (lane >> 2);
#pragma unroll
        for (int nt = 0; nt < 8; nt++) {
            int cc = n0 + wn*64 + nt*8 + (lane & 3)*2;
            float v[4];
#pragma unroll
            for (int r = 0; r < 4; r++) {
                v[r] = acc[mt][nt][r] * scale;
                if (do_relu) v[r] = fmaxf(v[r], 0.f);
            }
            if (Cf) {
                *(float2*)(Cf + (size_t)r0 * DM + cc)       = make_float2(v[0], v[1]);
                *(float2*)(Cf + (size_t)(r0 + 8) * DM + cc) = make_float2(v[2], v[3]);
            }
            if (Ch) {
                *(uint32_t*)(Ch + (size_t)r0 * DM + cc)     = packh(v[0], v[1]);
                *(uint32_t*)(Ch + (size_t)(r0+8) * DM + cc) = packh(v[2], v[3]);
            }
        }
    }
}

// ======================= fp32 -> fp16 (elementwise) =======================
__global__ __launch_bounds__(256) void cvt_kernel(
    const float4* __restrict__ X, uint32_t* __restrict__ H)
{
    int i = blockIdx.x * 256 + threadIdx.x;
    float4 v = X[i];
    H[i*2+0] = packh(v.x, v.y);
    H[i*2+1] = packh(v.z, v.w);
}

// ======= transpose + cvt, all 6 weights in one launch (z = weight) ========
struct W6 { const float* p[6]; };

__global__ __launch_bounds__(256) void transpose_cvt_all_kernel(
    W6 ws, __half* __restrict__ T)
{
    __shared__ float t[32][33];
    const int wz = blockIdx.z;
    const float* W = ws.p[wz];
    __half* th = T + (size_t)wz * DM * DM;
    const int n0 = blockIdx.x * 32, k0 = blockIdx.y * 32;
    const int tx = threadIdx.x, ty = threadIdx.y;
#pragma unroll
    for (int r = 0; r < 32; r += 8)
        t[ty + r][tx] = W[(size_t)(k0 + ty + r) * DM + n0 + tx];
    __syncthreads();
#pragma unroll
    for (int r = 0; r < 32; r += 8)
        th[(size_t)(n0 + ty + r) * DM + k0 + tx] = __float2half_rn(t[tx][ty + r]);
}

// ================ tensor-core flash attention, fp16 =======================
// Q pre-scaled by 1/8. Br=128 (8 warps x 16 rows), Bc=64, double-buffered.
#define AT_Q 0
#define AT_STG 16384
#define AT_STGSZ 16384      // K 8KB + V 8KB
#define SMEM_ATTN (16384 + 2*16384)   // 48 KB

__device__ __forceinline__ void attn_issue_kv(
    uint32_t s, int tid, size_t base, int kt,
    const __half* __restrict__ K, const __half* __restrict__ V)
{
#pragma unroll
    for (int i = 0; i < 2; i++) {
        int idx = tid + i * 256;
        int row = idx >> 3, c16 = idx & 7;
        uint32_t off = row * 128 + c16 * 16;
        off ^= (off >> 3) & 0x70;
        size_t g = base + (size_t)(kt * 64 + row) * DM + c16 * 8;
        CP16(s + off,        K + g);
        CP16(s + 8192 + off, V + g);
    }
}

__global__ __launch_bounds__(256, 2) void attn_mma_kernel(
    const __half* __restrict__ Q, const __half* __restrict__ K,
    const __half* __restrict__ V, __half* __restrict__ O)
{
    extern __shared__ char smem[];
    const uint32_t sb = smem_u32(smem);
    const int tid = threadIdx.x, lane = tid & 31, w = tid >> 5;
    const int q0 = blockIdx.x * 128;
    const int h = blockIdx.y, b = blockIdx.z;
    const size_t base = (size_t)b * SS * DM + h * DHD;

    // load Q tile (128 rows x 128B)
#pragma unroll
    for (int i = 0; i < 4; i++) {
        int idx = tid + i * 256;
        int row = idx >> 3, c16 = idx & 7;
        uint32_t off = row * 128 + c16 * 16;
        off ^= (off >> 3) & 0x70;
        CP16(sb + AT_Q + off, Q + base + (size_t)(q0 + row) * DM + c16 * 8);
    }
    attn_issue_kv(sb + AT_STG, tid, base, 0, K, V);
    CP_COMMIT();

    float acco[8][4];
#pragma unroll
    for (int nt = 0; nt < 8; nt++)
#pragma unroll
        for (int r = 0; r < 4; r++) acco[nt][r] = 0.f;
    float runm0 = -1e30f, runm1 = -1e30f, runs0 = 0.f, runs1 = 0.f;

    const int arow = w * 16 + (lane & 15);
    const int akb  = (lane >> 4) << 4;
    const int brow = lane & 7;
    const int bkb  = ((lane >> 3) & 1) << 4;
    const int vrow = lane & 15;

    for (int kt = 0; kt < SS / 64; kt++) {
        if (kt + 1 < SS / 64) {
            attn_issue_kv(sb + AT_STG + ((kt + 1) & 1) * AT_STGSZ, tid, base,
                          kt + 1, K, V);
            CP_COMMIT();
            CP_WAIT1();
        } else {
            CP_WAIT0();
        }
        __syncthreads();

        const uint32_t sK = sb + AT_STG + (kt & 1) * AT_STGSZ;
        const uint32_t sV = sK + 8192;

        // ---- QK^T: 16x64 scores per warp ----
        float accs[8][4];
#pragma unroll
        for (int nt = 0; nt < 8; nt++)
#pragma unroll
            for (int r = 0; r < 4; r++) accs[nt][r] = 0.f;

#pragma unroll
        for (int ks = 0; ks < 4; ks++) {
            uint32_t aq[4];
            uint32_t o = (uint32_t)arow * 128 + ks * 32 + akb;
            o ^= (o >> 3) & 0x70;
            LDSM4(aq, sb + AT_Q + o);
#pragma unroll
            for (int nt = 0; nt < 8; nt++) {
                uint32_t bo = (uint32_t)(nt * 8 + brow) * 128 + ks * 32 + bkb;
                bo ^= (bo >> 3) & 0x70;
                uint32_t bk[2];
                LDSM2(bk, sK + bo);
                MMA16816(accs[nt], aq, bk);
            }
        }

        // ---- online softmax ----
        float mx0 = -1e30f, mx1 = -1e30f;
#pragma unroll
        for (int nt = 0; nt < 8; nt++) {
            mx0 = fmaxf(mx0, fmaxf(accs[nt][0], accs[nt][1]));
            mx1 = fmaxf(mx1, fmaxf(accs[nt][2], accs[nt][3]));
        }
        mx0 = fmaxf(mx0, __shfl_xor_sync(0xffffffffu, mx0, 1));
        mx0 = fmaxf(mx0, __shfl_xor_sync(0xffffffffu, mx0, 2));
        mx1 = fmaxf(mx1, __shfl_xor_sync(0xffffffffu, mx1, 1));
        mx1 = fmaxf(mx1, __shfl_xor_sync(0xffffffffu, mx1, 2));
        float nm0 = fmaxf(runm0, mx0), nm1 = fmaxf(runm1, mx1);
        float c0 = __expf(runm0 - nm0), c1 = __expf(runm1 - nm1);
        runm0 = nm0; runm1 = nm1;
        float s0 = 0.f, s1 = 0.f;
#pragma unroll
        for (int nt = 0; nt < 8; nt++) {
            accs[nt][0] = __expf(accs[nt][0] - nm0); s0 += accs[nt][0];
            accs[nt][1] = __expf(accs[nt][1] - nm0); s0 += accs[nt][1];
            accs[nt][2] = __expf(accs[nt][2] - nm1); s1 += accs[nt][2];
            accs[nt][3] = __expf(accs[nt][3] - nm1); s1 += accs[nt][3];
        }
        s0 += __shfl_xor_sync(0xffffffffu, s0, 1);
        s0 += __shfl_xor_sync(0xffffffffu, s0, 2);
        s1 += __shfl_xor_sync(0xffffffffu, s1, 1);
        s1 += __shfl_xor_sync(0xffffffffu, s1, 2);
        runs0 = runs0 * c0 + s0;
        runs1 = runs1 * c1 + s1;
#pragma unroll
        for (int nt = 0; nt < 8; nt++) {
            acco[nt][0] *= c0; acco[nt][1] *= c0;
            acco[nt][2] *= c1; acco[nt][3] *= c1;
        }

        // ---- P @ V ----
#pragma unroll
        for (int j = 0; j < 4; j++) {
            float* pa = accs[2*j];
            float* pb = accs[2*j + 1];
            uint32_t ap[4];
            ap[0] = packh(pa[0], pa[1]);
            ap[1] = packh(pa[2], pa[3]);
            ap[2] = packh(pb[0], pb[1]);
            ap[3] = packh(pb[2], pb[3]);
            uint32_t vr = (uint32_t)(j * 16 + vrow) * 128;
#pragma unroll
            for (int nt = 0; nt < 8; nt++) {
                uint32_t vo = vr + nt * 16;
                vo ^= (vo >> 3) & 0x70;
                uint32_t bv[2];
                LDSM2T(bv, sV + vo);
                MMA16816(acco[nt], ap, bv);
            }
        }
        __syncthreads();
    }

    // ---- epilogue: normalize + write ctx fp16 ----
    const float i0 = 1.f / runs0, i1 = 1.f / runs1;
    const size_t r0 = (size_t)(b * SS + q0 + w * 16 + (lane >> 2));
#pragma unroll
    for (int nt = 0; nt < 8; nt++) {
        int cc = h * DHD + nt * 8 + (lane & 3) * 2;
        *(uint32_t*)(O + r0 * DM + cc)     = packh(acco[nt][0]*i0, acco[nt][1]*i0);
        *(uint32_t*)(O + (r0+8) * DM + cc) = packh(acco[nt][2]*i1, acco[nt][3]*i1);
    }
}

// ======================= residual-add + LayerNorm =========================
__device__ __forceinline__ float block_sum256(float v, float* red) {
#pragma unroll
    for (int o = 16; o; o >>= 1) v += __shfl_xor_sync(0xffffffffu, v, o);
    int lane = threadIdx.x & 31, wid = threadIdx.x >> 5;
    if (lane == 0) red[wid] = v;
    __syncthreads();
    if (threadIdx.x < 32) {
        float t = (threadIdx.x < 8) ? red[threadIdx.x] : 0.f;
#pragma unroll
        for (int o = 4; o; o >>= 1) t += __shfl_xor_sync(0xffffffffu, t, o);
        if (threadIdx.x == 0) red[0] = t;
    }
    __syncthreads();
    float r = red[0];
    __syncthreads();
    return r;
}

__global__ __launch_bounds__(256) void ln_kernel(
    const float* __restrict__ x, const float* __restrict__ res,
    const float* __restrict__ gamma, const float* __restrict__ beta,
    float* __restrict__ out, __half* __restrict__ oh)
{
    __shared__ float red[8];
    const int row = blockIdx.x;
    const int tid = threadIdx.x;

    float4 v = ((const float4*)(x + (size_t)row * DM))[tid];
    float4 r = ((const float4*)(res + (size_t)row * DM))[tid];
    v.x += r.x; v.y += r.y; v.z += r.z; v.w += r.w;

    float s = v.x + v.y + v.z + v.w;
    float tot = block_sum256(s, red);
    float mean = tot * (1.f / DM);

    float dx = v.x - mean, dy = v.y - mean, dz = v.z - mean, dw = v.w - mean;
    float sq = dx*dx + dy*dy + dz*dz + dw*dw;
    float totsq = block_sum256(sq, red);
    float rstd = rsqrtf(totsq * (1.f / DM) + LN_EPS);

    float4 g = ((const float4*)gamma)[tid];
    float4 bb = ((const float4*)beta)[tid];
    float4 o;
    o.x = dx * rstd * g.x + bb.x;
    o.y = dy * rstd * g.y + bb.y;
    o.z = dz * rstd * g.z + bb.z;
    o.w = dw * rstd * g.w + bb.w;
    if (out) ((float4*)(out + (size_t)row * DM))[tid] = o;
    if (oh) {
        uint32_t* hp = (uint32_t*)(oh + (size_t)row * DM) + tid*2;
        hp[0] = packh(o.x, o.y);
        hp[1] = packh(o.z, o.w);
    }
}

// ================================ driver ==================================
extern "C" void kernel_launch(void* const* d_in, const int* in_sizes, int n_in,
                              void* d_out, int out_size)
{
    const float* query = (const float*)d_in[0];
    const float* gamma = (const float*)d_in[7];
    const float* beta  = (const float*)d_in[8];

    float *b0, *b1;
    __half *ah, *bh, *qh, *kh, *vh, *wt;
    cudaGetSymbolAddress((void**)&b0, g_buf0);
    cudaGetSymbolAddress((void**)&b1, g_buf1);
    cudaGetSymbolAddress((void**)&ah, g_a);
    cudaGetSymbolAddress((void**)&bh, g_b);
    cudaGetSymbolAddress((void**)&qh, g_q);
    cudaGetSymbolAddress((void**)&kh, g_k);
    cudaGetSymbolAddress((void**)&vh, g_v);
    cudaGetSymbolAddress((void**)&wt, g_wt);

    cudaFuncSetAttribute(gemm_mma_kernel,
                         cudaFuncAttributeMaxDynamicSharedMemorySize, SMEM_GEMM);
    cudaFuncSetAttribute(attn_mma_kernel,
                         cudaFuncAttributeMaxDynamicSharedMemorySize, SMEM_ATTN);

    const dim3 ggrid(DM / 256, MROWS / 128);          // (4, 32) = 128 CTAs
    const int cvt_blocks = (MROWS * DM / 4) / 256;

    // weight transform: one launch for all 6
    W6 ws;
    for (int i = 0; i < 6; i++) ws.p[i] = (const float*)d_in[1 + i];
    transpose_cvt_all_kernel<<<dim3(DM/32, DM/32, 6), dim3(32, 8)>>>(ws, wt);

    // query -> fp16 once
    cvt_kernel<<<cvt_blocks, 256>>>((const float4*)query, (uint32_t*)ah);

    // QKV projections -> fp16 (Q pre-scaled by 1/8)
    gemm_mma_kernel<<<ggrid, 256, SMEM_GEMM>>>(ah, wt + 0*(size_t)DM*DM, nullptr, qh, 0, 0.125f);
    gemm_mma_kernel<<<ggrid, 256, SMEM_GEMM>>>(ah, wt + 1*(size_t)DM*DM, nullptr, kh, 0, 1.f);
    gemm_mma_kernel<<<ggrid, 256, SMEM_GEMM>>>(ah, wt + 2*(size_t)DM*DM, nullptr, vh, 0, 1.f);

    // attention -> ctx fp16 in ah
    attn_mma_kernel<<<dim3(SS/128, HH, BB), 256, SMEM_ATTN>>>(qh, kh, vh, ah);

    // ctx @ W1 -> fp32 b0 ; LN(b0 + query) -> fp32 b1 + fp16 ah
    gemm_mma_kernel<<<ggrid, 256, SMEM_GEMM>>>(ah, wt + 3*(size_t)DM*DM, b0, nullptr, 0, 1.f);
    ln_kernel<<<MROWS, 256>>>(b0, query, gamma, beta, b1, ah);

    // relu(residual @ W2) -> fp16 bh ; bh @ W3 -> fp32 b0 ; LN -> out
    gemm_mma_kernel<<<ggrid, 256, SMEM_GEMM>>>(ah, wt + 4*(size_t)DM*DM, nullptr, bh, 1, 1.f);
    gemm_mma_kernel<<<ggrid, 256, SMEM_GEMM>>>(bh, wt + 5*(size_t)DM*DM, b0, nullptr, 0, 1.f);
    ln_kernel<<<MROWS, 256>>>(b0, b1, gamma, beta, (float*)d_out, nullptr);
}

// round 9
// speedup vs baseline: 6.6945x; 1.0194x over previous
#include <cuda_runtime.h>
#include <cuda_fp16.h>
#include <cstdint>
#include <math.h>

#define SS 2048
#define DM 1024
#define HH 16
#define DHD 64
#define BB 2
#define MROWS (BB*SS)   // 4096
#define LN_EPS 1e-3f

// ---------------- scratch buffers (no allocation allowed) ----------------
__device__ float g_buf0[MROWS*DM];
__device__ float g_buf1[MROWS*DM];
__device__ __half g_a[MROWS*DM];
__device__ __half g_b[MROWS*DM];
__device__ __half g_q[MROWS*DM];
__device__ __half g_k[MROWS*DM];
__device__ __half g_v[MROWS*DM];
__device__ __half g_wt[6*DM*DM];

// ========================= PTX helpers (portable) =========================
__device__ __forceinline__ uint32_t smem_u32(const void* p) {
    uint32_t a;
    asm("{ .reg .u64 t; cvta.to.shared.u64 t, %1; cvt.u32.u64 %0, t; }"
        : "=r"(a) : "l"(p));
    return a;
}
#define CP16(dst, src) \
    asm volatile("cp.async.cg.shared.global [%0], [%1], 16;" \
                 :: "r"(dst), "l"(src) : "memory")
#define CP_COMMIT()  asm volatile("cp.async.commit_group;" ::: "memory")
#define CP_WAIT1()   asm volatile("cp.async.wait_group 1;" ::: "memory")
#define CP_WAIT0()   asm volatile("cp.async.wait_group 0;" ::: "memory")

#define LDSM4(r, addr) \
    asm volatile("ldmatrix.sync.aligned.m8n8.x4.shared.b16 {%0,%1,%2,%3}, [%4];" \
        : "=r"((r)[0]), "=r"((r)[1]), "=r"((r)[2]), "=r"((r)[3]) : "r"(addr))
#define LDSM2(r, addr) \
    asm volatile("ldmatrix.sync.aligned.m8n8.x2.shared.b16 {%0,%1}, [%2];" \
        : "=r"((r)[0]), "=r"((r)[1]) : "r"(addr))
#define LDSM2T(r, addr) \
    asm volatile("ldmatrix.sync.aligned.m8n8.x2.trans.shared.b16 {%0,%1}, [%2];" \
        : "=r"((r)[0]), "=r"((r)[1]) : "r"(addr))
#define MMA16816(d, a, b) \
    asm volatile("mma.sync.aligned.m16n8k16.row.col.f32.f16.f16.f32 " \
        "{%0,%1,%2,%3}, {%4,%5,%6,%7}, {%8,%9}, {%0,%1,%2,%3};" \
        : "+f"((d)[0]), "+f"((d)[1]), "+f"((d)[2]), "+f"((d)[3]) \
        : "r"((a)[0]), "r"((a)[1]), "r"((a)[2]), "r"((a)[3]), \
          "r"((b)[0]), "r"((b)[1]))

__device__ __forceinline__ uint32_t packh(float lo, float hi) {
    uint32_t r;
    asm("cvt.rn.f16x2.f32 %0, %1, %2;" : "=r"(r) : "f"(hi), "f"(lo));
    return r;
}

// ==================== fp16 GEMM via mma.sync (HMMA) =======================
// C = A @ W. A fp16 [M,K] rm; B[n,k]=W[k,n] fp16 [N,K] rm (TN).
// CTA 128x256, 256 threads (8 warps, 2Mx4N), warp tile 64x64, K-chunk 64,
// 3-stage cp.async (144 KB smem). Supports merged-output launches: the
// epilogue selects Ch0/Ch1/Ch2 by n-block (1024 cols per output); scale is
// applied only to output 0.
#define NCH 16              // 1024 / 64
#define STG48 49152         // A 16 KB + B 32 KB
#define SMEM_GEMM (3*STG48)

__device__ __forceinline__ void gemm_issue_stage(
    uint32_t s, int tid, int m0, int n0, int kc,
    const __half* __restrict__ A, const __half* __restrict__ B)
{
    const int g = tid & 7;
#pragma unroll
    for (int i = 0; i < 4; i++) {
        int row = (tid + i * 256) >> 3;
        uint32_t o = row * 128 + g * 16; o ^= (o >> 3) & 0x70;
        CP16(s + o, A + (size_t)(m0 + row) * DM + kc + g * 8);
    }
#pragma unroll
    for (int i = 0; i < 8; i++) {
        int row = (tid + i * 256) >> 3;
        uint32_t o = row * 128 + g * 16; o ^= (o >> 3) & 0x70;
        CP16(s + 16384 + o, B + (size_t)(n0 + row) * DM + kc + g * 8);
    }
}

__global__ __launch_bounds__(256, 1) void gemm_mma_kernel(
    const __half* __restrict__ A, const __half* __restrict__ B,
    float* __restrict__ Cf, __half* __restrict__ Ch0,
    __half* __restrict__ Ch1, __half* __restrict__ Ch2,
    int do_relu, float scale)
{
    extern __shared__ char smem[];
    const uint32_t sb = smem_u32(smem);
    const int tid = threadIdx.x;
    const int lane = tid & 31;
    const int wid = tid >> 5;
    const int wm = wid & 1;
    const int wn = wid >> 1;
    const int m0 = blockIdx.y * 128;
    const int n0 = blockIdx.x * 256;

    float acc[4][8][4];
#pragma unroll
    for (int mt = 0; mt < 4; mt++)
#pragma unroll
        for (int nt = 0; nt < 8; nt++)
#pragma unroll
            for (int r = 0; r < 4; r++) acc[mt][nt][r] = 0.f;

    const int a_row = lane & 15;
    const int a_kb  = (lane >> 4) << 4;
    const int b_row = ((lane >> 4) << 3) + (lane & 7);
    const int b_kb  = ((lane >> 3) & 1) << 4;

    gemm_issue_stage(sb, tid, m0, n0, 0, A, B);
    CP_COMMIT();
    gemm_issue_stage(sb + STG48, tid, m0, n0, 64, A, B);
    CP_COMMIT();

    for (int c = 0; c < NCH; c++) {
        if (c + 1 < NCH) CP_WAIT1(); else CP_WAIT0();
        __syncthreads();

        const uint32_t sA = sb + (c % 3) * STG48;
        const uint32_t sB = sA + 16384;

#pragma unroll
        for (int kk = 0; kk < 4; kk++) {
            const int kbyte = kk * 32;
            uint32_t af[4][4], bfr[8][2];

#pragma unroll
            for (int mt = 0; mt < 4; mt++) {
                uint32_t o = (uint32_t)(wm*64 + mt*16 + a_row) * 128 + kbyte + a_kb;
                o ^= (o >> 3) & 0x70;
                LDSM4(af[mt], sA + o);
            }
#pragma unroll
            for (int p = 0; p < 4; p++) {
                uint32_t rr[4];
                uint32_t o = (uint32_t)(wn*64 + p*16 + b_row) * 128 + kbyte + b_kb;
                o ^= (o >> 3) & 0x70;
                LDSM4(rr, sB + o);
                bfr[p*2][0]   = rr[0]; bfr[p*2][1]   = rr[1];
                bfr[p*2+1][0] = rr[2]; bfr[p*2+1][1] = rr[3];
            }
#pragma unroll
            for (int mt = 0; mt < 4; mt++)
#pragma unroll
                for (int nt = 0; nt < 8; nt++)
                    MMA16816(acc[mt][nt], af[mt], bfr[nt]);
        }

        if (c + 2 < NCH) {
            gemm_issue_stage(sb + ((c + 2) % 3) * STG48, tid, m0, n0,
                             (c + 2) * 64, A, B);
            CP_COMMIT();
        }
    }

    // epilogue — select output by n-block (merged QKV support)
    const int which = n0 >> 10;
    __half* Ch = (which == 0) ? Ch0 : ((which == 1) ? Ch1 : Ch2);
    const int ncol = n0 & 1023;
    const float sc = (which == 0) ? scale : 1.f;

#pragma unroll
    for (int mt = 0; mt < 4; mt++) {
        int r0 = m0 + wm*64 + mt*16 + (lane >> 2);
#pragma unroll
        for (int nt = 0; nt < 8; nt++) {
            int cc = ncol + wn*64 + nt*8 + (lane & 3)*2;
            float v[4];
#pragma unroll
            for (int r = 0; r < 4; r++) {
                v[r] = acc[mt][nt][r] * sc;
                if (do_relu) v[r] = fmaxf(v[r], 0.f);
            }
            if (Cf) {
                *(float2*)(Cf + (size_t)r0 * DM + cc)       = make_float2(v[0], v[1]);
                *(float2*)(Cf + (size_t)(r0 + 8) * DM + cc) = make_float2(v[2], v[3]);
            }
            if (Ch) {
                *(uint32_t*)(Ch + (size_t)r0 * DM + cc)     = packh(v[0], v[1]);
                *(uint32_t*)(Ch + (size_t)(r0+8) * DM + cc) = packh(v[2], v[3]);
            }
        }
    }
}

// ======================= fp32 -> fp16 (elementwise) =======================
__global__ __launch_bounds__(256) void cvt_kernel(
    const float4* __restrict__ X, uint32_t* __restrict__ H)
{
    int i = blockIdx.x * 256 + threadIdx.x;
    float4 v = X[i];
    H[i*2+0] = packh(v.x, v.y);
    H[i*2+1] = packh(v.z, v.w);
}

// ==== transpose + cvt, vectorized stores; all 6 weights in one launch =====
// Tile: 64 k-rows x 32 n-cols. Output writes are packed fp16x2 (4B), one
// warp covers a 128B contiguous run of one n-row.
struct W6 { const float* p[6]; };

__global__ __launch_bounds__(256) void transpose_cvt_all_kernel(
    W6 ws, __half* __restrict__ T)
{
    __shared__ float t[64][33];
    const int wz = blockIdx.z;
    const float* W = ws.p[wz];
    __half* th = T + (size_t)wz * DM * DM;
    const int n0 = blockIdx.x * 32, k0 = blockIdx.y * 64;
    const int tx = threadIdx.x, ty = threadIdx.y;   // 32 x 8
#pragma unroll
    for (int r = 0; r < 8; r++)
        t[ty + r*8][tx] = W[(size_t)(k0 + ty + r*8) * DM + n0 + tx];
    __syncthreads();
    const int tid = ty * 32 + tx;
#pragma unroll
    for (int w = 0; w < 4; w++) {
        int idx = tid + w * 256;
        int nl = idx >> 5;          // 0..31
        int u  = idx & 31;          // 0..31  (2 fp16 per u)
        uint32_t pk = packh(t[2*u][nl], t[2*u+1][nl]);
        *(uint32_t*)(th + (size_t)(n0 + nl) * DM + k0 + 2*u) = pk;
    }
}

// ================ tensor-core flash attention, fp16 =======================
// Q pre-scaled by 1/8. Br=128 (8 warps x 16 rows), Bc=64, double-buffered
// K/V; Q fragments hoisted into registers (loop-invariant, DH=64).
#define AT_Q 0
#define AT_STG 16384
#define AT_STGSZ 16384      // K 8KB + V 8KB
#define SMEM_ATTN (16384 + 2*16384)   // 48 KB

__device__ __forceinline__ void attn_issue_kv(
    uint32_t s, int tid, size_t base, int kt,
    const __half* __restrict__ K, const __half* __restrict__ V)
{
#pragma unroll
    for (int i = 0; i < 2; i++) {
        int idx = tid + i * 256;
        int row = idx >> 3, c16 = idx & 7;
        uint32_t off = row * 128 + c16 * 16;
        off ^= (off >> 3) & 0x70;
        size_t g = base + (size_t)(kt * 64 + row) * DM + c16 * 8;
        CP16(s + off,        K + g);
        CP16(s + 8192 + off, V + g);
    }
}

__global__ __launch_bounds__(256, 2) void attn_mma_kernel(
    const __half* __restrict__ Q, const __half* __restrict__ K,
    const __half* __restrict__ V, __half* __restrict__ O)
{
    extern __shared__ char smem[];
    const uint32_t sb = smem_u32(smem);
    const int tid = threadIdx.x, lane = tid & 31, w = tid >> 5;
    const int q0 = blockIdx.x * 128;
    const int h = blockIdx.y, b = blockIdx.z;
    const size_t base = (size_t)b * SS * DM + h * DHD;

    // Q tile -> smem (own cp.async group)
#pragma unroll
    for (int i = 0; i < 4; i++) {
        int idx = tid + i * 256;
        int row = idx >> 3, c16 = idx & 7;
        uint32_t off = row * 128 + c16 * 16;
        off ^= (off >> 3) & 0x70;
        CP16(sb + AT_Q + off, Q + base + (size_t)(q0 + row) * DM + c16 * 8);
    }
    CP_COMMIT();
    attn_issue_kv(sb + AT_STG, tid, base, 0, K, V);
    CP_COMMIT();

    const int arow = w * 16 + (lane & 15);
    const int akb  = (lane >> 4) << 4;
    const int brow = lane & 7;
    const int bkb  = ((lane >> 3) & 1) << 4;
    const int vrow = lane & 15;

    // wait for Q group, hoist Q fragments into registers (loop-invariant)
    CP_WAIT1();
    __syncthreads();
    uint32_t aqr[4][4];
#pragma unroll
    for (int ks = 0; ks < 4; ks++) {
        uint32_t o = (uint32_t)arow * 128 + ks * 32 + akb;
        o ^= (o >> 3) & 0x70;
        LDSM4(aqr[ks], sb + AT_Q + o);
    }

    float acco[8][4];
#pragma unroll
    for (int nt = 0; nt < 8; nt++)
#pragma unroll
        for (int r = 0; r < 4; r++) acco[nt][r] = 0.f;
    float runm0 = -1e30f, runm1 = -1e30f, runs0 = 0.f, runs1 = 0.f;

    for (int kt = 0; kt < SS / 64; kt++) {
        if (kt + 1 < SS / 64) {
            attn_issue_kv(sb + AT_STG + ((kt + 1) & 1) * AT_STGSZ, tid, base,
                          kt + 1, K, V);
            CP_COMMIT();
            CP_WAIT1();
        } else {
            CP_WAIT0();
        }
        __syncthreads();

        const uint32_t sK = sb + AT_STG + (kt & 1) * AT_STGSZ;
        const uint32_t sV = sK + 8192;

        // ---- QK^T: 16x64 scores per warp ----
        float accs[8][4];
#pragma unroll
        for (int nt = 0; nt < 8; nt++)
#pragma unroll
            for (int r = 0; r < 4; r++) accs[nt][r] = 0.f;

#pragma unroll
        for (int ks = 0; ks < 4; ks++) {
#pragma unroll
            for (int nt = 0; nt < 8; nt++) {
                uint32_t bo = (uint32_t)(nt * 8 + brow) * 128 + ks * 32 + bkb;
                bo ^= (bo >> 3) & 0x70;
                uint32_t bk[2];
                LDSM2(bk, sK + bo);
                MMA16816(accs[nt], aqr[ks], bk);
            }
        }

        // ---- online softmax ----
        float mx0 = -1e30f, mx1 = -1e30f;
#pragma unroll
        for (int nt = 0; nt < 8; nt++) {
            mx0 = fmaxf(mx0, fmaxf(accs[nt][0], accs[nt][1]));
            mx1 = fmaxf(mx1, fmaxf(accs[nt][2], accs[nt][3]));
        }
        mx0 = fmaxf(mx0, __shfl_xor_sync(0xffffffffu, mx0, 1));
        mx0 = fmaxf(mx0, __shfl_xor_sync(0xffffffffu, mx0, 2));
        mx1 = fmaxf(mx1, __shfl_xor_sync(0xffffffffu, mx1, 1));
        mx1 = fmaxf(mx1, __shfl_xor_sync(0xffffffffu, mx1, 2));
        float nm0 = fmaxf(runm0, mx0), nm1 = fmaxf(runm1, mx1);
        float c0 = __expf(runm0 - nm0), c1 = __expf(runm1 - nm1);
        runm0 = nm0; runm1 = nm1;
        float s0 = 0.f, s1 = 0.f;
#pragma unroll
        for (int nt = 0; nt < 8; nt++) {
            accs[nt][0] = __expf(accs[nt][0] - nm0); s0 += accs[nt][0];
            accs[nt][1] = __expf(accs[nt][1] - nm0); s0 += accs[nt][1];
            accs[nt][2] = __expf(accs[nt][2] - nm1); s1 += accs[nt][2];
            accs[nt][3] = __expf(accs[nt][3] - nm1); s1 += accs[nt][3];
        }
        s0 += __shfl_xor_sync(0xffffffffu, s0, 1);
        s0 += __shfl_xor_sync(0xffffffffu, s0, 2);
        s1 += __shfl_xor_sync(0xffffffffu, s1, 1);
        s1 += __shfl_xor_sync(0xffffffffu, s1, 2);
        runs0 = runs0 * c0 + s0;
        runs1 = runs1 * c1 + s1;
#pragma unroll
        for (int nt = 0; nt < 8; nt++) {
            acco[nt][0] *= c0; acco[nt][1] *= c0;
            acco[nt][2] *= c1; acco[nt][3] *= c1;
        }

        // ---- P @ V ----
#pragma unroll
        for (int j = 0; j < 4; j++) {
            float* pa = accs[2*j];
            float* pb = accs[2*j + 1];
            uint32_t ap[4];
            ap[0] = packh(pa[0], pa[1]);
            ap[1] = packh(pa[2], pa[3]);
            ap[2] = packh(pb[0], pb[1]);
            ap[3] = packh(pb[2], pb[3]);
            uint32_t vr = (uint32_t)(j * 16 + vrow) * 128;
#pragma unroll
            for (int nt = 0; nt < 8; nt++) {
                uint32_t vo = vr + nt * 16;
                vo ^= (vo >> 3) & 0x70;
                uint32_t bv[2];
                LDSM2T(bv, sV + vo);
                MMA16816(acco[nt], ap, bv);
            }
        }
        __syncthreads();
    }

    // ---- epilogue ----
    const float i0 = 1.f / runs0, i1 = 1.f / runs1;
    const size_t r0 = (size_t)(b * SS + q0 + w * 16 + (lane >> 2));
#pragma unroll
    for (int nt = 0; nt < 8; nt++) {
        int cc = h * DHD + nt * 8 + (lane & 3) * 2;
        *(uint32_t*)(O + r0 * DM + cc)     = packh(acco[nt][0]*i0, acco[nt][1]*i0);
        *(uint32_t*)(O + (r0+8) * DM + cc) = packh(acco[nt][2]*i1, acco[nt][3]*i1);
    }
}

// ======================= residual-add + LayerNorm =========================
__device__ __forceinline__ float block_sum256(float v, float* red) {
#pragma unroll
    for (int o = 16; o; o >>= 1) v += __shfl_xor_sync(0xffffffffu, v, o);
    int lane = threadIdx.x & 31, wid = threadIdx.x >> 5;
    if (lane == 0) red[wid] = v;
    __syncthreads();
    if (threadIdx.x < 32) {
        float t = (threadIdx.x < 8) ? red[threadIdx.x] : 0.f;
#pragma unroll
        for (int o = 4; o; o >>= 1) t += __shfl_xor_sync(0xffffffffu, t, o);
        if (threadIdx.x == 0) red[0] = t;
    }
    __syncthreads();
    float r = red[0];
    __syncthreads();
    return r;
}

__global__ __launch_bounds__(256) void ln_kernel(
    const float* __restrict__ x, const float* __restrict__ res,
    const float* __restrict__ gamma, const float* __restrict__ beta,
    float* __restrict__ out, __half* __restrict__ oh)
{
    __shared__ float red[8];
    const int row = blockIdx.x;
    const int tid = threadIdx.x;

    float4 v = ((const float4*)(x + (size_t)row * DM))[tid];
    float4 r = ((const float4*)(res + (size_t)row * DM))[tid];
    v.x += r.x; v.y += r.y; v.z += r.z; v.w += r.w;

    float s = v.x + v.y + v.z + v.w;
    float tot = block_sum256(s, red);
    float mean = tot * (1.f / DM);

    float dx = v.x - mean, dy = v.y - mean, dz = v.z - mean, dw = v.w - mean;
    float sq = dx*dx + dy*dy + dz*dz + dw*dw;
    float totsq = block_sum256(sq, red);
    float rstd = rsqrtf(totsq * (1.f / DM) + LN_EPS);

    float4 g = ((const float4*)gamma)[tid];
    float4 bb = ((const float4*)beta)[tid];
    float4 o;
    o.x = dx * rstd * g.x + bb.x;
    o.y = dy * rstd * g.y + bb.y;
    o.z = dz * rstd * g.z + bb.z;
    o.w = dw * rstd * g.w + bb.w;
    if (out) ((float4*)(out + (size_t)row * DM))[tid] = o;
    if (oh) {
        uint32_t* hp = (uint32_t*)(oh + (size_t)row * DM) + tid*2;
        hp[0] = packh(o.x, o.y);
        hp[1] = packh(o.z, o.w);
    }
}

// ================================ driver ==================================
extern "C" void kernel_launch(void* const* d_in, const int* in_sizes, int n_in,
                              void* d_out, int out_size)
{
    const float* query = (const float*)d_in[0];
    const float* gamma = (const float*)d_in[7];
    const float* beta  = (const float*)d_in[8];

    float *b0, *b1;
    __half *ah, *bh, *qh, *kh, *vh, *wt;
    cudaGetSymbolAddress((void**)&b0, g_buf0);
    cudaGetSymbolAddress((void**)&b1, g_buf1);
    cudaGetSymbolAddress((void**)&ah, g_a);
    cudaGetSymbolAddress((void**)&bh, g_b);
    cudaGetSymbolAddress((void**)&qh, g_q);
    cudaGetSymbolAddress((void**)&kh, g_k);
    cudaGetSymbolAddress((void**)&vh, g_v);
    cudaGetSymbolAddress((void**)&wt, g_wt);

    cudaFuncSetAttribute(gemm_mma_kernel,
                         cudaFuncAttributeMaxDynamicSharedMemorySize, SMEM_GEMM);
    cudaFuncSetAttribute(attn_mma_kernel,
                         cudaFuncAttributeMaxDynamicSharedMemorySize, SMEM_ATTN);

    const dim3 ggrid(DM / 256, MROWS / 128);          // (4, 32)
    const dim3 ggrid_qkv(3 * DM / 256, MROWS / 128);  // (12, 32)
    const int cvt_blocks = (MROWS * DM / 4) / 256;

    // weight transform: one launch for all 6 (vectorized stores)
    W6 ws;
    for (int i = 0; i < 6; i++) ws.p[i] = (const float*)d_in[1 + i];
    transpose_cvt_all_kernel<<<dim3(DM/32, DM/64, 6), dim3(32, 8)>>>(ws, wt);

    // query -> fp16 once
    cvt_kernel<<<cvt_blocks, 256>>>((const float4*)query, (uint32_t*)ah);

    // merged QKV projection (N = 3072; Q pre-scaled by 1/8)
    gemm_mma_kernel<<<ggrid_qkv, 256, SMEM_GEMM>>>(
        ah, wt, nullptr, qh, kh, vh, 0, 0.125f);

    // attention -> ctx fp16 in ah
    attn_mma_kernel<<<dim3(SS/128, HH, BB), 256, SMEM_ATTN>>>(qh, kh, vh, ah);

    // ctx @ W1 -> fp32 b0 ; LN(b0 + query) -> fp32 b1 + fp16 ah
    gemm_mma_kernel<<<ggrid, 256, SMEM_GEMM>>>(
        ah, wt + 3*(size_t)DM*DM, b0, nullptr, nullptr, nullptr, 0, 1.f);
    ln_kernel<<<MROWS, 256>>>(b0, query, gamma, beta, b1, ah);

    // relu(residual @ W2) -> fp16 bh ; bh @ W3 -> fp32 b0 ; LN -> out
    gemm_mma_kernel<<<ggrid, 256, SMEM_GEMM>>>(
        ah, wt + 4*(size_t)DM*DM, nullptr, bh, bh, bh, 1, 1.f);
    gemm_mma_kernel<<<ggrid, 256, SMEM_GEMM>>>(
        bh, wt + 5*(size_t)DM*DM, b0, nullptr, nullptr, nullptr, 0, 1.f);
    ln_kernel<<<MROWS, 256>>>(b0, b1, gamma, beta, (float*)d_out, nullptr);
}

// round 10
// speedup vs baseline: 6.7694x; 1.0112x over previous
#include <cuda_runtime.h>
#include <cuda_fp16.h>
#include <cstdint>
#include <math.h>

#define SS 2048
#define DM 1024
#define HH 16
#define DHD 64
#define BB 2
#define MROWS (BB*SS)   // 4096
#define LN_EPS 1e-3f

// ---------------- scratch buffers (no allocation allowed) ----------------
__device__ float g_buf0[MROWS*DM];
__device__ float g_buf1[MROWS*DM];
__device__ __half g_a[MROWS*DM];
__device__ __half g_b[MROWS*DM];
__device__ __half g_q[MROWS*DM];
__device__ __half g_k[MROWS*DM];
__device__ __half g_v[MROWS*DM];
__device__ __half g_wt[6*DM*DM];

// ========================= PTX helpers (portable) =========================
__device__ __forceinline__ uint32_t smem_u32(const void* p) {
    uint32_t a;
    asm("{ .reg .u64 t; cvta.to.shared.u64 t, %1; cvt.u32.u64 %0, t; }"
        : "=r"(a) : "l"(p));
    return a;
}
#define CP16(dst, src) \
    asm volatile("cp.async.cg.shared.global [%0], [%1], 16;" \
                 :: "r"(dst), "l"(src) : "memory")
#define CP_COMMIT()  asm volatile("cp.async.commit_group;" ::: "memory")
#define CP_WAIT1()   asm volatile("cp.async.wait_group 1;" ::: "memory")
#define CP_WAIT0()   asm volatile("cp.async.wait_group 0;" ::: "memory")

#define LDSM4(r, addr) \
    asm volatile("ldmatrix.sync.aligned.m8n8.x4.shared.b16 {%0,%1,%2,%3}, [%4];" \
        : "=r"((r)[0]), "=r"((r)[1]), "=r"((r)[2]), "=r"((r)[3]) : "r"(addr))
#define LDSM4T(r, addr) \
    asm volatile("ldmatrix.sync.aligned.m8n8.x4.trans.shared.b16 {%0,%1,%2,%3}, [%4];" \
        : "=r"((r)[0]), "=r"((r)[1]), "=r"((r)[2]), "=r"((r)[3]) : "r"(addr))
#define MMA16816(d, a, b) \
    asm volatile("mma.sync.aligned.m16n8k16.row.col.f32.f16.f16.f32 " \
        "{%0,%1,%2,%3}, {%4,%5,%6,%7}, {%8,%9}, {%0,%1,%2,%3};" \
        : "+f"((d)[0]), "+f"((d)[1]), "+f"((d)[2]), "+f"((d)[3]) \
        : "r"((a)[0]), "r"((a)[1]), "r"((a)[2]), "r"((a)[3]), \
          "r"((b)[0]), "r"((b)[1]))

__device__ __forceinline__ uint32_t packh(float lo, float hi) {
    uint32_t r;
    asm("cvt.rn.f16x2.f32 %0, %1, %2;" : "=r"(r) : "f"(hi), "f"(lo));
    return r;
}

// ==================== fp16 GEMM via mma.sync (HMMA) =======================
#define NCH 16              // 1024 / 64
#define STG48 49152         // A 16 KB + B 32 KB
#define SMEM_GEMM (3*STG48)

__device__ __forceinline__ void gemm_issue_stage(
    uint32_t s, int tid, int m0, int n0, int kc,
    const __half* __restrict__ A, const __half* __restrict__ B)
{
    const int g = tid & 7;
#pragma unroll
    for (int i = 0; i < 4; i++) {
        int row = (tid + i * 256) >> 3;
        uint32_t o = row * 128 + g * 16; o ^= (o >> 3) & 0x70;
        CP16(s + o, A + (size_t)(m0 + row) * DM + kc + g * 8);
    }
#pragma unroll
    for (int i = 0; i < 8; i++) {
        int row = (tid + i * 256) >> 3;
        uint32_t o = row * 128 + g * 16; o ^= (o >> 3) & 0x70;
        CP16(s + 16384 + o, B + (size_t)(n0 + row) * DM + kc + g * 8);
    }
}

__global__ __launch_bounds__(256, 1) void gemm_mma_kernel(
    const __half* __restrict__ A, const __half* __restrict__ B,
    float* __restrict__ Cf, __half* __restrict__ Ch0,
    __half* __restrict__ Ch1, __half* __restrict__ Ch2,
    int do_relu, float scale)
{
    extern __shared__ char smem[];
    const uint32_t sb = smem_u32(smem);
    const int tid = threadIdx.x;
    const int lane = tid & 31;
    const int wid = tid >> 5;
    const int wm = wid & 1;
    const int wn = wid >> 1;
    const int m0 = blockIdx.y * 128;
    const int n0 = blockIdx.x * 256;

    float acc[4][8][4];
#pragma unroll
    for (int mt = 0; mt < 4; mt++)
#pragma unroll
        for (int nt = 0; nt < 8; nt++)
#pragma unroll
            for (int r = 0; r < 4; r++) acc[mt][nt][r] = 0.f;

    const int a_row = lane & 15;
    const int a_kb  = (lane >> 4) << 4;
    const int b_row = ((lane >> 4) << 3) + (lane & 7);
    const int b_kb  = ((lane >> 3) & 1) << 4;

    gemm_issue_stage(sb, tid, m0, n0, 0, A, B);
    CP_COMMIT();
    gemm_issue_stage(sb + STG48, tid, m0, n0, 64, A, B);
    CP_COMMIT();

    for (int c = 0; c < NCH; c++) {
        if (c + 1 < NCH) CP_WAIT1(); else CP_WAIT0();
        __syncthreads();

        const uint32_t sA = sb + (c % 3) * STG48;
        const uint32_t sB = sA + 16384;

#pragma unroll
        for (int kk = 0; kk < 4; kk++) {
            const int kbyte = kk * 32;
            uint32_t af[4][4], bfr[8][2];

#pragma unroll
            for (int mt = 0; mt < 4; mt++) {
                uint32_t o = (uint32_t)(wm*64 + mt*16 + a_row) * 128 + kbyte + a_kb;
                o ^= (o >> 3) & 0x70;
                LDSM4(af[mt], sA + o);
            }
#pragma unroll
            for (int p = 0; p < 4; p++) {
                uint32_t rr[4];
                uint32_t o = (uint32_t)(wn*64 + p*16 + b_row) * 128 + kbyte + b_kb;
                o ^= (o >> 3) & 0x70;
                LDSM4(rr, sB + o);
                bfr[p*2][0]   = rr[0]; bfr[p*2][1]   = rr[1];
                bfr[p*2+1][0] = rr[2]; bfr[p*2+1][1] = rr[3];
            }
#pragma unroll
            for (int mt = 0; mt < 4; mt++)
#pragma unroll
                for (int nt = 0; nt < 8; nt++)
                    MMA16816(acc[mt][nt], af[mt], bfr[nt]);
        }

        if (c + 2 < NCH) {
            gemm_issue_stage(sb + ((c + 2) % 3) * STG48, tid, m0, n0,
                             (c + 2) * 64, A, B);
            CP_COMMIT();
        }
    }

    const int which = n0 >> 10;
    __half* Ch = (which == 0) ? Ch0 : ((which == 1) ? Ch1 : Ch2);
    const int ncol = n0 & 1023;
    const float sc = (which == 0) ? scale : 1.f;

#pragma unroll
    for (int mt = 0; mt < 4; mt++) {
        int r0 = m0 + wm*64 + mt*16 + (lane >> 2);
#pragma unroll
        for (int nt = 0; nt < 8; nt++) {
            int cc = ncol + wn*64 + nt*8 + (lane & 3)*2;
            float v[4];
#pragma unroll
            for (int r = 0; r < 4; r++) {
                v[r] = acc[mt][nt][r] * sc;
                if (do_relu) v[r] = fmaxf(v[r], 0.f);
            }
            if (Cf) {
                *(float2*)(Cf + (size_t)r0 * DM + cc)       = make_float2(v[0], v[1]);
                *(float2*)(Cf + (size_t)(r0 + 8) * DM + cc) = make_float2(v[2], v[3]);
            }
            if (Ch) {
                *(uint32_t*)(Ch + (size_t)r0 * DM + cc)     = packh(v[0], v[1]);
                *(uint32_t*)(Ch + (size_t)(r0+8) * DM + cc) = packh(v[2], v[3]);
            }
        }
    }
}

// ======================= fp32 -> fp16 (elementwise) =======================
__global__ __launch_bounds__(256) void cvt_kernel(
    const float4* __restrict__ X, uint32_t* __restrict__ H)
{
    int i = blockIdx.x * 256 + threadIdx.x;
    float4 v = X[i];
    H[i*2+0] = packh(v.x, v.y);
    H[i*2+1] = packh(v.z, v.w);
}

// ==== transpose + cvt, vectorized stores; all 6 weights in one launch =====
struct W6 { const float* p[6]; };

__global__ __launch_bounds__(256) void transpose_cvt_all_kernel(
    W6 ws, __half* __restrict__ T)
{
    __shared__ float t[64][33];
    const int wz = blockIdx.z;
    const float* W = ws.p[wz];
    __half* th = T + (size_t)wz * DM * DM;
    const int n0 = blockIdx.x * 32, k0 = blockIdx.y * 64;
    const int tx = threadIdx.x, ty = threadIdx.y;   // 32 x 8
#pragma unroll
    for (int r = 0; r < 8; r++)
        t[ty + r*8][tx] = W[(size_t)(k0 + ty + r*8) * DM + n0 + tx];
    __syncthreads();
    const int tid = ty * 32 + tx;
#pragma unroll
    for (int w = 0; w < 4; w++) {
        int idx = tid + w * 256;
        int nl = idx >> 5;
        int u  = idx & 31;
        uint32_t pk = packh(t[2*u][nl], t[2*u+1][nl]);
        *(uint32_t*)(th + (size_t)(n0 + nl) * DM + k0 + 2*u) = pk;
    }
}

// ================ tensor-core flash attention, fp16 =======================
// Q pre-scaled by log2(e)/8 (exp2-domain softmax). Br=128, Bc=64,
// double-buffered K/V; Q frags register-hoisted; paired LDSM4/LDSM4T;
// conditional rescale when running max is unchanged.
#define AT_Q 0
#define AT_STG 16384
#define AT_STGSZ 16384      // K 8KB + V 8KB
#define SMEM_ATTN (16384 + 2*16384)   // 48 KB

__device__ __forceinline__ void attn_issue_kv(
    uint32_t s, int tid, size_t base, int kt,
    const __half* __restrict__ K, const __half* __restrict__ V)
{
#pragma unroll
    for (int i = 0; i < 2; i++) {
        int idx = tid + i * 256;
        int row = idx >> 3, c16 = idx & 7;
        uint32_t off = row * 128 + c16 * 16;
        off ^= (off >> 3) & 0x70;
        size_t g = base + (size_t)(kt * 64 + row) * DM + c16 * 8;
        CP16(s + off,        K + g);
        CP16(s + 8192 + off, V + g);
    }
}

__global__ __launch_bounds__(256, 2) void attn_mma_kernel(
    const __half* __restrict__ Q, const __half* __restrict__ K,
    const __half* __restrict__ V, __half* __restrict__ O)
{
    extern __shared__ char smem[];
    const uint32_t sb = smem_u32(smem);
    const int tid = threadIdx.x, lane = tid & 31, w = tid >> 5;
    const int q0 = blockIdx.x * 128;
    const int h = blockIdx.y, b = blockIdx.z;
    const size_t base = (size_t)b * SS * DM + h * DHD;

#pragma unroll
    for (int i = 0; i < 4; i++) {
        int idx = tid + i * 256;
        int row = idx >> 3, c16 = idx & 7;
        uint32_t off = row * 128 + c16 * 16;
        off ^= (off >> 3) & 0x70;
        CP16(sb + AT_Q + off, Q + base + (size_t)(q0 + row) * DM + c16 * 8);
    }
    CP_COMMIT();
    attn_issue_kv(sb + AT_STG, tid, base, 0, K, V);
    CP_COMMIT();

    const int arow = w * 16 + (lane & 15);
    const int akb  = (lane >> 4) << 4;
    // paired-K LDSM4 lane mapping (2 n-tiles per load)
    const int kp_row = ((lane >> 4) << 3) + (lane & 7);   // + p*16
    const int kp_kb  = ((lane >> 3) & 1) << 4;            // + ks*32
    // paired-V LDSM4T lane mapping (2 n-tiles per load)
    const int vp_row = lane & 15;                          // + j*16
    const int vp_nb  = (lane >> 4) << 4;                   // + nt*16 bytes

    CP_WAIT1();
    __syncthreads();
    uint32_t aqr[4][4];
#pragma unroll
    for (int ks = 0; ks < 4; ks++) {
        uint32_t o = (uint32_t)arow * 128 + ks * 32 + akb;
        o ^= (o >> 3) & 0x70;
        LDSM4(aqr[ks], sb + AT_Q + o);
    }

    float acco[8][4];
#pragma unroll
    for (int nt = 0; nt < 8; nt++)
#pragma unroll
        for (int r = 0; r < 4; r++) acco[nt][r] = 0.f;
    float runm0 = -1e30f, runm1 = -1e30f, runs0 = 0.f, runs1 = 0.f;

    for (int kt = 0; kt < SS / 64; kt++) {
        if (kt + 1 < SS / 64) {
            attn_issue_kv(sb + AT_STG + ((kt + 1) & 1) * AT_STGSZ, tid, base,
                          kt + 1, K, V);
            CP_COMMIT();
            CP_WAIT1();
        } else {
            CP_WAIT0();
        }
        __syncthreads();

        const uint32_t sK = sb + AT_STG + (kt & 1) * AT_STGSZ;
        const uint32_t sV = sK + 8192;

        // ---- QK^T (scores in exp2 domain; Q pre-scaled by log2e/8) ----
        float accs[8][4];
#pragma unroll
        for (int nt = 0; nt < 8; nt++)
#pragma unroll
            for (int r = 0; r < 4; r++) accs[nt][r] = 0.f;

#pragma unroll
        for (int ks = 0; ks < 4; ks++) {
#pragma unroll
            for (int p = 0; p < 4; p++) {
                uint32_t bo = (uint32_t)(p * 16 + kp_row) * 128 + ks * 32 + kp_kb;
                bo ^= (bo >> 3) & 0x70;
                uint32_t rr[4];
                LDSM4(rr, sK + bo);
                MMA16816(accs[p*2],   aqr[ks], (rr));
                MMA16816(accs[p*2+1], aqr[ks], (rr + 2));
            }
        }

        // ---- online softmax (base 2) ----
        float mx0 = -1e30f, mx1 = -1e30f;
#pragma unroll
        for (int nt = 0; nt < 8; nt++) {
            mx0 = fmaxf(mx0, fmaxf(accs[nt][0], accs[nt][1]));
            mx1 = fmaxf(mx1, fmaxf(accs[nt][2], accs[nt][3]));
        }
        mx0 = fmaxf(mx0, __shfl_xor_sync(0xffffffffu, mx0, 1));
        mx0 = fmaxf(mx0, __shfl_xor_sync(0xffffffffu, mx0, 2));
        mx1 = fmaxf(mx1, __shfl_xor_sync(0xffffffffu, mx1, 1));
        mx1 = fmaxf(mx1, __shfl_xor_sync(0xffffffffu, mx1, 2));

        if (mx0 > runm0 || mx1 > runm1) {
            float nm0 = fmaxf(runm0, mx0), nm1 = fmaxf(runm1, mx1);
            float c0 = exp2f(runm0 - nm0), c1 = exp2f(runm1 - nm1);
            runm0 = nm0; runm1 = nm1;
            runs0 *= c0; runs1 *= c1;
#pragma unroll
            for (int nt = 0; nt < 8; nt++) {
                acco[nt][0] *= c0; acco[nt][1] *= c0;
                acco[nt][2] *= c1; acco[nt][3] *= c1;
            }
        }

        float s0 = 0.f, s1 = 0.f;
#pragma unroll
        for (int nt = 0; nt < 8; nt++) {
            accs[nt][0] = exp2f(accs[nt][0] - runm0); s0 += accs[nt][0];
            accs[nt][1] = exp2f(accs[nt][1] - runm0); s0 += accs[nt][1];
            accs[nt][2] = exp2f(accs[nt][2] - runm1); s1 += accs[nt][2];
            accs[nt][3] = exp2f(accs[nt][3] - runm1); s1 += accs[nt][3];
        }
        s0 += __shfl_xor_sync(0xffffffffu, s0, 1);
        s0 += __shfl_xor_sync(0xffffffffu, s0, 2);
        s1 += __shfl_xor_sync(0xffffffffu, s1, 1);
        s1 += __shfl_xor_sync(0xffffffffu, s1, 2);
        runs0 += s0;
        runs1 += s1;

        // ---- P @ V (paired LDSM4T) ----
#pragma unroll
        for (int j = 0; j < 4; j++) {
            float* pa = accs[2*j];
            float* pb = accs[2*j + 1];
            uint32_t ap[4];
            ap[0] = packh(pa[0], pa[1]);
            ap[1] = packh(pa[2], pa[3]);
            ap[2] = packh(pb[0], pb[1]);
            ap[3] = packh(pb[2], pb[3]);
            uint32_t vr = (uint32_t)(j * 16 + vp_row) * 128;
#pragma unroll
            for (int np = 0; np < 4; np++) {
                uint32_t vo = vr + np * 32 + vp_nb;
                vo ^= (vo >> 3) & 0x70;
                uint32_t rr[4];
                LDSM4T(rr, sV + vo);
                MMA16816(acco[np*2],   ap, (rr));
                MMA16816(acco[np*2+1], ap, (rr + 2));
            }
        }
        __syncthreads();
    }

    const float i0 = 1.f / runs0, i1 = 1.f / runs1;
    const size_t r0 = (size_t)(b * SS + q0 + w * 16 + (lane >> 2));
#pragma unroll
    for (int nt = 0; nt < 8; nt++) {
        int cc = h * DHD + nt * 8 + (lane & 3) * 2;
        *(uint32_t*)(O + r0 * DM + cc)     = packh(acco[nt][0]*i0, acco[nt][1]*i0);
        *(uint32_t*)(O + (r0+8) * DM + cc) = packh(acco[nt][2]*i1, acco[nt][3]*i1);
    }
}

// ======================= residual-add + LayerNorm =========================
__device__ __forceinline__ float block_sum256(float v, float* red) {
#pragma unroll
    for (int o = 16; o; o >>= 1) v += __shfl_xor_sync(0xffffffffu, v, o);
    int lane = threadIdx.x & 31, wid = threadIdx.x >> 5;
    if (lane == 0) red[wid] = v;
    __syncthreads();
    if (threadIdx.x < 32) {
        float t = (threadIdx.x < 8) ? red[threadIdx.x] : 0.f;
#pragma unroll
        for (int o = 4; o; o >>= 1) t += __shfl_xor_sync(0xffffffffu, t, o);
        if (threadIdx.x == 0) red[0] = t;
    }
    __syncthreads();
    float r = red[0];
    __syncthreads();
    return r;
}

__global__ __launch_bounds__(256) void ln_kernel(
    const float* __restrict__ x, const float* __restrict__ res,
    const float* __restrict__ gamma, const float* __restrict__ beta,
    float* __restrict__ out, __half* __restrict__ oh)
{
    __shared__ float red[8];
    const int row = blockIdx.x;
    const int tid = threadIdx.x;

    float4 v = ((const float4*)(x + (size_t)row * DM))[tid];
    float4 r = ((const float4*)(res + (size_t)row * DM))[tid];
    v.x += r.x; v.y += r.y; v.z += r.z; v.w += r.w;

    float s = v.x + v.y + v.z + v.w;
    float tot = block_sum256(s, red);
    float mean = tot * (1.f / DM);

    float dx = v.x - mean, dy = v.y - mean, dz = v.z - mean, dw = v.w - mean;
    float sq = dx*dx + dy*dy + dz*dz + dw*dw;
    float totsq = block_sum256(sq, red);
    float rstd = rsqrtf(totsq * (1.f / DM) + LN_EPS);

    float4 g = ((const float4*)gamma)[tid];
    float4 bb = ((const float4*)beta)[tid];
    float4 o;
    o.x = dx * rstd * g.x + bb.x;
    o.y = dy * rstd * g.y + bb.y;
    o.z = dz * rstd * g.z + bb.z;
    o.w = dw * rstd * g.w + bb.w;
    if (out) ((float4*)(out + (size_t)row * DM))[tid] = o;
    if (oh) {
        uint32_t* hp = (uint32_t*)(oh + (size_t)row * DM) + tid*2;
        hp[0] = packh(o.x, o.y);
        hp[1] = packh(o.z, o.w);
    }
}

// ================================ driver ==================================
extern "C" void kernel_launch(void* const* d_in, const int* in_sizes, int n_in,
                              void* d_out, int out_size)
{
    const float* query = (const float*)d_in[0];
    const float* gamma = (const float*)d_in[7];
    const float* beta  = (const float*)d_in[8];

    float *b0, *b1;
    __half *ah, *bh, *qh, *kh, *vh, *wt;
    cudaGetSymbolAddress((void**)&b0, g_buf0);
    cudaGetSymbolAddress((void**)&b1, g_buf1);
    cudaGetSymbolAddress((void**)&ah, g_a);
    cudaGetSymbolAddress((void**)&bh, g_b);
    cudaGetSymbolAddress((void**)&qh, g_q);
    cudaGetSymbolAddress((void**)&kh, g_k);
    cudaGetSymbolAddress((void**)&vh, g_v);
    cudaGetSymbolAddress((void**)&wt, g_wt);

    cudaFuncSetAttribute(gemm_mma_kernel,
                         cudaFuncAttributeMaxDynamicSharedMemorySize, SMEM_GEMM);
    cudaFuncSetAttribute(attn_mma_kernel,
                         cudaFuncAttributeMaxDynamicSharedMemorySize, SMEM_ATTN);

    const dim3 ggrid(DM / 256, MROWS / 128);          // (4, 32)
    const dim3 ggrid_qkv(3 * DM / 256, MROWS / 128);  // (12, 32)
    const int cvt_blocks = (MROWS * DM / 4) / 256;
    const float QSCALE = 0.125f * 1.44269504088896f;  // fold log2(e) for exp2

    W6 ws;
    for (int i = 0; i < 6; i++) ws.p[i] = (const float*)d_in[1 + i];
    transpose_cvt_all_kernel<<<dim3(DM/32, DM/64, 6), dim3(32, 8)>>>(ws, wt);

    cvt_kernel<<<cvt_blocks, 256>>>((const float4*)query, (uint32_t*)ah);

    // merged QKV projection (N = 3072; Q pre-scaled into exp2 domain)
    gemm_mma_kernel<<<ggrid_qkv, 256, SMEM_GEMM>>>(
        ah, wt, nullptr, qh, kh, vh, 0, QSCALE);

    // attention -> ctx fp16 in ah
    attn_mma_kernel<<<dim3(SS/128, HH, BB), 256, SMEM_ATTN>>>(qh, kh, vh, ah);

    // ctx @ W1 -> fp32 b0 ; LN(b0 + query) -> fp32 b1 + fp16 ah
    gemm_mma_kernel<<<ggrid, 256, SMEM_GEMM>>>(
        ah, wt + 3*(size_t)DM*DM, b0, nullptr, nullptr, nullptr, 0, 1.f);
    ln_kernel<<<MROWS, 256>>>(b0, query, gamma, beta, b1, ah);

    // relu(residual @ W2) -> fp16 bh ; bh @ W3 -> fp32 b0 ; LN -> out
    gemm_mma_kernel<<<ggrid, 256, SMEM_GEMM>>>(
        ah, wt + 4*(size_t)DM*DM, nullptr, bh, bh, bh, 1, 1.f);
    gemm_mma_kernel<<<ggrid, 256, SMEM_GEMM>>>(
        bh, wt + 5*(size_t)DM*DM, b0, nullptr, nullptr, nullptr, 0, 1.f);
    ln_kernel<<<MROWS, 256>>>(b0, b1, gamma, beta, (float*)d_out, nullptr);
}

// round 11
// speedup vs baseline: 6.8637x; 1.0139x over previous
#include <cuda_runtime.h>
#include <cuda_fp16.h>
#include <cstdint>
#include <math.h>

#define SS 2048
#define DM 1024
#define HH 16
#define DHD 64
#define BB 2
#define MROWS (BB*SS)   // 4096
#define LN_EPS 1e-3f

// ---------------- scratch buffers (no allocation allowed) ----------------
__device__ float g_buf0[MROWS*DM];
__device__ float g_buf1[MROWS*DM];
__device__ __half g_a[MROWS*DM];
__device__ __half g_b[MROWS*DM];
__device__ __half g_q[MROWS*DM];
__device__ __half g_k[MROWS*DM];
__device__ __half g_v[MROWS*DM];
__device__ __half g_wt[6*DM*DM];

// ========================= PTX helpers (portable) =========================
__device__ __forceinline__ uint32_t smem_u32(const void* p) {
    uint32_t a;
    asm("{ .reg .u64 t; cvta.to.shared.u64 t, %1; cvt.u32.u64 %0, t; }"
        : "=r"(a) : "l"(p));
    return a;
}
#define CP16(dst, src) \
    asm volatile("cp.async.cg.shared.global [%0], [%1], 16;" \
                 :: "r"(dst), "l"(src) : "memory")
#define CP_COMMIT()  asm volatile("cp.async.commit_group;" ::: "memory")
#define CP_WAIT1()   asm volatile("cp.async.wait_group 1;" ::: "memory")
#define CP_WAIT0()   asm volatile("cp.async.wait_group 0;" ::: "memory")

#define LDSM4(r, addr) \
    asm volatile("ldmatrix.sync.aligned.m8n8.x4.shared.b16 {%0,%1,%2,%3}, [%4];" \
        : "=r"((r)[0]), "=r"((r)[1]), "=r"((r)[2]), "=r"((r)[3]) : "r"(addr))
#define LDSM4T(r, addr) \
    asm volatile("ldmatrix.sync.aligned.m8n8.x4.trans.shared.b16 {%0,%1,%2,%3}, [%4];" \
        : "=r"((r)[0]), "=r"((r)[1]), "=r"((r)[2]), "=r"((r)[3]) : "r"(addr))
#define MMA16816(d, a, b) \
    asm volatile("mma.sync.aligned.m16n8k16.row.col.f32.f16.f16.f32 " \
        "{%0,%1,%2,%3}, {%4,%5,%6,%7}, {%8,%9}, {%0,%1,%2,%3};" \
        : "+f"((d)[0]), "+f"((d)[1]), "+f"((d)[2]), "+f"((d)[3]) \
        : "r"((a)[0]), "r"((a)[1]), "r"((a)[2]), "r"((a)[3]), \
          "r"((b)[0]), "r"((b)[1]))

__device__ __forceinline__ uint32_t packh(float lo, float hi) {
    uint32_t r;
    asm("cvt.rn.f16x2.f32 %0, %1, %2;" : "=r"(r) : "f"(hi), "f"(lo));
    return r;
}

// ==================== fp16 GEMM via mma.sync (HMMA) =======================
// Fragment double-buffering: LDSMs for k-step kk+1 issue before MMAs of kk
// so the smem crossbar and tensor pipe run concurrently.
#define NCH 16              // 1024 / 64
#define STG48 49152         // A 16 KB + B 32 KB
#define SMEM_GEMM (3*STG48)

__device__ __forceinline__ void gemm_issue_stage(
    uint32_t s, int tid, int m0, int n0, int kc,
    const __half* __restrict__ A, const __half* __restrict__ B)
{
    const int g = tid & 7;
#pragma unroll
    for (int i = 0; i < 4; i++) {
        int row = (tid + i * 256) >> 3;
        uint32_t o = row * 128 + g * 16; o ^= (o >> 3) & 0x70;
        CP16(s + o, A + (size_t)(m0 + row) * DM + kc + g * 8);
    }
#pragma unroll
    for (int i = 0; i < 8; i++) {
        int row = (tid + i * 256) >> 3;
        uint32_t o = row * 128 + g * 16; o ^= (o >> 3) & 0x70;
        CP16(s + 16384 + o, B + (size_t)(n0 + row) * DM + kc + g * 8);
    }
}

__global__ __launch_bounds__(256, 1) void gemm_mma_kernel(
    const __half* __restrict__ A, const __half* __restrict__ B,
    float* __restrict__ Cf, __half* __restrict__ Ch0,
    __half* __restrict__ Ch1, __half* __restrict__ Ch2,
    int do_relu, float scale)
{
    extern __shared__ char smem[];
    const uint32_t sb = smem_u32(smem);
    const int tid = threadIdx.x;
    const int lane = tid & 31;
    const int wid = tid >> 5;
    const int wm = wid & 1;
    const int wn = wid >> 1;
    const int m0 = blockIdx.y * 128;
    const int n0 = blockIdx.x * 256;

    float acc[4][8][4];
#pragma unroll
    for (int mt = 0; mt < 4; mt++)
#pragma unroll
        for (int nt = 0; nt < 8; nt++)
#pragma unroll
            for (int r = 0; r < 4; r++) acc[mt][nt][r] = 0.f;

    const int a_row = lane & 15;
    const int a_kb  = (lane >> 4) << 4;
    const int b_row = ((lane >> 4) << 3) + (lane & 7);
    const int b_kb  = ((lane >> 3) & 1) << 4;

    gemm_issue_stage(sb, tid, m0, n0, 0, A, B);
    CP_COMMIT();
    gemm_issue_stage(sb + STG48, tid, m0, n0, 64, A, B);
    CP_COMMIT();

    uint32_t af[2][4][4], bfr[2][8][2];

    for (int c = 0; c < NCH; c++) {
        if (c + 1 < NCH) CP_WAIT1(); else CP_WAIT0();
        __syncthreads();

        const uint32_t sA = sb + (c % 3) * STG48;
        const uint32_t sB = sA + 16384;

        // lambda: load frags for one k-step into buffer bsel
        auto ldfrag = [&](int bsel, int kbyte) {
#pragma unroll
            for (int mt = 0; mt < 4; mt++) {
                uint32_t o = (uint32_t)(wm*64 + mt*16 + a_row) * 128 + kbyte + a_kb;
                o ^= (o >> 3) & 0x70;
                LDSM4(af[bsel][mt], sA + o);
            }
#pragma unroll
            for (int p = 0; p < 4; p++) {
                uint32_t rr[4];
                uint32_t o = (uint32_t)(wn*64 + p*16 + b_row) * 128 + kbyte + b_kb;
                o ^= (o >> 3) & 0x70;
                LDSM4(rr, sB + o);
                bfr[bsel][p*2][0]   = rr[0]; bfr[bsel][p*2][1]   = rr[1];
                bfr[bsel][p*2+1][0] = rr[2]; bfr[bsel][p*2+1][1] = rr[3];
            }
        };

        ldfrag(0, 0);
#pragma unroll
        for (int kk = 0; kk < 4; kk++) {
            if (kk < 3) ldfrag((kk + 1) & 1, (kk + 1) * 32);
            const int cur = kk & 1;
#pragma unroll
            for (int mt = 0; mt < 4; mt++)
#pragma unroll
                for (int nt = 0; nt < 8; nt++)
                    MMA16816(acc[mt][nt], af[cur][mt], bfr[cur][nt]);
        }

        if (c + 2 < NCH) {
            gemm_issue_stage(sb + ((c + 2) % 3) * STG48, tid, m0, n0,
                             (c + 2) * 64, A, B);
            CP_COMMIT();
        }
    }

    const int which = n0 >> 10;
    __half* Ch = (which == 0) ? Ch0 : ((which == 1) ? Ch1 : Ch2);
    const int ncol = n0 & 1023;
    const float sc = (which == 0) ? scale : 1.f;

#pragma unroll
    for (int mt = 0; mt < 4; mt++) {
        int r0 = m0 + wm*64 + mt*16 + (lane >> 2);
#pragma unroll
        for (int nt = 0; nt < 8; nt++) {
            int cc = ncol + wn*64 + nt*8 + (lane & 3)*2;
            float v[4];
#pragma unroll
            for (int r = 0; r < 4; r++) {
                v[r] = acc[mt][nt][r] * sc;
                if (do_relu) v[r] = fmaxf(v[r], 0.f);
            }
            if (Cf) {
                *(float2*)(Cf + (size_t)r0 * DM + cc)       = make_float2(v[0], v[1]);
                *(float2*)(Cf + (size_t)(r0 + 8) * DM + cc) = make_float2(v[2], v[3]);
            }
            if (Ch) {
                *(uint32_t*)(Ch + (size_t)r0 * DM + cc)     = packh(v[0], v[1]);
                *(uint32_t*)(Ch + (size_t)(r0+8) * DM + cc) = packh(v[2], v[3]);
            }
        }
    }
}

// ======================= fp32 -> fp16 (elementwise) =======================
__global__ __launch_bounds__(256) void cvt_kernel(
    const float4* __restrict__ X, uint32_t* __restrict__ H)
{
    int i = blockIdx.x * 256 + threadIdx.x;
    float4 v = X[i];
    H[i*2+0] = packh(v.x, v.y);
    H[i*2+1] = packh(v.z, v.w);
}

// ==== transpose + cvt, vectorized stores; all 6 weights in one launch =====
struct W6 { const float* p[6]; };

__global__ __launch_bounds__(256) void transpose_cvt_all_kernel(
    W6 ws, __half* __restrict__ T)
{
    __shared__ float t[64][33];
    const int wz = blockIdx.z;
    const float* W = ws.p[wz];
    __half* th = T + (size_t)wz * DM * DM;
    const int n0 = blockIdx.x * 32, k0 = blockIdx.y * 64;
    const int tx = threadIdx.x, ty = threadIdx.y;   // 32 x 8
#pragma unroll
    for (int r = 0; r < 8; r++)
        t[ty + r*8][tx] = W[(size_t)(k0 + ty + r*8) * DM + n0 + tx];
    __syncthreads();
    const int tid = ty * 32 + tx;
#pragma unroll
    for (int w = 0; w < 4; w++) {
        int idx = tid + w * 256;
        int nl = idx >> 5;
        int u  = idx & 31;
        uint32_t pk = packh(t[2*u][nl], t[2*u+1][nl]);
        *(uint32_t*)(th + (size_t)(n0 + nl) * DM + k0 + 2*u) = pk;
    }
}

// ================ tensor-core flash attention, fp16 =======================
// exp2-domain softmax, Q frags hoisted, paired LDSM4/LDSM4T, and fragment
// double-buffering: K frags prefetched one k-step ahead; V frags for j=0
// issued BEFORE softmax so the softmax chain overlaps V load latency.
#define AT_Q 0
#define AT_STG 16384
#define AT_STGSZ 16384      // K 8KB + V 8KB
#define SMEM_ATTN (16384 + 2*16384)   // 48 KB

__device__ __forceinline__ void attn_issue_kv(
    uint32_t s, int tid, size_t base, int kt,
    const __half* __restrict__ K, const __half* __restrict__ V)
{
#pragma unroll
    for (int i = 0; i < 2; i++) {
        int idx = tid + i * 256;
        int row = idx >> 3, c16 = idx & 7;
        uint32_t off = row * 128 + c16 * 16;
        off ^= (off >> 3) & 0x70;
        size_t g = base + (size_t)(kt * 64 + row) * DM + c16 * 8;
        CP16(s + off,        K + g);
        CP16(s + 8192 + off, V + g);
    }
}

__global__ __launch_bounds__(256, 2) void attn_mma_kernel(
    const __half* __restrict__ Q, const __half* __restrict__ K,
    const __half* __restrict__ V, __half* __restrict__ O)
{
    extern __shared__ char smem[];
    const uint32_t sb = smem_u32(smem);
    const int tid = threadIdx.x, lane = tid & 31, w = tid >> 5;
    const int q0 = blockIdx.x * 128;
    const int h = blockIdx.y, b = blockIdx.z;
    const size_t base = (size_t)b * SS * DM + h * DHD;

#pragma unroll
    for (int i = 0; i < 4; i++) {
        int idx = tid + i * 256;
        int row = idx >> 3, c16 = idx & 7;
        uint32_t off = row * 128 + c16 * 16;
        off ^= (off >> 3) & 0x70;
        CP16(sb + AT_Q + off, Q + base + (size_t)(q0 + row) * DM + c16 * 8);
    }
    CP_COMMIT();
    attn_issue_kv(sb + AT_STG, tid, base, 0, K, V);
    CP_COMMIT();

    const int arow = w * 16 + (lane & 15);
    const int akb  = (lane >> 4) << 4;
    const int kp_row = ((lane >> 4) << 3) + (lane & 7);
    const int kp_kb  = ((lane >> 3) & 1) << 4;
    const int vp_row = lane & 15;
    const int vp_nb  = (lane >> 4) << 4;

    CP_WAIT1();
    __syncthreads();
    uint32_t aqr[4][4];
#pragma unroll
    for (int ks = 0; ks < 4; ks++) {
        uint32_t o = (uint32_t)arow * 128 + ks * 32 + akb;
        o ^= (o >> 3) & 0x70;
        LDSM4(aqr[ks], sb + AT_Q + o);
    }

    float acco[8][4];
#pragma unroll
    for (int nt = 0; nt < 8; nt++)
#pragma unroll
        for (int r = 0; r < 4; r++) acco[nt][r] = 0.f;
    float runm0 = -1e30f, runm1 = -1e30f, runs0 = 0.f, runs1 = 0.f;

    uint32_t kf[2][4][4];
    uint32_t vf[2][4][4];

    for (int kt = 0; kt < SS / 64; kt++) {
        if (kt + 1 < SS / 64) {
            attn_issue_kv(sb + AT_STG + ((kt + 1) & 1) * AT_STGSZ, tid, base,
                          kt + 1, K, V);
            CP_COMMIT();
            CP_WAIT1();
        } else {
            CP_WAIT0();
        }
        __syncthreads();

        const uint32_t sK = sb + AT_STG + (kt & 1) * AT_STGSZ;
        const uint32_t sV = sK + 8192;

        auto ldk = [&](int bsel, int ks) {
#pragma unroll
            for (int p = 0; p < 4; p++) {
                uint32_t bo = (uint32_t)(p * 16 + kp_row) * 128 + ks * 32 + kp_kb;
                bo ^= (bo >> 3) & 0x70;
                LDSM4(kf[bsel][p], sK + bo);
            }
        };
        auto ldv = [&](int bsel, int j) {
#pragma unroll
            for (int np = 0; np < 4; np++) {
                uint32_t vo = (uint32_t)(j * 16 + vp_row) * 128 + np * 32 + vp_nb;
                vo ^= (vo >> 3) & 0x70;
                LDSM4T(vf[bsel][np], sV + vo);
            }
        };

        // ---- QK^T with K-frag double-buffering ----
        float accs[8][4];
#pragma unroll
        for (int nt = 0; nt < 8; nt++)
#pragma unroll
            for (int r = 0; r < 4; r++) accs[nt][r] = 0.f;

        ldk(0, 0);
#pragma unroll
        for (int ks = 0; ks < 4; ks++) {
            if (ks < 3) ldk((ks + 1) & 1, ks + 1);
            const int cur = ks & 1;
#pragma unroll
            for (int p = 0; p < 4; p++) {
                MMA16816(accs[p*2],   aqr[ks], (kf[cur][p]));
                MMA16816(accs[p*2+1], aqr[ks], (kf[cur][p] + 2));
            }
        }

        // prefetch V for j=0 — overlaps softmax below
        ldv(0, 0);

        // ---- online softmax (base 2) ----
        float mx0 = -1e30f, mx1 = -1e30f;
#pragma unroll
        for (int nt = 0; nt < 8; nt++) {
            mx0 = fmaxf(mx0, fmaxf(accs[nt][0], accs[nt][1]));
            mx1 = fmaxf(mx1, fmaxf(accs[nt][2], accs[nt][3]));
        }
        mx0 = fmaxf(mx0, __shfl_xor_sync(0xffffffffu, mx0, 1));
        mx0 = fmaxf(mx0, __shfl_xor_sync(0xffffffffu, mx0, 2));
        mx1 = fmaxf(mx1, __shfl_xor_sync(0xffffffffu, mx1, 1));
        mx1 = fmaxf(mx1, __shfl_xor_sync(0xffffffffu, mx1, 2));

        if (mx0 > runm0 || mx1 > runm1) {
            float nm0 = fmaxf(runm0, mx0), nm1 = fmaxf(runm1, mx1);
            float c0 = exp2f(runm0 - nm0), c1 = exp2f(runm1 - nm1);
            runm0 = nm0; runm1 = nm1;
            runs0 *= c0; runs1 *= c1;
#pragma unroll
            for (int nt = 0; nt < 8; nt++) {
                acco[nt][0] *= c0; acco[nt][1] *= c0;
                acco[nt][2] *= c1; acco[nt][3] *= c1;
            }
        }

        float s0 = 0.f, s1 = 0.f;
#pragma unroll
        for (int nt = 0; nt < 8; nt++) {
            accs[nt][0] = exp2f(accs[nt][0] - runm0); s0 += accs[nt][0];
            accs[nt][1] = exp2f(accs[nt][1] - runm0); s0 += accs[nt][1];
            accs[nt][2] = exp2f(accs[nt][2] - runm1); s1 += accs[nt][2];
            accs[nt][3] = exp2f(accs[nt][3] - runm1); s1 += accs[nt][3];
        }
        s0 += __shfl_xor_sync(0xffffffffu, s0, 1);
        s0 += __shfl_xor_sync(0xffffffffu, s0, 2);
        s1 += __shfl_xor_sync(0xffffffffu, s1, 1);
        s1 += __shfl_xor_sync(0xffffffffu, s1, 2);
        runs0 += s0;
        runs1 += s1;

        // ---- P @ V with V-frag double-buffering ----
#pragma unroll
        for (int j = 0; j < 4; j++) {
            if (j < 3) ldv((j + 1) & 1, j + 1);
            const int cur = j & 1;
            float* pa = accs[2*j];
            float* pb = accs[2*j + 1];
            uint32_t ap[4];
            ap[0] = packh(pa[0], pa[1]);
            ap[1] = packh(pa[2], pa[3]);
            ap[2] = packh(pb[0], pb[1]);
            ap[3] = packh(pb[2], pb[3]);
#pragma unroll
            for (int np = 0; np < 4; np++) {
                MMA16816(acco[np*2],   ap, (vf[cur][np]));
                MMA16816(acco[np*2+1], ap, (vf[cur][np] + 2));
            }
        }
        __syncthreads();
    }

    const float i0 = 1.f / runs0, i1 = 1.f / runs1;
    const size_t r0 = (size_t)(b * SS + q0 + w * 16 + (lane >> 2));
#pragma unroll
    for (int nt = 0; nt < 8; nt++) {
        int cc = h * DHD + nt * 8 + (lane & 3) * 2;
        *(uint32_t*)(O + r0 * DM + cc)     = packh(acco[nt][0]*i0, acco[nt][1]*i0);
        *(uint32_t*)(O + (r0+8) * DM + cc) = packh(acco[nt][2]*i1, acco[nt][3]*i1);
    }
}

// ======================= residual-add + LayerNorm =========================
__device__ __forceinline__ float block_sum256(float v, float* red) {
#pragma unroll
    for (int o = 16; o; o >>= 1) v += __shfl_xor_sync(0xffffffffu, v, o);
    int lane = threadIdx.x & 31, wid = threadIdx.x >> 5;
    if (lane == 0) red[wid] = v;
    __syncthreads();
    if (threadIdx.x < 32) {
        float t = (threadIdx.x < 8) ? red[threadIdx.x] : 0.f;
#pragma unroll
        for (int o = 4; o; o >>= 1) t += __shfl_xor_sync(0xffffffffu, t, o);
        if (threadIdx.x == 0) red[0] = t;
    }
    __syncthreads();
    float r = red[0];
    __syncthreads();
    return r;
}

__global__ __launch_bounds__(256) void ln_kernel(
    const float* __restrict__ x, const float* __restrict__ res,
    const float* __restrict__ gamma, const float* __restrict__ beta,
    float* __restrict__ out, __half* __restrict__ oh)
{
    __shared__ float red[8];
    const int row = blockIdx.x;
    const int tid = threadIdx.x;

    float4 v = ((const float4*)(x + (size_t)row * DM))[tid];
    float4 r = ((const float4*)(res + (size_t)row * DM))[tid];
    v.x += r.x; v.y += r.y; v.z += r.z; v.w += r.w;

    float s = v.x + v.y + v.z + v.w;
    float tot = block_sum256(s, red);
    float mean = tot * (1.f / DM);

    float dx = v.x - mean, dy = v.y - mean, dz = v.z - mean, dw = v.w - mean;
    float sq = dx*dx + dy*dy + dz*dz + dw*dw;
    float totsq = block_sum256(sq, red);
    float rstd = rsqrtf(totsq * (1.f / DM) + LN_EPS);

    float4 g = ((const float4*)gamma)[tid];
    float4 bb = ((const float4*)beta)[tid];
    float4 o;
    o.x = dx * rstd * g.x + bb.x;
    o.y = dy * rstd * g.y + bb.y;
    o.z = dz * rstd * g.z + bb.z;
    o.w = dw * rstd * g.w + bb.w;
    if (out) ((float4*)(out + (size_t)row * DM))[tid] = o;
    if (oh) {
        uint32_t* hp = (uint32_t*)(oh + (size_t)row * DM) + tid*2;
        hp[0] = packh(o.x, o.y);
        hp[1] = packh(o.z, o.w);
    }
}

// ================================ driver ==================================
extern "C" void kernel_launch(void* const* d_in, const int* in_sizes, int n_in,
                              void* d_out, int out_size)
{
    const float* query = (const float*)d_in[0];
    const float* gamma = (const float*)d_in[7];
    const float* beta  = (const float*)d_in[8];

    float *b0, *b1;
    __half *ah, *bh, *qh, *kh, *vh, *wt;
    cudaGetSymbolAddress((void**)&b0, g_buf0);
    cudaGetSymbolAddress((void**)&b1, g_buf1);
    cudaGetSymbolAddress((void**)&ah, g_a);
    cudaGetSymbolAddress((void**)&bh, g_b);
    cudaGetSymbolAddress((void**)&qh, g_q);
    cudaGetSymbolAddress((void**)&kh, g_k);
    cudaGetSymbolAddress((void**)&vh, g_v);
    cudaGetSymbolAddress((void**)&wt, g_wt);

    cudaFuncSetAttribute(gemm_mma_kernel,
                         cudaFuncAttributeMaxDynamicSharedMemorySize, SMEM_GEMM);
    cudaFuncSetAttribute(attn_mma_kernel,
                         cudaFuncAttributeMaxDynamicSharedMemorySize, SMEM_ATTN);

    const dim3 ggrid(DM / 256, MROWS / 128);          // (4, 32)
    const dim3 ggrid_qkv(3 * DM / 256, MROWS / 128);  // (12, 32)
    const int cvt_blocks = (MROWS * DM / 4) / 256;
    const float QSCALE = 0.125f * 1.44269504088896f;  // fold log2(e) for exp2

    W6 ws;
    for (int i = 0; i < 6; i++) ws.p[i] = (const float*)d_in[1 + i];
    transpose_cvt_all_kernel<<<dim3(DM/32, DM/64, 6), dim3(32, 8)>>>(ws, wt);

    cvt_kernel<<<cvt_blocks, 256>>>((const float4*)query, (uint32_t*)ah);

    // merged QKV projection (N = 3072; Q pre-scaled into exp2 domain)
    gemm_mma_kernel<<<ggrid_qkv, 256, SMEM_GEMM>>>(
        ah, wt, nullptr, qh, kh, vh, 0, QSCALE);

    // attention -> ctx fp16 in ah
    attn_mma_kernel<<<dim3(SS/128, HH, BB), 256, SMEM_ATTN>>>(qh, kh, vh, ah);

    // ctx @ W1 -> fp32 b0 ; LN(b0 + query) -> fp32 b1 + fp16 ah
    gemm_mma_kernel<<<ggrid, 256, SMEM_GEMM>>>(
        ah, wt + 3*(size_t)DM*DM, b0, nullptr, nullptr, nullptr, 0, 1.f);
    ln_kernel<<<MROWS, 256>>>(b0, query, gamma, beta, b1, ah);

    // relu(residual @ W2) -> fp16 bh ; bh @ W3 -> fp32 b0 ; LN -> out
    gemm_mma_kernel<<<ggrid, 256, SMEM_GEMM>>>(
        ah, wt + 4*(size_t)DM*DM, nullptr, bh, bh, bh, 1, 1.f);
    gemm_mma_kernel<<<ggrid, 256, SMEM_GEMM>>>(
        bh, wt + 5*(size_t)DM*DM, b0, nullptr, nullptr, nullptr, 0, 1.f);
    ln_kernel<<<MROWS, 256>>>(b0, b1, gamma, beta, (float*)d_out, nullptr);
}

// round 13
// speedup vs baseline: 6.9896x; 1.0183x over previous
#include <cuda_runtime.h>
#include <cuda_fp16.h>
#include <cstdint>
#include <math.h>

#define SS 2048
#define DM 1024
#define HH 16
#define DHD 64
#define BB 2
#define MROWS (BB*SS)   // 4096
#define LN_EPS 1e-3f

// ---------------- scratch buffers (no allocation allowed) ----------------
__device__ float g_buf0[MROWS*DM];
__device__ float g_buf1[MROWS*DM];
__device__ __half g_a[MROWS*DM];
__device__ __half g_b[MROWS*DM];
__device__ __half g_q[MROWS*DM];
__device__ __half g_k[MROWS*DM];
__device__ __half g_v[MROWS*DM];
__device__ __half g_wt[6*DM*DM];   // transposed fp16 weights, [N,K] stacked

// ========================= PTX helpers (portable) =========================
__device__ __forceinline__ uint32_t smem_u32(const void* p) {
    uint32_t a;
    asm("{ .reg .u64 t; cvta.to.shared.u64 t, %1; cvt.u32.u64 %0, t; }"
        : "=r"(a) : "l"(p));
    return a;
}
#define CP16(dst, src) \
    asm volatile("cp.async.cg.shared.global [%0], [%1], 16;" \
                 :: "r"(dst), "l"(src) : "memory")
#define CP_COMMIT()  asm volatile("cp.async.commit_group;" ::: "memory")
#define CP_WAIT2()   asm volatile("cp.async.wait_group 2;" ::: "memory")
#define CP_WAIT1()   asm volatile("cp.async.wait_group 1;" ::: "memory")
#define CP_WAIT0()   asm volatile("cp.async.wait_group 0;" ::: "memory")

#define LDSM4(r, addr) \
    asm volatile("ldmatrix.sync.aligned.m8n8.x4.shared.b16 {%0,%1,%2,%3}, [%4];" \
        : "=r"((r)[0]), "=r"((r)[1]), "=r"((r)[2]), "=r"((r)[3]) : "r"(addr))
#define LDSM4T(r, addr) \
    asm volatile("ldmatrix.sync.aligned.m8n8.x4.trans.shared.b16 {%0,%1,%2,%3}, [%4];" \
        : "=r"((r)[0]), "=r"((r)[1]), "=r"((r)[2]), "=r"((r)[3]) : "r"(addr))
#define MMA16816(d, a, b) \
    asm volatile("mma.sync.aligned.m16n8k16.row.col.f32.f16.f16.f32 " \
        "{%0,%1,%2,%3}, {%4,%5,%6,%7}, {%8,%9}, {%0,%1,%2,%3};" \
        : "+f"((d)[0]), "+f"((d)[1]), "+f"((d)[2]), "+f"((d)[3]) \
        : "r"((a)[0]), "r"((a)[1]), "r"((a)[2]), "r"((a)[3]), \
          "r"((b)[0]), "r"((b)[1]))

__device__ __forceinline__ uint32_t packh(float lo, float hi) {
    uint32_t r;
    asm("cvt.rn.f16x2.f32 %0, %1, %2;" : "=r"(r) : "f"(hi), "f"(lo));
    return r;
}

// ==================== fp16 GEMM via mma.sync (HMMA) =======================
// Round-10 proven mainloop. C = A @ W; A fp16 [M,K] rm; B[n,k]=W[k,n] fp16
// [N,K] rm (pre-transposed, 3 QKV weights stacked for merged launch).
// CTA 128x256, 256 threads (8 warps, 2Mx4N), warp tile 64x64, K-chunk 64,
// 3-stage cp.async. Epilogue selects Ch0/1/2 by n-block.
#define NCH 16              // 1024 / 64
#define STG48 49152         // A 16 KB + B 32 KB
#define SMEM_GEMM (3*STG48)

__device__ __forceinline__ void gemm_issue_stage(
    uint32_t s, int tid, int m0, int n0, int kc,
    const __half* __restrict__ A, const __half* __restrict__ B)
{
    const int g = tid & 7;
#pragma unroll
    for (int i = 0; i < 4; i++) {
        int row = (tid + i * 256) >> 3;
        uint32_t o = row * 128 + g * 16; o ^= (o >> 3) & 0x70;
        CP16(s + o, A + (size_t)(m0 + row) * DM + kc + g * 8);
    }
#pragma unroll
    for (int i = 0; i < 8; i++) {
        int row = (tid + i * 256) >> 3;
        uint32_t o = row * 128 + g * 16; o ^= (o >> 3) & 0x70;
        CP16(s + 16384 + o, B + (size_t)(n0 + row) * DM + kc + g * 8);
    }
}

__global__ __launch_bounds__(256, 1) void gemm_mma_kernel(
    const __half* __restrict__ A, const __half* __restrict__ B,
    float* __restrict__ Cf, __half* __restrict__ Ch0,
    __half* __restrict__ Ch1, __half* __restrict__ Ch2,
    int do_relu, float scale)
{
    extern __shared__ char smem[];
    const uint32_t sb = smem_u32(smem);
    const int tid = threadIdx.x;
    const int lane = tid & 31;
    const int wid = tid >> 5;
    const int wm = wid & 1;
    const int wn = wid >> 1;
    const int m0 = blockIdx.y * 128;
    const int n0 = blockIdx.x * 256;

    float acc[4][8][4];
#pragma unroll
    for (int mt = 0; mt < 4; mt++)
#pragma unroll
        for (int nt = 0; nt < 8; nt++)
#pragma unroll
            for (int r = 0; r < 4; r++) acc[mt][nt][r] = 0.f;

    const int a_row = lane & 15;
    const int a_kb  = (lane >> 4) << 4;
    const int b_row = ((lane >> 4) << 3) + (lane & 7);
    const int b_kb  = ((lane >> 3) & 1) << 4;

    gemm_issue_stage(sb, tid, m0, n0, 0, A, B);
    CP_COMMIT();
    gemm_issue_stage(sb + STG48, tid, m0, n0, 64, A, B);
    CP_COMMIT();

    for (int c = 0; c < NCH; c++) {
        if (c + 1 < NCH) CP_WAIT1(); else CP_WAIT0();
        __syncthreads();

        const uint32_t sA = sb + (c % 3) * STG48;
        const uint32_t sB = sA + 16384;

#pragma unroll
        for (int kk = 0; kk < 4; kk++) {
            const int kbyte = kk * 32;
            uint32_t af[4][4], bfr[8][2];

#pragma unroll
            for (int mt = 0; mt < 4; mt++) {
                uint32_t o = (uint32_t)(wm*64 + mt*16 + a_row) * 128 + kbyte + a_kb;
                o ^= (o >> 3) & 0x70;
                LDSM4(af[mt], sA + o);
            }
#pragma unroll
            for (int p = 0; p < 4; p++) {
                uint32_t rr[4];
                uint32_t o = (uint32_t)(wn*64 + p*16 + b_row) * 128 + kbyte + b_kb;
                o ^= (o >> 3) & 0x70;
                LDSM4(rr, sB + o);
                bfr[p*2][0]   = rr[0]; bfr[p*2][1]   = rr[1];
                bfr[p*2+1][0] = rr[2]; bfr[p*2+1][1] = rr[3];
            }
#pragma unroll
            for (int mt = 0; mt < 4; mt++)
#pragma unroll
                for (int nt = 0; nt < 8; nt++)
                    MMA16816(acc[mt][nt], af[mt], bfr[nt]);
        }

        if (c + 2 < NCH) {
            gemm_issue_stage(sb + ((c + 2) % 3) * STG48, tid, m0, n0,
                             (c + 2) * 64, A, B);
            CP_COMMIT();
        }
    }

    const int which = n0 >> 10;
    __half* Ch = (which == 0) ? Ch0 : ((which == 1) ? Ch1 : Ch2);
    const int ncol = n0 & 1023;
    const float sc = (which == 0) ? scale : 1.f;

#pragma unroll
    for (int mt = 0; mt < 4; mt++) {
        int r0 = m0 + wm*64 + mt*16 + (lane >> 2);
#pragma unroll
        for (int nt = 0; nt < 8; nt++) {
            int cc = ncol + wn*64 + nt*8 + (lane & 3)*2;
            float v[4];
#pragma unroll
            for (int r = 0; r < 4; r++) {
                v[r] = acc[mt][nt][r] * sc;
                if (do_relu) v[r] = fmaxf(v[r], 0.f);
            }
            if (Cf) {
                *(float2*)(Cf + (size_t)r0 * DM + cc)       = make_float2(v[0], v[1]);
                *(float2*)(Cf + (size_t)(r0 + 8) * DM + cc) = make_float2(v[2], v[3]);
            }
            if (Ch) {
                *(uint32_t*)(Ch + (size_t)r0 * DM + cc)     = packh(v[0], v[1]);
                *(uint32_t*)(Ch + (size_t)(r0+8) * DM + cc) = packh(v[2], v[3]);
            }
        }
    }
}

// ======================= fp32 -> fp16 (elementwise) =======================
__global__ __launch_bounds__(256) void cvt_kernel(
    const float4* __restrict__ X, uint32_t* __restrict__ H)
{
    int i = blockIdx.x * 256 + threadIdx.x;
    float4 v = X[i];
    H[i*2+0] = packh(v.x, v.y);
    H[i*2+1] = packh(v.z, v.w);
}

// ==== transpose + cvt, vectorized stores; all 6 weights in one launch =====
struct W6 { const float* p[6]; };

__global__ __launch_bounds__(256) void transpose_cvt_all_kernel(
    W6 ws, __half* __restrict__ T)
{
    __shared__ float t[64][33];
    const int wz = blockIdx.z;
    const float* W = ws.p[wz];
    __half* th = T + (size_t)wz * DM * DM;
    const int n0 = blockIdx.x * 32, k0 = blockIdx.y * 64;
    const int tx = threadIdx.x, ty = threadIdx.y;   // 32 x 8
#pragma unroll
    for (int r = 0; r < 8; r++)
        t[ty + r*8][tx] = W[(size_t)(k0 + ty + r*8) * DM + n0 + tx];
    __syncthreads();
    const int tid = ty * 32 + tx;
#pragma unroll
    for (int w = 0; w < 4; w++) {
        int idx = tid + w * 256;
        int nl = idx >> 5;
        int u  = idx & 31;
        uint32_t pk = packh(t[2*u][nl], t[2*u+1][nl]);
        *(uint32_t*)(th + (size_t)(n0 + nl) * DM + k0 + 2*u) = pk;
    }
}

// ================ tensor-core flash attention, fp16 =======================
// exp2-domain softmax, Q frags hoisted, paired LDSM4/LDSM4T, K/V fragment
// double-buffering, V j=0 prefetch overlapping softmax, 3-stage cp.async KV
// pipeline (race-free: issue after sync, buffer reused 2 syncs later).
#define AT_Q 0
#define AT_STG 16384
#define AT_STGSZ 16384      // K 8KB + V 8KB
#define SMEM_ATTN (16384 + 3*16384)   // 64 KB
#define NKT (SS/64)

__device__ __forceinline__ void attn_issue_kv(
    uint32_t s, int tid, size_t base, int kt,
    const __half* __restrict__ K, const __half* __restrict__ V)
{
#pragma unroll
    for (int i = 0; i < 2; i++) {
        int idx = tid + i * 256;
        int row = idx >> 3, c16 = idx & 7;
        uint32_t off = row * 128 + c16 * 16;
        off ^= (off >> 3) & 0x70;
        size_t g = base + (size_t)(kt * 64 + row) * DM + c16 * 8;
        CP16(s + off,        K + g);
        CP16(s + 8192 + off, V + g);
    }
}

__global__ __launch_bounds__(256, 2) void attn_mma_kernel(
    const __half* __restrict__ Q, const __half* __restrict__ K,
    const __half* __restrict__ V, __half* __restrict__ O)
{
    extern __shared__ char smem[];
    const uint32_t sb = smem_u32(smem);
    const int tid = threadIdx.x, lane = tid & 31, w = tid >> 5;
    const int q0 = blockIdx.x * 128;
    const int h = blockIdx.y, b = blockIdx.z;
    const size_t base = (size_t)b * SS * DM + h * DHD;

#pragma unroll
    for (int i = 0; i < 4; i++) {
        int idx = tid + i * 256;
        int row = idx >> 3, c16 = idx & 7;
        uint32_t off = row * 128 + c16 * 16;
        off ^= (off >> 3) & 0x70;
        CP16(sb + AT_Q + off, Q + base + (size_t)(q0 + row) * DM + c16 * 8);
    }
    CP_COMMIT();
    attn_issue_kv(sb + AT_STG + 0 * AT_STGSZ, tid, base, 0, K, V);
    CP_COMMIT();
    attn_issue_kv(sb + AT_STG + 1 * AT_STGSZ, tid, base, 1, K, V);
    CP_COMMIT();

    const int arow = w * 16 + (lane & 15);
    const int akb  = (lane >> 4) << 4;
    const int kp_row = ((lane >> 4) << 3) + (lane & 7);
    const int kp_kb  = ((lane >> 3) & 1) << 4;
    const int vp_row = lane & 15;
    const int vp_nb  = (lane >> 4) << 4;

    CP_WAIT2();
    __syncthreads();
    uint32_t aqr[4][4];
#pragma unroll
    for (int ks = 0; ks < 4; ks++) {
        uint32_t o = (uint32_t)arow * 128 + ks * 32 + akb;
        o ^= (o >> 3) & 0x70;
        LDSM4(aqr[ks], sb + AT_Q + o);
    }

    float acco[8][4];
#pragma unroll
    for (int nt = 0; nt < 8; nt++)
#pragma unroll
        for (int r = 0; r < 4; r++) acco[nt][r] = 0.f;
    float runm0 = -1e30f, runm1 = -1e30f, runs0 = 0.f, runs1 = 0.f;

    uint32_t kf[2][4][4];
    uint32_t vf[2][4][4];

    for (int kt = 0; kt < NKT; kt++) {
        if (kt + 1 < NKT) CP_WAIT1(); else CP_WAIT0();
        __syncthreads();
        if (kt + 2 < NKT) {
            attn_issue_kv(sb + AT_STG + ((kt + 2) % 3) * AT_STGSZ, tid, base,
                          kt + 2, K, V);
            CP_COMMIT();
        }

        const uint32_t sK = sb + AT_STG + (kt % 3) * AT_STGSZ;
        const uint32_t sV = sK + 8192;

        auto ldk = [&](int bsel, int ks) {
#pragma unroll
            for (int p = 0; p < 4; p++) {
                uint32_t bo = (uint32_t)(p * 16 + kp_row) * 128 + ks * 32 + kp_kb;
                bo ^= (bo >> 3) & 0x70;
                LDSM4(kf[bsel][p], sK + bo);
            }
        };
        auto ldv = [&](int bsel, int j) {
#pragma unroll
            for (int np = 0; np < 4; np++) {
                uint32_t vo = (uint32_t)(j * 16 + vp_row) * 128 + np * 32 + vp_nb;
                vo ^= (vo >> 3) & 0x70;
                LDSM4T(vf[bsel][np], sV + vo);
            }
        };

        float accs[8][4];
#pragma unroll
        for (int nt = 0; nt < 8; nt++)
#pragma unroll
            for (int r = 0; r < 4; r++) accs[nt][r] = 0.f;

        ldk(0, 0);
#pragma unroll
        for (int ks = 0; ks < 4; ks++) {
            if (ks < 3) ldk((ks + 1) & 1, ks + 1);
            const int cur = ks & 1;
#pragma unroll
            for (int p = 0; p < 4; p++) {
                MMA16816(accs[p*2],   aqr[ks], (kf[cur][p]));
                MMA16816(accs[p*2+1], aqr[ks], (kf[cur][p] + 2));
            }
        }

        ldv(0, 0);   // overlaps softmax below

        float mx0 = -1e30f, mx1 = -1e30f;
#pragma unroll
        for (int nt = 0; nt < 8; nt++) {
            mx0 = fmaxf(mx0, fmaxf(accs[nt][0], accs[nt][1]));
            mx1 = fmaxf(mx1, fmaxf(accs[nt][2], accs[nt][3]));
        }
        mx0 = fmaxf(mx0, __shfl_xor_sync(0xffffffffu, mx0, 1));
        mx0 = fmaxf(mx0, __shfl_xor_sync(0xffffffffu, mx0, 2));
        mx1 = fmaxf(mx1, __shfl_xor_sync(0xffffffffu, mx1, 1));
        mx1 = fmaxf(mx1, __shfl_xor_sync(0xffffffffu, mx1, 2));

        if (mx0 > runm0 || mx1 > runm1) {
            float nm0 = fmaxf(runm0, mx0), nm1 = fmaxf(runm1, mx1);
            float c0 = exp2f(runm0 - nm0), c1 = exp2f(runm1 - nm1);
            runm0 = nm0; runm1 = nm1;
            runs0 *= c0; runs1 *= c1;
#pragma unroll
            for (int nt = 0; nt < 8; nt++) {
                acco[nt][0] *= c0; acco[nt][1] *= c0;
                acco[nt][2] *= c1; acco[nt][3] *= c1;
            }
        }

        float s0 = 0.f, s1 = 0.f;
#pragma unroll
        for (int nt = 0; nt < 8; nt++) {
            accs[nt][0] = exp2f(accs[nt][0] - runm0); s0 += accs[nt][0];
            accs[nt][1] = exp2f(accs[nt][1] - runm0); s0 += accs[nt][1];
            accs[nt][2] = exp2f(accs[nt][2] - runm1); s1 += accs[nt][2];
            accs[nt][3] = exp2f(accs[nt][3] - runm1); s1 += accs[nt][3];
        }
        s0 += __shfl_xor_sync(0xffffffffu, s0, 1);
        s0 += __shfl_xor_sync(0xffffffffu, s0, 2);
        s1 += __shfl_xor_sync(0xffffffffu, s1, 1);
        s1 += __shfl_xor_sync(0xffffffffu, s1, 2);
        runs0 += s0;
        runs1 += s1;

#pragma unroll
        for (int j = 0; j < 4; j++) {
            if (j < 3) ldv((j + 1) & 1, j + 1);
            const int cur = j & 1;
            float* pa = accs[2*j];
            float* pb = accs[2*j + 1];
            uint32_t ap[4];
            ap[0] = packh(pa[0], pa[1]);
            ap[1] = packh(pa[2], pa[3]);
            ap[2] = packh(pb[0], pb[1]);
            ap[3] = packh(pb[2], pb[3]);
#pragma unroll
            for (int np = 0; np < 4; np++) {
                MMA16816(acco[np*2],   ap, (vf[cur][np]));
                MMA16816(acco[np*2+1], ap, (vf[cur][np] + 2));
            }
        }
    }

    const float i0 = 1.f / runs0, i1 = 1.f / runs1;
    const size_t r0 = (size_t)(b * SS + q0 + w * 16 + (lane >> 2));
#pragma unroll
    for (int nt = 0; nt < 8; nt++) {
        int cc = h * DHD + nt * 8 + (lane & 3) * 2;
        *(uint32_t*)(O + r0 * DM + cc)     = packh(acco[nt][0]*i0, acco[nt][1]*i0);
        *(uint32_t*)(O + (r0+8) * DM + cc) = packh(acco[nt][2]*i1, acco[nt][3]*i1);
    }
}

// ======================= residual-add + LayerNorm =========================
__device__ __forceinline__ float block_sum256(float v, float* red) {
#pragma unroll
    for (int o = 16; o; o >>= 1) v += __shfl_xor_sync(0xffffffffu, v, o);
    int lane = threadIdx.x & 31, wid = threadIdx.x >> 5;
    if (lane == 0) red[wid] = v;
    __syncthreads();
    if (threadIdx.x < 32) {
        float t = (threadIdx.x < 8) ? red[threadIdx.x] : 0.f;
#pragma unroll
        for (int o = 4; o; o >>= 1) t += __shfl_xor_sync(0xffffffffu, t, o);
        if (threadIdx.x == 0) red[0] = t;
    }
    __syncthreads();
    float r = red[0];
    __syncthreads();
    return r;
}

__global__ __launch_bounds__(256) void ln_kernel(
    const float* __restrict__ x, const float* __restrict__ res,
    const float* __restrict__ gamma, const float* __restrict__ beta,
    float* __restrict__ out, __half* __restrict__ oh)
{
    __shared__ float red[8];
    const int row = blockIdx.x;
    const int tid = threadIdx.x;

    float4 v = ((const float4*)(x + (size_t)row * DM))[tid];
    float4 r = ((const float4*)(res + (size_t)row * DM))[tid];
    v.x += r.x; v.y += r.y; v.z += r.z; v.w += r.w;

    float s = v.x + v.y + v.z + v.w;
    float tot = block_sum256(s, red);
    float mean = tot * (1.f / DM);

    float dx = v.x - mean, dy = v.y - mean, dz = v.z - mean, dw = v.w - mean;
    float sq = dx*dx + dy*dy + dz*dz + dw*dw;
    float totsq = block_sum256(sq, red);
    float rstd = rsqrtf(totsq * (1.f / DM) + LN_EPS);

    float4 g = ((const float4*)gamma)[tid];
    float4 bb = ((const float4*)beta)[tid];
    float4 o;
    o.x = dx * rstd * g.x + bb.x;
    o.y = dy * rstd * g.y + bb.y;
    o.z = dz * rstd * g.z + bb.z;
    o.w = dw * rstd * g.w + bb.w;
    if (out) ((float4*)(out + (size_t)row * DM))[tid] = o;
    if (oh) {
        uint32_t* hp = (uint32_t*)(oh + (size_t)row * DM) + tid*2;
        hp[0] = packh(o.x, o.y);
        hp[1] = packh(o.z, o.w);
    }
}

// ================================ driver ==================================
extern "C" void kernel_launch(void* const* d_in, const int* in_sizes, int n_in,
                              void* d_out, int out_size)
{
    const float* query = (const float*)d_in[0];
    const float* gamma = (const float*)d_in[7];
    const float* beta  = (const float*)d_in[8];

    float *b0, *b1;
    __half *ah, *bh, *qh, *kh, *vh, *wt;
    cudaGetSymbolAddress((void**)&b0, g_buf0);
    cudaGetSymbolAddress((void**)&b1, g_buf1);
    cudaGetSymbolAddress((void**)&ah, g_a);
    cudaGetSymbolAddress((void**)&bh, g_b);
    cudaGetSymbolAddress((void**)&qh, g_q);
    cudaGetSymbolAddress((void**)&kh, g_k);
    cudaGetSymbolAddress((void**)&vh, g_v);
    cudaGetSymbolAddress((void**)&wt, g_wt);

    cudaFuncSetAttribute(gemm_mma_kernel,
                         cudaFuncAttributeMaxDynamicSharedMemorySize, SMEM_GEMM);
    cudaFuncSetAttribute(attn_mma_kernel,
                         cudaFuncAttributeMaxDynamicSharedMemorySize, SMEM_ATTN);

    const dim3 ggrid(DM / 256, MROWS / 128);          // (4, 32)
    const dim3 ggrid_qkv(3 * DM / 256, MROWS / 128);  // (12, 32)
    const int cvt_blocks = (MROWS * DM / 4) / 256;
    const float QSCALE = 0.125f * 1.44269504088896f;  // fold log2(e) for exp2

    // weight transform: transpose + cvt, all 6 in one launch
    W6 ws;
    for (int i = 0; i < 6; i++) ws.p[i] = (const float*)d_in[1 + i];
    transpose_cvt_all_kernel<<<dim3(DM/32, DM/64, 6), dim3(32, 8)>>>(ws, wt);

    // query -> fp16
    cvt_kernel<<<cvt_blocks, 256>>>((const float4*)query, (uint32_t*)ah);

    // merged QKV projection (N = 3072; Q pre-scaled into exp2 domain)
    gemm_mma_kernel<<<ggrid_qkv, 256, SMEM_GEMM>>>(
        ah, wt, nullptr, qh, kh, vh, 0, QSCALE);

    // attention -> ctx fp16 in ah
    attn_mma_kernel<<<dim3(SS/128, HH, BB), 256, SMEM_ATTN>>>(qh, kh, vh, ah);

    // ctx @ W1 -> fp32 b0 ; LN(b0 + query) -> fp32 b1 + fp16 ah
    gemm_mma_kernel<<<ggrid, 256, SMEM_GEMM>>>(
        ah, wt + 3*(size_t)DM*DM, b0, nullptr, nullptr, nullptr, 0, 1.f);
    ln_kernel<<<MROWS, 256>>>(b0, query, gamma, beta, b1, ah);

    // relu(residual @ W2) -> fp16 bh ; bh @ W3 -> fp32 b0 ; LN -> out
    gemm_mma_kernel<<<ggrid, 256, SMEM_GEMM>>>(
        ah, wt + 4*(size_t)DM*DM, nullptr, bh, bh, bh, 1, 1.f);
    gemm_mma_kernel<<<ggrid, 256, SMEM_GEMM>>>(
        bh, wt + 5*(size_t)DM*DM, b0, nullptr, nullptr, nullptr, 0, 1.f);
    ln_kernel<<<MROWS, 256>>>(b0, b1, gamma, beta, (float*)d_out, nullptr);
}